// round 2
// baseline (speedup 1.0000x reference)
#include <cuda_runtime.h>
#include <math.h>

#define Bb_ 16
#define T_ 500
#define D_ 768
#define FFN_ 3072
#define NH_ 12
#define DH_ 64
#define L_ 3

// ---------------- scratch (device globals; no allocation) ----------------
__device__ float g_bufA[49152000];   // conv ping / reused as attention scores (48M)
__device__ float g_bufB[24576000];   // conv pong / reused as FFN hidden (24.576M)
__device__ float g_qer[48000000];    // qer buffer
__device__ float g_x[6144000];
__device__ float g_xn[6144000];
__device__ float g_q[6144000];
__device__ float g_k[6144000];
__device__ float g_v[6144000];
__device__ float g_o[6144000];

__device__ __forceinline__ float gelu_f(float x) {
    return 0.5f * x * (1.0f + erff(x * 0.7071067811865475f));
}

// ---------------- conv 5x5, pad 2, + GELU ----------------
// block: 32x4 threads. Block computes 32(W) x 16(H) outputs for 4 output channels.
__global__ void __launch_bounds__(128) conv5x5_gelu(
    const float* __restrict__ in, const float* __restrict__ w,
    const float* __restrict__ bias, float* __restrict__ out,
    int Ci, int Co, int H)
{
    const int W = 500;
    __shared__ float tile[20][36];
    int tx = threadIdx.x, ty = threadIdx.y;
    int tid = ty * 32 + tx;
    int hBlocks = (H + 15) / 16;
    int x0 = blockIdx.x * 32;
    int y0 = (blockIdx.y % hBlocks) * 16;
    int co0 = (blockIdx.y / hBlocks) * 4;
    int b = blockIdx.z;

    float acc[4][4];
#pragma unroll
    for (int i = 0; i < 4; i++)
#pragma unroll
        for (int j = 0; j < 4; j++) acc[i][j] = 0.f;

    for (int ci = 0; ci < Ci; ci++) {
        const float* ip = in + ((long long)(b * Ci + ci)) * H * W;
        for (int idx = tid; idx < 720; idx += 128) {
            int r = idx / 36, c = idx % 36;
            int gy = y0 + r - 2, gx = x0 + c - 2;
            tile[r][c] = (gy >= 0 && gy < H && gx >= 0 && gx < W) ? ip[gy * W + gx] : 0.f;
        }
        __syncthreads();
#pragma unroll
        for (int dx = 0; dx < 5; dx++) {
            float v[8];
#pragma unroll
            for (int rr = 0; rr < 8; rr++) v[rr] = tile[ty * 4 + rr][tx + dx];
#pragma unroll
            for (int c4 = 0; c4 < 4; c4++) {
                const float* wp = w + ((long long)((co0 + c4) * Ci + ci)) * 25 + dx;
#pragma unroll
                for (int dy = 0; dy < 5; dy++) {
                    float wv = __ldg(wp + dy * 5);
#pragma unroll
                    for (int ry = 0; ry < 4; ry++) acc[c4][ry] += v[ry + dy] * wv;
                }
            }
        }
        __syncthreads();
    }
    int x = x0 + tx;
    if (x < W) {
#pragma unroll
        for (int c4 = 0; c4 < 4; c4++) {
            float bv = bias[co0 + c4];
#pragma unroll
            for (int ry = 0; ry < 4; ry++) {
                int y = y0 + ty * 4 + ry;
                if (y < H)
                    out[(((long long)b * Co + co0 + c4) * H + y) * W + x] = gelu_f(acc[c4][ry] + bv);
            }
        }
    }
}

// ---------------- maxpool over freq: (2,1) stride (2,1) ----------------
__global__ void maxpool_freq(const float* __restrict__ in, float* __restrict__ out,
                             int C, int Hout)
{
    long long total = (long long)Bb_ * C * Hout * 500;
    long long idx = (long long)blockIdx.x * blockDim.x + threadIdx.x;
    if (idx >= total) return;
    int w = (int)(idx % 500);
    long long r = idx / 500;
    int h = (int)(r % Hout);
    long long bc = r / Hout;
    const float* p = in + (bc * (2LL * Hout) + 2 * h) * 500 + w;
    out[idx] = fmaxf(p[0], p[500]);
}

// ---------------- transpose [B,768,500] -> [B,500,768] ----------------
__global__ void transpose_kernel(const float* __restrict__ in, float* __restrict__ out)
{
    __shared__ float t[32][33];
    int b = blockIdx.z;
    int k0 = blockIdx.x * 32;   // over 768
    int t0 = blockIdx.y * 32;   // over 500
    int tx = threadIdx.x, ty = threadIdx.y;   // 32 x 8
    const float* ip = in + (long long)b * 768 * 500;
    float* op = out + (long long)b * 500 * 768;
#pragma unroll
    for (int r = 0; r < 32; r += 8) {
        int kk = k0 + ty + r, tt = t0 + tx;
        t[ty + r][tx] = (tt < 500) ? ip[(long long)kk * 500 + tt] : 0.f;
    }
    __syncthreads();
#pragma unroll
    for (int r = 0; r < 32; r += 8) {
        int tt = t0 + ty + r, kk = k0 + tx;
        if (tt < 500) op[(long long)tt * 768 + kk] = t[tx][ty + r];
    }
}

// ---------------- generic batched GEMM ----------------
// C = act(alpha*A*B + bias) + addsrc ; two-level batch (zo, zi) strides.
__global__ void __launch_bounds__(256) gemm_kernel(
    const float* __restrict__ A, const float* __restrict__ Bm,
    const float* __restrict__ bias, const float* __restrict__ addsrc,
    float* __restrict__ C,
    int M, int N, int K, int lda, int ldb, int ldc,
    long long sAo, long long sAi, long long sBo, long long sBi,
    long long sCo, long long sCi, int batchInner,
    int transB, int act, float alpha)
{
    __shared__ float As[16][64];
    __shared__ float Bs[16][68];

    int zo = blockIdx.z / batchInner, zi = blockIdx.z % batchInner;
    A  += (long long)zo * sAo + (long long)zi * sAi;
    Bm += (long long)zo * sBo + (long long)zi * sBi;
    long long coff = (long long)zo * sCo + (long long)zi * sCi;

    int m0 = blockIdx.y * 64, n0 = blockIdx.x * 64;
    int tid = threadIdx.x;
    int tx = tid % 16, ty = tid / 16;

    float acc[4][4];
#pragma unroll
    for (int i = 0; i < 4; i++)
#pragma unroll
        for (int j = 0; j < 4; j++) acc[i][j] = 0.f;

    int am = tid / 4;
    int ak = (tid % 4) * 4;
    int bn_nt = tid % 64;
    int bk_nt = (tid / 64) * 4;
    int bk_t = tid % 16;
    int bn_t = (tid / 16) * 4;

    for (int k0 = 0; k0 < K; k0 += 16) {
#pragma unroll
        for (int r = 0; r < 4; r++) {
            int kk = k0 + ak + r;
            As[ak + r][am] = (m0 + am < M && kk < K) ? A[(long long)(m0 + am) * lda + kk] : 0.f;
        }
        if (!transB) {
#pragma unroll
            for (int r = 0; r < 4; r++) {
                int kk = k0 + bk_nt + r;
                Bs[bk_nt + r][bn_nt] = (kk < K && n0 + bn_nt < N)
                                           ? Bm[(long long)kk * ldb + n0 + bn_nt] : 0.f;
            }
        } else {
#pragma unroll
            for (int r = 0; r < 4; r++) {
                int n = n0 + bn_t + r;
                int kk = k0 + bk_t;
                Bs[bk_t][bn_t + r] = (kk < K && n < N) ? Bm[(long long)n * ldb + kk] : 0.f;
            }
        }
        __syncthreads();
#pragma unroll
        for (int kk = 0; kk < 16; kk++) {
            float4 a = *(const float4*)&As[kk][ty * 4];
            float4 b = *(const float4*)&Bs[kk][tx * 4];
            acc[0][0] += a.x * b.x; acc[0][1] += a.x * b.y; acc[0][2] += a.x * b.z; acc[0][3] += a.x * b.w;
            acc[1][0] += a.y * b.x; acc[1][1] += a.y * b.y; acc[1][2] += a.y * b.z; acc[1][3] += a.y * b.w;
            acc[2][0] += a.z * b.x; acc[2][1] += a.z * b.y; acc[2][2] += a.z * b.z; acc[2][3] += a.z * b.w;
            acc[3][0] += a.w * b.x; acc[3][1] += a.w * b.y; acc[3][2] += a.w * b.z; acc[3][3] += a.w * b.w;
        }
        __syncthreads();
    }

    const float* addp = addsrc ? addsrc + coff : (const float*)0;
    float* Cp = C + coff;
#pragma unroll
    for (int i = 0; i < 4; i++) {
        int m = m0 + ty * 4 + i;
        if (m >= M) continue;
#pragma unroll
        for (int j = 0; j < 4; j++) {
            int n = n0 + tx * 4 + j;
            if (n >= N) continue;
            float vv = acc[i][j] * alpha;
            if (bias) vv += bias[n];
            if (act) vv = gelu_f(vv);
            if (addp) vv += addp[(long long)m * ldc + n];
            Cp[(long long)m * ldc + n] = vv;
        }
    }
}

// ---------------- layernorm (row = 768) ----------------
__global__ void __launch_bounds__(256) layernorm_kernel(
    const float* __restrict__ in, float* __restrict__ out,
    const float* __restrict__ g, const float* __restrict__ b)
{
    __shared__ float red[256];
    int row = blockIdx.x, tid = threadIdx.x;
    const float* xp = in + (long long)row * 768;
    float v0 = xp[tid], v1 = xp[tid + 256], v2 = xp[tid + 512];
    red[tid] = v0 + v1 + v2;
    __syncthreads();
    for (int o = 128; o > 0; o >>= 1) { if (tid < o) red[tid] += red[tid + o]; __syncthreads(); }
    float mean = red[0] * (1.0f / 768.0f);
    __syncthreads();
    float d0 = v0 - mean, d1 = v1 - mean, d2 = v2 - mean;
    red[tid] = d0 * d0 + d1 * d1 + d2 * d2;
    __syncthreads();
    for (int o = 128; o > 0; o >>= 1) { if (tid < o) red[tid] += red[tid + o]; __syncthreads(); }
    float rstd = rsqrtf(red[0] * (1.0f / 768.0f) + 1e-5f);
    float* op = out + (long long)row * 768;
    op[tid]       = d0 * rstd * g[tid]       + b[tid];
    op[tid + 256] = d1 * rstd * g[tid + 256] + b[tid + 256];
    op[tid + 512] = d2 * rstd * g[tid + 512] + b[tid + 512];
}

// ---------------- skew add: scores += srel(qer) ----------------
__global__ void skew_add_kernel(float* __restrict__ scores, const float* __restrict__ qer)
{
    long long idx = (long long)blockIdx.x * blockDim.x + threadIdx.x;
    long long total = 48000000LL;
    if (idx >= total) return;
    int k = (int)(idx % 500);
    long long r = idx / 500;
    int q = (int)(r % 500);
    long long bh = r / 500;
    float srel;
    if (k <= q)          srel = qer[(bh * 500 + q) * 500 + (499 - q + k)];
    else if (k == q + 1) srel = 0.f;
    else                 srel = qer[(bh * 500 + q + 1) * 500 + (k - q - 2)];
    scores[idx] += srel;
}

// ---------------- softmax over last dim (500) ----------------
__global__ void __launch_bounds__(256) softmax_kernel(float* __restrict__ s)
{
    __shared__ float red[256];
    long long row = blockIdx.x;
    int tid = threadIdx.x;
    float* p = s + row * 500;
    float v0 = p[tid];
    float v1 = (tid + 256 < 500) ? p[tid + 256] : -1e30f;
    red[tid] = fmaxf(v0, v1);
    __syncthreads();
    for (int o = 128; o > 0; o >>= 1) { if (tid < o) red[tid] = fmaxf(red[tid], red[tid + o]); __syncthreads(); }
    float mx = red[0];
    __syncthreads();
    float e0 = expf(v0 - mx);
    float e1 = (tid + 256 < 500) ? expf(v1 - mx) : 0.f;
    red[tid] = e0 + e1;
    __syncthreads();
    for (int o = 128; o > 0; o >>= 1) { if (tid < o) red[tid] += red[tid + o]; __syncthreads(); }
    float inv = 1.0f / red[0];
    p[tid] = e0 * inv;
    if (tid + 256 < 500) p[tid + 256] = e1 * inv;
}

// ---------------- orchestration ----------------
static void gemm(const float* A, const float* Bm, const float* bias, const float* add, float* C,
                 int M, int N, int K, int lda, int ldb, int ldc,
                 long long sAo, long long sAi, long long sBo, long long sBi,
                 long long sCo, long long sCi, int binner, int batch,
                 int transB, int act, float alpha)
{
    dim3 grid((N + 63) / 64, (M + 63) / 64, batch);
    gemm_kernel<<<grid, 256>>>(A, Bm, bias, add, C, M, N, K, lda, ldb, ldc,
                               sAo, sAi, sBo, sBi, sCo, sCi, binner, transB, act, alpha);
}

extern "C" void kernel_launch(void* const* d_in, const int* in_sizes, int n_in,
                              void* d_out, int out_size)
{
    (void)in_sizes; (void)n_in; (void)out_size;
    const float* spec    = (const float*)d_in[0];
    const float* cw1     = (const float*)d_in[1];
    const float* cb1     = (const float*)d_in[2];
    const float* cw2     = (const float*)d_in[3];
    const float* cb2     = (const float*)d_in[4];
    const float* cw3     = (const float*)d_in[5];
    const float* cb3     = (const float*)d_in[6];
    const float* cw4     = (const float*)d_in[7];
    const float* cb4     = (const float*)d_in[8];
    const float* proj_w  = (const float*)d_in[9];
    const float* proj_b  = (const float*)d_in[10];
    const float* ln1_g   = (const float*)d_in[11];
    const float* ln1_b   = (const float*)d_in[12];
    const float* wq      = (const float*)d_in[13];
    const float* bq      = (const float*)d_in[14];
    const float* wk      = (const float*)d_in[15];
    const float* bk      = (const float*)d_in[16];
    const float* wv      = (const float*)d_in[17];
    const float* bv      = (const float*)d_in[18];
    const float* wo      = (const float*)d_in[19];
    const float* bo      = (const float*)d_in[20];
    const float* er      = (const float*)d_in[21];
    const float* ln2_g   = (const float*)d_in[22];
    const float* ln2_b   = (const float*)d_in[23];
    const float* w1      = (const float*)d_in[24];
    const float* b1      = (const float*)d_in[25];
    const float* w2      = (const float*)d_in[26];
    const float* b2      = (const float*)d_in[27];
    const float* deprj_w = (const float*)d_in[28];
    const float* deprj_b = (const float*)d_in[29];
    float* outp = (float*)d_out;

    float *bufA, *bufB, *qer, *x, *xn, *q, *k, *v, *o;
    cudaGetSymbolAddress((void**)&bufA, g_bufA);
    cudaGetSymbolAddress((void**)&bufB, g_bufB);
    cudaGetSymbolAddress((void**)&qer,  g_qer);
    cudaGetSymbolAddress((void**)&x,    g_x);
    cudaGetSymbolAddress((void**)&xn,   g_xn);
    cudaGetSymbolAddress((void**)&q,    g_q);
    cudaGetSymbolAddress((void**)&k,    g_k);
    cudaGetSymbolAddress((void**)&v,    g_v);
    cudaGetSymbolAddress((void**)&o,    g_o);
    float* scores = bufA;   // 48M fits in 49.152M
    float* hbuf = bufB;     // 24.576M exactly

    dim3 cblk(32, 4);
    // --- CNN ---
    conv5x5_gelu<<<dim3(16, 12 * 8,  16), cblk>>>(spec, cw1, cb1, bufA, 1, 32, 192);
    { long long n = (long long)Bb_ * 32 * 96 * 500;
      maxpool_freq<<<(unsigned)((n + 255) / 256), 256>>>(bufA, bufB, 32, 96); }
    conv5x5_gelu<<<dim3(16, 6 * 16,  16), cblk>>>(bufB, cw2, cb2, bufA, 32, 64, 96);
    { long long n = (long long)Bb_ * 64 * 48 * 500;
      maxpool_freq<<<(unsigned)((n + 255) / 256), 256>>>(bufA, bufB, 64, 48); }
    conv5x5_gelu<<<dim3(16, 3 * 16,  16), cblk>>>(bufB, cw3, cb3, bufA, 64, 64, 48);
    { long long n = (long long)Bb_ * 64 * 24 * 500;
      maxpool_freq<<<(unsigned)((n + 255) / 256), 256>>>(bufA, bufB, 64, 24); }
    conv5x5_gelu<<<dim3(16, 2 * 16,  16), cblk>>>(bufB, cw4, cb4, bufA, 64, 64, 24);
    { long long n = (long long)Bb_ * 64 * 12 * 500;
      maxpool_freq<<<(unsigned)((n + 255) / 256), 256>>>(bufA, bufB, 64, 12); }
    // bufB = [B,768,500]; transpose -> xn [B,500,768]
    transpose_kernel<<<dim3(24, 16, 16), dim3(32, 8)>>>(bufB, xn);
    // proj
    gemm(xn, proj_w, proj_b, 0, x, 8000, 768, 768, 768, 768, 768,
         0, 0, 0, 0, 0, 0, 1, 1, 0, 0, 1.0f);

    const float scale = 0.125f; // 1/sqrt(64)
    const long long sQ = (long long)T_ * D_;        // 384000
    const long long sS = 12LL * T_ * T_;            // per-batch scores outer
    const long long sSi = (long long)T_ * T_;       // 250000

    for (int i = 0; i < L_; i++) {
        layernorm_kernel<<<8000, 256>>>(x, xn, ln1_g + i * 768, ln1_b + i * 768);
        gemm(xn, wq + (long long)i * 768 * 768, bq + i * 768, 0, q, 8000, 768, 768,
             768, 768, 768, 0, 0, 0, 0, 0, 0, 1, 1, 0, 0, 1.0f);
        gemm(xn, wk + (long long)i * 768 * 768, bk + i * 768, 0, k, 8000, 768, 768,
             768, 768, 768, 0, 0, 0, 0, 0, 0, 1, 1, 0, 0, 1.0f);
        gemm(xn, wv + (long long)i * 768 * 768, bv + i * 768, 0, v, 8000, 768, 768,
             768, 768, 768, 0, 0, 0, 0, 0, 0, 1, 1, 0, 0, 1.0f);
        // scores = scale * Q K^T   (batch zo=b(16), zi=h(12))
        gemm(q, k, 0, 0, scores, 500, 500, 64, 768, 768, 500,
             sQ, 64, sQ, 64, sS, sSi, 12, 192, 1, 0, scale);
        // qer = scale * Q er^T
        gemm(q, er + (long long)i * 500 * 64, 0, 0, qer, 500, 500, 64, 768, 64, 500,
             sQ, 64, 0, 0, sS, sSi, 12, 192, 1, 0, scale);
        skew_add_kernel<<<(48000000 + 255) / 256, 256>>>(scores, qer);
        softmax_kernel<<<96000, 256>>>(scores);
        // o = attn @ V  -> [B,T,H,DH] view
        gemm(scores, v, 0, 0, o, 500, 64, 500, 500, 768, 768,
             sS, sSi, sQ, 64, sQ, 64, 12, 192, 0, 0, 1.0f);
        // x = x + o @ wo + bo
        gemm(o, wo + (long long)i * 768 * 768, bo + i * 768, x, x, 8000, 768, 768,
             768, 768, 768, 0, 0, 0, 0, 0, 0, 1, 1, 0, 0, 1.0f);
        layernorm_kernel<<<8000, 256>>>(x, xn, ln2_g + i * 768, ln2_b + i * 768);
        // h = gelu(xn @ w1 + b1)
        gemm(xn, w1 + (long long)i * 768 * 3072, b1 + i * 3072, 0, hbuf, 8000, 3072, 768,
             768, 3072, 3072, 0, 0, 0, 0, 0, 0, 1, 1, 0, 1, 1.0f);
        // x = x + h @ w2 + b2
        gemm(hbuf, w2 + (long long)i * 3072 * 768, b2 + i * 768, x, x, 8000, 768, 3072,
             3072, 768, 768, 0, 0, 0, 0, 0, 0, 1, 1, 0, 0, 1.0f);
    }
    // final deproj
    gemm(x, deprj_w, deprj_b, 0, outp, 8000, 192, 768, 768, 192, 192,
         0, 0, 0, 0, 0, 0, 1, 1, 0, 0, 1.0f);
}

// round 3
// speedup vs baseline: 1.1255x; 1.1255x over previous
#include <cuda_runtime.h>
#include <math.h>

#define Bb_ 16
#define T_ 500
#define D_ 768
#define FFN_ 3072
#define NH_ 12
#define DH_ 64
#define L_ 3

// ---------------- scratch (device globals; no allocation) ----------------
__device__ float g_bufA[49152000];   // conv ping / reused as attention scores (48M)
__device__ float g_bufB[24576000];   // conv pong / reused as FFN hidden (24.576M)
__device__ float g_qer[48000000];    // qer buffer
__device__ float g_x[6144000];
__device__ float g_xn[6144000];
__device__ float g_q[6144000];
__device__ float g_k[6144000];
__device__ float g_v[6144000];
__device__ float g_o[6144000];

__device__ __forceinline__ float gelu_f(float x) {
    return 0.5f * x * (1.0f + erff(x * 0.7071067811865475f));
}

// ---------------- conv 5x5, pad 2, + GELU + freq-maxpool(2,1) fused ----------------
// block: 32x4 threads. Block computes 32(W) x 16(H input rows) for 4 output
// channels; writes 8 pooled rows: out[h/2] = max(gelu(y0), gelu(y1)).
__global__ void __launch_bounds__(128) conv5x5_gelu_pool(
    const float* __restrict__ in, const float* __restrict__ w,
    const float* __restrict__ bias, float* __restrict__ out,
    int Ci, int Co, int H)
{
    const int W = 500;
    __shared__ float tile[20][36];
    int tx = threadIdx.x, ty = threadIdx.y;
    int tid = ty * 32 + tx;
    int hBlocks = (H + 15) / 16;
    int x0 = blockIdx.x * 32;
    int y0 = (blockIdx.y % hBlocks) * 16;
    int co0 = (blockIdx.y / hBlocks) * 4;
    int b = blockIdx.z;
    int HP = H >> 1;

    float acc[4][4];
#pragma unroll
    for (int i = 0; i < 4; i++)
#pragma unroll
        for (int j = 0; j < 4; j++) acc[i][j] = 0.f;

    for (int ci = 0; ci < Ci; ci++) {
        const float* ip = in + ((long long)(b * Ci + ci)) * H * W;
        for (int idx = tid; idx < 720; idx += 128) {
            int r = idx / 36, c = idx % 36;
            int gy = y0 + r - 2, gx = x0 + c - 2;
            tile[r][c] = (gy >= 0 && gy < H && gx >= 0 && gx < W) ? ip[gy * W + gx] : 0.f;
        }
        __syncthreads();
#pragma unroll
        for (int dx = 0; dx < 5; dx++) {
            float v[8];
#pragma unroll
            for (int rr = 0; rr < 8; rr++) v[rr] = tile[ty * 4 + rr][tx + dx];
#pragma unroll
            for (int c4 = 0; c4 < 4; c4++) {
                const float* wp = w + ((long long)((co0 + c4) * Ci + ci)) * 25 + dx;
#pragma unroll
                for (int dy = 0; dy < 5; dy++) {
                    float wv = __ldg(wp + dy * 5);
#pragma unroll
                    for (int ry = 0; ry < 4; ry++) acc[c4][ry] += v[ry + dy] * wv;
                }
            }
        }
        __syncthreads();
    }
    int x = x0 + tx;
    if (x < W) {
#pragma unroll
        for (int c4 = 0; c4 < 4; c4++) {
            float bv = bias[co0 + c4];
#pragma unroll
            for (int p = 0; p < 2; p++) {
                int y = y0 + ty * 4 + 2 * p;      // even row of the pool pair
                if (y + 1 < H) {
                    float g0 = gelu_f(acc[c4][2 * p] + bv);
                    float g1 = gelu_f(acc[c4][2 * p + 1] + bv);
                    int yp = (y >> 1);
                    out[(((long long)b * Co + co0 + c4) * HP + yp) * W + x] = fmaxf(g0, g1);
                }
            }
        }
    }
}

// ---------------- transpose [B,768,500] -> [B,500,768] ----------------
__global__ void transpose_kernel(const float* __restrict__ in, float* __restrict__ out)
{
    __shared__ float t[32][33];
    int b = blockIdx.z;
    int k0 = blockIdx.x * 32;   // over 768
    int t0 = blockIdx.y * 32;   // over 500
    int tx = threadIdx.x, ty = threadIdx.y;   // 32 x 8
    const float* ip = in + (long long)b * 768 * 500;
    float* op = out + (long long)b * 500 * 768;
#pragma unroll
    for (int r = 0; r < 32; r += 8) {
        int kk = k0 + ty + r, tt = t0 + tx;
        t[ty + r][tx] = (tt < 500) ? ip[(long long)kk * 500 + tt] : 0.f;
    }
    __syncthreads();
#pragma unroll
    for (int r = 0; r < 32; r += 8) {
        int tt = t0 + ty + r, kk = k0 + tx;
        if (tt < 500) op[(long long)tt * 768 + kk] = t[tx][ty + r];
    }
}

// ---------------- big dense GEMM: 128x128 tile, 8x8 microtile, double buffered ----
// C = act(A*B + bias) (+ addsrc). Non-transposed B only. K must be multiple of 16,
// N multiple of 4. Used for proj/QKV/out-proj/FFN/deproj.
__global__ void __launch_bounds__(256) gemm128_kernel(
    const float* __restrict__ A, const float* __restrict__ Bm,
    const float* __restrict__ bias, const float* __restrict__ addsrc,
    float* __restrict__ C, int M, int N, int K,
    int lda, int ldb, int ldc, int act)
{
    __shared__ float As[2][16][128];
    __shared__ float Bs[2][16][128];
    int tid = threadIdx.x;
    int m0 = blockIdx.y * 128, n0 = blockIdx.x * 128;
    int tx = tid & 15, ty = tid >> 4;

    int arow = tid >> 2;           // 0..63
    int acol = (tid & 3) * 4;      // 0,4,8,12
    int brow = tid >> 5;           // 0..7
    int bcol = (tid & 31) * 4;     // 0..124

    float4 areg[2], breg[2];
    float acc[8][8];
#pragma unroll
    for (int i = 0; i < 8; i++)
#pragma unroll
        for (int j = 0; j < 8; j++) acc[i][j] = 0.f;

    // ---- prologue: load k-tile 0 ----
#pragma unroll
    for (int p = 0; p < 2; p++) {
        int m = m0 + arow + p * 64;
        areg[p] = make_float4(0.f, 0.f, 0.f, 0.f);
        if (m < M) areg[p] = *(const float4*)(A + (long long)m * lda + acol);
        int n = n0 + bcol;
        breg[p] = make_float4(0.f, 0.f, 0.f, 0.f);
        if (n < N) breg[p] = *(const float4*)(Bm + (long long)(brow + p * 8) * ldb + n);
    }
#pragma unroll
    for (int p = 0; p < 2; p++) {
        As[0][acol + 0][arow + p * 64] = areg[p].x;
        As[0][acol + 1][arow + p * 64] = areg[p].y;
        As[0][acol + 2][arow + p * 64] = areg[p].z;
        As[0][acol + 3][arow + p * 64] = areg[p].w;
        *(float4*)&Bs[0][brow + p * 8][bcol] = breg[p];
    }
    __syncthreads();

    int st = 0;
    for (int k0 = 16; k0 < K; k0 += 16) {
        // prefetch next k-tile into registers
#pragma unroll
        for (int p = 0; p < 2; p++) {
            int m = m0 + arow + p * 64;
            areg[p] = make_float4(0.f, 0.f, 0.f, 0.f);
            if (m < M) areg[p] = *(const float4*)(A + (long long)m * lda + k0 + acol);
            int n = n0 + bcol;
            breg[p] = make_float4(0.f, 0.f, 0.f, 0.f);
            if (n < N) breg[p] = *(const float4*)(Bm + (long long)(k0 + brow + p * 8) * ldb + n);
        }
        // compute current stage
#pragma unroll
        for (int kk = 0; kk < 16; kk++) {
            float a[8], b[8];
            *(float4*)&a[0] = *(const float4*)&As[st][kk][ty * 8];
            *(float4*)&a[4] = *(const float4*)&As[st][kk][ty * 8 + 4];
            *(float4*)&b[0] = *(const float4*)&Bs[st][kk][tx * 8];
            *(float4*)&b[4] = *(const float4*)&Bs[st][kk][tx * 8 + 4];
#pragma unroll
            for (int i = 0; i < 8; i++)
#pragma unroll
                for (int j = 0; j < 8; j++) acc[i][j] += a[i] * b[j];
        }
        // store prefetched tile into the other stage
        int ns = st ^ 1;
#pragma unroll
        for (int p = 0; p < 2; p++) {
            As[ns][acol + 0][arow + p * 64] = areg[p].x;
            As[ns][acol + 1][arow + p * 64] = areg[p].y;
            As[ns][acol + 2][arow + p * 64] = areg[p].z;
            As[ns][acol + 3][arow + p * 64] = areg[p].w;
            *(float4*)&Bs[ns][brow + p * 8][bcol] = breg[p];
        }
        __syncthreads();
        st = ns;
    }
    // last stage
#pragma unroll
    for (int kk = 0; kk < 16; kk++) {
        float a[8], b[8];
        *(float4*)&a[0] = *(const float4*)&As[st][kk][ty * 8];
        *(float4*)&a[4] = *(const float4*)&As[st][kk][ty * 8 + 4];
        *(float4*)&b[0] = *(const float4*)&Bs[st][kk][tx * 8];
        *(float4*)&b[4] = *(const float4*)&Bs[st][kk][tx * 8 + 4];
#pragma unroll
        for (int i = 0; i < 8; i++)
#pragma unroll
            for (int j = 0; j < 8; j++) acc[i][j] += a[i] * b[j];
    }

    // ---- epilogue ----
#pragma unroll
    for (int i = 0; i < 8; i++) {
        int m = m0 + ty * 8 + i;
        if (m >= M) continue;
#pragma unroll
        for (int jj = 0; jj < 2; jj++) {
            int n = n0 + tx * 8 + jj * 4;
            if (n >= N) continue;   // N multiple of 4
            float4 v;
            v.x = acc[i][jj * 4 + 0]; v.y = acc[i][jj * 4 + 1];
            v.z = acc[i][jj * 4 + 2]; v.w = acc[i][jj * 4 + 3];
            float4 bb = *(const float4*)(bias + n);
            v.x += bb.x; v.y += bb.y; v.z += bb.z; v.w += bb.w;
            if (act) {
                v.x = gelu_f(v.x); v.y = gelu_f(v.y);
                v.z = gelu_f(v.z); v.w = gelu_f(v.w);
            }
            if (addsrc) {
                float4 r = *(const float4*)(addsrc + (long long)m * ldc + n);
                v.x += r.x; v.y += r.y; v.z += r.z; v.w += r.w;
            }
            *(float4*)(C + (long long)m * ldc + n) = v;
        }
    }
}

// ---------------- small batched GEMM (attention: QK^T, Q*er^T, attn*V) ----------
__global__ void __launch_bounds__(256) gemm_kernel(
    const float* __restrict__ A, const float* __restrict__ Bm,
    float* __restrict__ C,
    int M, int N, int K, int lda, int ldb, int ldc,
    long long sAo, long long sAi, long long sBo, long long sBi,
    long long sCo, long long sCi, int batchInner,
    int transB, float alpha)
{
    __shared__ float As[16][64];
    __shared__ float Bs[16][68];

    int zo = blockIdx.z / batchInner, zi = blockIdx.z % batchInner;
    A  += (long long)zo * sAo + (long long)zi * sAi;
    Bm += (long long)zo * sBo + (long long)zi * sBi;
    long long coff = (long long)zo * sCo + (long long)zi * sCi;

    int m0 = blockIdx.y * 64, n0 = blockIdx.x * 64;
    int tid = threadIdx.x;
    int tx = tid % 16, ty = tid / 16;

    float acc[4][4];
#pragma unroll
    for (int i = 0; i < 4; i++)
#pragma unroll
        for (int j = 0; j < 4; j++) acc[i][j] = 0.f;

    int am = tid / 4;
    int ak = (tid % 4) * 4;
    int bn_nt = tid % 64;
    int bk_nt = (tid / 64) * 4;
    int bk_t = tid % 16;
    int bn_t = (tid / 16) * 4;

    for (int k0 = 0; k0 < K; k0 += 16) {
#pragma unroll
        for (int r = 0; r < 4; r++) {
            int kk = k0 + ak + r;
            As[ak + r][am] = (m0 + am < M && kk < K) ? A[(long long)(m0 + am) * lda + kk] : 0.f;
        }
        if (!transB) {
#pragma unroll
            for (int r = 0; r < 4; r++) {
                int kk = k0 + bk_nt + r;
                Bs[bk_nt + r][bn_nt] = (kk < K && n0 + bn_nt < N)
                                           ? Bm[(long long)kk * ldb + n0 + bn_nt] : 0.f;
            }
        } else {
#pragma unroll
            for (int r = 0; r < 4; r++) {
                int n = n0 + bn_t + r;
                int kk = k0 + bk_t;
                Bs[bk_t][bn_t + r] = (kk < K && n < N) ? Bm[(long long)n * ldb + kk] : 0.f;
            }
        }
        __syncthreads();
#pragma unroll
        for (int kk = 0; kk < 16; kk++) {
            float4 a = *(const float4*)&As[kk][ty * 4];
            float4 b = *(const float4*)&Bs[kk][tx * 4];
            acc[0][0] += a.x * b.x; acc[0][1] += a.x * b.y; acc[0][2] += a.x * b.z; acc[0][3] += a.x * b.w;
            acc[1][0] += a.y * b.x; acc[1][1] += a.y * b.y; acc[1][2] += a.y * b.z; acc[1][3] += a.y * b.w;
            acc[2][0] += a.z * b.x; acc[2][1] += a.z * b.y; acc[2][2] += a.z * b.z; acc[2][3] += a.z * b.w;
            acc[3][0] += a.w * b.x; acc[3][1] += a.w * b.y; acc[3][2] += a.w * b.z; acc[3][3] += a.w * b.w;
        }
        __syncthreads();
    }

    float* Cp = C + coff;
#pragma unroll
    for (int i = 0; i < 4; i++) {
        int m = m0 + ty * 4 + i;
        if (m >= M) continue;
#pragma unroll
        for (int j = 0; j < 4; j++) {
            int n = n0 + tx * 4 + j;
            if (n >= N) continue;
            Cp[(long long)m * ldc + n] = acc[i][j] * alpha;
        }
    }
}

// ---------------- layernorm (row = 768) ----------------
__global__ void __launch_bounds__(256) layernorm_kernel(
    const float* __restrict__ in, float* __restrict__ out,
    const float* __restrict__ g, const float* __restrict__ b)
{
    __shared__ float red[256];
    int row = blockIdx.x, tid = threadIdx.x;
    const float* xp = in + (long long)row * 768;
    float v0 = xp[tid], v1 = xp[tid + 256], v2 = xp[tid + 512];
    red[tid] = v0 + v1 + v2;
    __syncthreads();
    for (int o = 128; o > 0; o >>= 1) { if (tid < o) red[tid] += red[tid + o]; __syncthreads(); }
    float mean = red[0] * (1.0f / 768.0f);
    __syncthreads();
    float d0 = v0 - mean, d1 = v1 - mean, d2 = v2 - mean;
    red[tid] = d0 * d0 + d1 * d1 + d2 * d2;
    __syncthreads();
    for (int o = 128; o > 0; o >>= 1) { if (tid < o) red[tid] += red[tid + o]; __syncthreads(); }
    float rstd = rsqrtf(red[0] * (1.0f / 768.0f) + 1e-5f);
    float* op = out + (long long)row * 768;
    op[tid]       = d0 * rstd * g[tid]       + b[tid];
    op[tid + 256] = d1 * rstd * g[tid + 256] + b[tid + 256];
    op[tid + 512] = d2 * rstd * g[tid + 512] + b[tid + 512];
}

// ---------------- fused skew + softmax over last dim (500) ----------------
// s holds scale*QK^T; qer holds scale*Q er^T. Computes softmax(s + srel(qer)).
__global__ void __launch_bounds__(256) softmax_skew_kernel(
    float* __restrict__ s, const float* __restrict__ qer)
{
    __shared__ float red[256];
    long long row = blockIdx.x;          // bh*500 + q
    int q = (int)(row % 500);
    long long bh = row / 500;
    int tid = threadIdx.x;
    float* p = s + row * 500;
    const float* qr0 = qer + (bh * 500 + q) * 500;        // k<=q : idx 499-q+k
    const float* qr1 = qer + (bh * 500 + q + 1) * 500;    // k>q+1: idx k-q-2

    int k0 = tid, k1 = tid + 256;
    float srel0 = (k0 <= q) ? qr0[499 - q + k0]
                : (k0 == q + 1) ? 0.f : qr1[k0 - q - 2];
    float v0 = p[k0] + srel0;
    float v1 = -1e30f;
    if (k1 < 500) {
        float srel1 = (k1 <= q) ? qr0[499 - q + k1]
                    : (k1 == q + 1) ? 0.f : qr1[k1 - q - 2];
        v1 = p[k1] + srel1;
    }
    red[tid] = fmaxf(v0, v1);
    __syncthreads();
    for (int o = 128; o > 0; o >>= 1) { if (tid < o) red[tid] = fmaxf(red[tid], red[tid + o]); __syncthreads(); }
    float mx = red[0];
    __syncthreads();
    float e0 = expf(v0 - mx);
    float e1 = (k1 < 500) ? expf(v1 - mx) : 0.f;
    red[tid] = e0 + e1;
    __syncthreads();
    for (int o = 128; o > 0; o >>= 1) { if (tid < o) red[tid] += red[tid + o]; __syncthreads(); }
    float inv = 1.0f / red[0];
    p[k0] = e0 * inv;
    if (k1 < 500) p[k1] = e1 * inv;
}

// ---------------- orchestration ----------------
static void gemm_attn(const float* A, const float* Bm, float* C,
                      int M, int N, int K, int lda, int ldb, int ldc,
                      long long sAo, long long sAi, long long sBo, long long sBi,
                      long long sCo, long long sCi, int binner, int batch,
                      int transB, float alpha)
{
    dim3 grid((N + 63) / 64, (M + 63) / 64, batch);
    gemm_kernel<<<grid, 256>>>(A, Bm, C, M, N, K, lda, ldb, ldc,
                               sAo, sAi, sBo, sBi, sCo, sCi, binner, transB, alpha);
}

static void gemm_big(const float* A, const float* Bm, const float* bias,
                     const float* add, float* C, int M, int N, int K,
                     int lda, int ldb, int ldc, int act)
{
    dim3 grid((N + 127) / 128, (M + 127) / 128);
    gemm128_kernel<<<grid, 256>>>(A, Bm, bias, add, C, M, N, K, lda, ldb, ldc, act);
}

extern "C" void kernel_launch(void* const* d_in, const int* in_sizes, int n_in,
                              void* d_out, int out_size)
{
    (void)in_sizes; (void)n_in; (void)out_size;
    const float* spec    = (const float*)d_in[0];
    const float* cw1     = (const float*)d_in[1];
    const float* cb1     = (const float*)d_in[2];
    const float* cw2     = (const float*)d_in[3];
    const float* cb2     = (const float*)d_in[4];
    const float* cw3     = (const float*)d_in[5];
    const float* cb3     = (const float*)d_in[6];
    const float* cw4     = (const float*)d_in[7];
    const float* cb4     = (const float*)d_in[8];
    const float* proj_w  = (const float*)d_in[9];
    const float* proj_b  = (const float*)d_in[10];
    const float* ln1_g   = (const float*)d_in[11];
    const float* ln1_b   = (const float*)d_in[12];
    const float* wq      = (const float*)d_in[13];
    const float* bq      = (const float*)d_in[14];
    const float* wk      = (const float*)d_in[15];
    const float* bk      = (const float*)d_in[16];
    const float* wv      = (const float*)d_in[17];
    const float* bv      = (const float*)d_in[18];
    const float* wo      = (const float*)d_in[19];
    const float* bo      = (const float*)d_in[20];
    const float* er      = (const float*)d_in[21];
    const float* ln2_g   = (const float*)d_in[22];
    const float* ln2_b   = (const float*)d_in[23];
    const float* w1      = (const float*)d_in[24];
    const float* b1      = (const float*)d_in[25];
    const float* w2      = (const float*)d_in[26];
    const float* b2      = (const float*)d_in[27];
    const float* deprj_w = (const float*)d_in[28];
    const float* deprj_b = (const float*)d_in[29];
    float* outp = (float*)d_out;

    float *bufA, *bufB, *qer, *x, *xn, *q, *k, *v, *o;
    cudaGetSymbolAddress((void**)&bufA, g_bufA);
    cudaGetSymbolAddress((void**)&bufB, g_bufB);
    cudaGetSymbolAddress((void**)&qer,  g_qer);
    cudaGetSymbolAddress((void**)&x,    g_x);
    cudaGetSymbolAddress((void**)&xn,   g_xn);
    cudaGetSymbolAddress((void**)&q,    g_q);
    cudaGetSymbolAddress((void**)&k,    g_k);
    cudaGetSymbolAddress((void**)&v,    g_v);
    cudaGetSymbolAddress((void**)&o,    g_o);
    float* scores = bufA;   // 48M fits in 49.152M
    float* hbuf = bufB;     // 24.576M exactly

    dim3 cblk(32, 4);
    // --- CNN with fused GELU+maxpool ---
    conv5x5_gelu_pool<<<dim3(16, 12 * 8,  16), cblk>>>(spec, cw1, cb1, bufB, 1, 32, 192);
    conv5x5_gelu_pool<<<dim3(16, 6 * 16,  16), cblk>>>(bufB, cw2, cb2, bufA, 32, 64, 96);
    conv5x5_gelu_pool<<<dim3(16, 3 * 16,  16), cblk>>>(bufA, cw3, cb3, bufB, 64, 64, 48);
    conv5x5_gelu_pool<<<dim3(16, 2 * 16,  16), cblk>>>(bufB, cw4, cb4, bufA, 64, 64, 24);
    // bufA = [B,768,500]; transpose -> xn [B,500,768]
    transpose_kernel<<<dim3(24, 16, 16), dim3(32, 8)>>>(bufA, xn);
    // proj
    gemm_big(xn, proj_w, proj_b, 0, x, 8000, 768, 768, 768, 768, 768, 0);

    const float scale = 0.125f; // 1/sqrt(64)
    const long long sQ = (long long)T_ * D_;        // 384000
    const long long sS = 12LL * T_ * T_;            // per-batch scores outer
    const long long sSi = (long long)T_ * T_;       // 250000

    for (int i = 0; i < L_; i++) {
        layernorm_kernel<<<8000, 256>>>(x, xn, ln1_g + i * 768, ln1_b + i * 768);
        gemm_big(xn, wq + (long long)i * 768 * 768, bq + i * 768, 0, q, 8000, 768, 768, 768, 768, 768, 0);
        gemm_big(xn, wk + (long long)i * 768 * 768, bk + i * 768, 0, k, 8000, 768, 768, 768, 768, 768, 0);
        gemm_big(xn, wv + (long long)i * 768 * 768, bv + i * 768, 0, v, 8000, 768, 768, 768, 768, 768, 0);
        // scores = scale * Q K^T   (batch zo=b(16), zi=h(12))
        gemm_attn(q, k, scores, 500, 500, 64, 768, 768, 500,
                  sQ, 64, sQ, 64, sS, sSi, 12, 192, 1, scale);
        // qer = scale * Q er^T
        gemm_attn(q, er + (long long)i * 500 * 64, qer, 500, 500, 64, 768, 64, 500,
                  sQ, 64, 0, 0, sS, sSi, 12, 192, 1, scale);
        // fused skew + softmax
        softmax_skew_kernel<<<96000, 256>>>(scores, qer);
        // o = attn @ V  -> [B,T,H,DH] view
        gemm_attn(scores, v, o, 500, 64, 500, 500, 768, 768,
                  sS, sSi, sQ, 64, sQ, 64, 12, 192, 0, 1.0f);
        // x = x + o @ wo + bo
        gemm_big(o, wo + (long long)i * 768 * 768, bo + i * 768, x, x, 8000, 768, 768, 768, 768, 768, 0);
        layernorm_kernel<<<8000, 256>>>(x, xn, ln2_g + i * 768, ln2_b + i * 768);
        // h = gelu(xn @ w1 + b1)
        gemm_big(xn, w1 + (long long)i * 768 * 3072, b1 + i * 3072, 0, hbuf, 8000, 3072, 768,
                 768, 3072, 3072, 1);
        // x = x + h @ w2 + b2
        gemm_big(hbuf, w2 + (long long)i * 3072 * 768, b2 + i * 768, x, x, 8000, 768, 3072,
                 3072, 768, 768, 0);
    }
    // final deproj
    gemm_big(x, deprj_w, deprj_b, 0, outp, 8000, 192, 768, 768, 192, 192, 0);
}

// round 4
// speedup vs baseline: 1.2163x; 1.0807x over previous
#include <cuda_runtime.h>
#include <math.h>

#define Bb_ 16
#define T_ 500
#define D_ 768
#define FFN_ 3072
#define NH_ 12
#define DH_ 64
#define L_ 3

// ---------------- scratch (device globals; no allocation) ----------------
__device__ float g_bufA[49152000];   // conv ping
__device__ float g_bufB[24576000];   // conv pong / FFN hidden
__device__ float g_qer[48000000];    // qer buffer
__device__ float g_x[6144000];
__device__ float g_xn[6144000];
__device__ float g_q[6144000];
__device__ float g_k[6144000];
__device__ float g_v[6144000];
__device__ float g_o[6144000];

__device__ __forceinline__ float gelu_f(float x) {
    return 0.5f * x * (1.0f + erff(x * 0.7071067811865475f));
}

// ---------------- conv 5x5, pad 2, + GELU + freq-maxpool(2,1) fused ----------------
// block: 32x4 threads; 32(W) x 16(H in-rows) x 4 out-channels; weights cached in smem.
__global__ void __launch_bounds__(128) conv5x5_gelu_pool(
    const float* __restrict__ in, const float* __restrict__ w,
    const float* __restrict__ bias, float* __restrict__ out,
    int Ci, int Co, int H)
{
    const int W = 500;
    __shared__ float tile[20][36];
    __shared__ float ws[6400];            // 4co * Ci(<=64) * 25
    int tx = threadIdx.x, ty = threadIdx.y;
    int tid = ty * 32 + tx;
    int hBlocks = (H + 15) / 16;
    int x0 = blockIdx.x * 32;
    int y0 = (blockIdx.y % hBlocks) * 16;
    int co0 = (blockIdx.y / hBlocks) * 4;
    int b = blockIdx.z;
    int HP = H >> 1;

    // preload weights: w[(co0+c4)*Ci*25 + s] for s in [0, 4*Ci*25)
    int wtot = 4 * Ci * 25;
    const float* wbase = w + (long long)co0 * Ci * 25;
    for (int s = tid; s < wtot; s += 128) ws[s] = wbase[s];

    float acc[4][4];
#pragma unroll
    for (int i = 0; i < 4; i++)
#pragma unroll
        for (int j = 0; j < 4; j++) acc[i][j] = 0.f;

    for (int ci = 0; ci < Ci; ci++) {
        const float* ip = in + ((long long)(b * Ci + ci)) * H * W;
        for (int idx = tid; idx < 720; idx += 128) {
            int r = idx / 36, c = idx % 36;
            int gy = y0 + r - 2, gx = x0 + c - 2;
            tile[r][c] = (gy >= 0 && gy < H && gx >= 0 && gx < W) ? ip[gy * W + gx] : 0.f;
        }
        __syncthreads();
#pragma unroll
        for (int dx = 0; dx < 5; dx++) {
            float v[8];
#pragma unroll
            for (int rr = 0; rr < 8; rr++) v[rr] = tile[ty * 4 + rr][tx + dx];
#pragma unroll
            for (int c4 = 0; c4 < 4; c4++) {
                const float* wp = ws + (c4 * Ci + ci) * 25 + dx;
#pragma unroll
                for (int dy = 0; dy < 5; dy++) {
                    float wv = wp[dy * 5];
#pragma unroll
                    for (int ry = 0; ry < 4; ry++) acc[c4][ry] += v[ry + dy] * wv;
                }
            }
        }
        __syncthreads();
    }
    int x = x0 + tx;
    if (x < W) {
#pragma unroll
        for (int c4 = 0; c4 < 4; c4++) {
            float bv = bias[co0 + c4];
#pragma unroll
            for (int p = 0; p < 2; p++) {
                int y = y0 + ty * 4 + 2 * p;
                if (y + 1 < H) {
                    float g0 = gelu_f(acc[c4][2 * p] + bv);
                    float g1 = gelu_f(acc[c4][2 * p + 1] + bv);
                    out[(((long long)b * Co + co0 + c4) * HP + (y >> 1)) * W + x] = fmaxf(g0, g1);
                }
            }
        }
    }
}

// ---------------- transpose [B,768,500] -> [B,500,768] ----------------
__global__ void transpose_kernel(const float* __restrict__ in, float* __restrict__ out)
{
    __shared__ float t[32][33];
    int b = blockIdx.z;
    int k0 = blockIdx.x * 32;
    int t0 = blockIdx.y * 32;
    int tx = threadIdx.x, ty = threadIdx.y;   // 32 x 8
    const float* ip = in + (long long)b * 768 * 500;
    float* op = out + (long long)b * 500 * 768;
#pragma unroll
    for (int r = 0; r < 32; r += 8) {
        int kk = k0 + ty + r, tt = t0 + tx;
        t[ty + r][tx] = (tt < 500) ? ip[(long long)kk * 500 + tt] : 0.f;
    }
    __syncthreads();
#pragma unroll
    for (int r = 0; r < 32; r += 8) {
        int tt = t0 + ty + r, kk = k0 + tx;
        if (tt < 500) op[(long long)tt * 768 + kk] = t[tx][ty + r];
    }
}

// ---------------- big dense GEMM: 128x128 tile, 8x8 microtile, double buffered ----
__global__ void __launch_bounds__(256) gemm128_kernel(
    const float* __restrict__ A, const float* __restrict__ Bm,
    const float* __restrict__ bias, const float* __restrict__ addsrc,
    float* __restrict__ C, int M, int N, int K,
    int lda, int ldb, int ldc, int act)
{
    __shared__ float As[2][16][128];
    __shared__ float Bs[2][16][128];
    int tid = threadIdx.x;
    int m0 = blockIdx.y * 128, n0 = blockIdx.x * 128;
    int tx = tid & 15, ty = tid >> 4;

    int arow = tid >> 2;
    int acol = (tid & 3) * 4;
    int brow = tid >> 5;
    int bcol = (tid & 31) * 4;

    float4 areg[2], breg[2];
    float acc[8][8];
#pragma unroll
    for (int i = 0; i < 8; i++)
#pragma unroll
        for (int j = 0; j < 8; j++) acc[i][j] = 0.f;

#pragma unroll
    for (int p = 0; p < 2; p++) {
        int m = m0 + arow + p * 64;
        areg[p] = make_float4(0.f, 0.f, 0.f, 0.f);
        if (m < M) areg[p] = *(const float4*)(A + (long long)m * lda + acol);
        int n = n0 + bcol;
        breg[p] = make_float4(0.f, 0.f, 0.f, 0.f);
        if (n < N) breg[p] = *(const float4*)(Bm + (long long)(brow + p * 8) * ldb + n);
    }
#pragma unroll
    for (int p = 0; p < 2; p++) {
        As[0][acol + 0][arow + p * 64] = areg[p].x;
        As[0][acol + 1][arow + p * 64] = areg[p].y;
        As[0][acol + 2][arow + p * 64] = areg[p].z;
        As[0][acol + 3][arow + p * 64] = areg[p].w;
        *(float4*)&Bs[0][brow + p * 8][bcol] = breg[p];
    }
    __syncthreads();

    int st = 0;
    for (int k0 = 16; k0 < K; k0 += 16) {
#pragma unroll
        for (int p = 0; p < 2; p++) {
            int m = m0 + arow + p * 64;
            areg[p] = make_float4(0.f, 0.f, 0.f, 0.f);
            if (m < M) areg[p] = *(const float4*)(A + (long long)m * lda + k0 + acol);
            int n = n0 + bcol;
            breg[p] = make_float4(0.f, 0.f, 0.f, 0.f);
            if (n < N) breg[p] = *(const float4*)(Bm + (long long)(k0 + brow + p * 8) * ldb + n);
        }
#pragma unroll
        for (int kk = 0; kk < 16; kk++) {
            float a[8], b[8];
            *(float4*)&a[0] = *(const float4*)&As[st][kk][ty * 8];
            *(float4*)&a[4] = *(const float4*)&As[st][kk][ty * 8 + 4];
            *(float4*)&b[0] = *(const float4*)&Bs[st][kk][tx * 8];
            *(float4*)&b[4] = *(const float4*)&Bs[st][kk][tx * 8 + 4];
#pragma unroll
            for (int i = 0; i < 8; i++)
#pragma unroll
                for (int j = 0; j < 8; j++) acc[i][j] += a[i] * b[j];
        }
        int ns = st ^ 1;
#pragma unroll
        for (int p = 0; p < 2; p++) {
            As[ns][acol + 0][arow + p * 64] = areg[p].x;
            As[ns][acol + 1][arow + p * 64] = areg[p].y;
            As[ns][acol + 2][arow + p * 64] = areg[p].z;
            As[ns][acol + 3][arow + p * 64] = areg[p].w;
            *(float4*)&Bs[ns][brow + p * 8][bcol] = breg[p];
        }
        __syncthreads();
        st = ns;
    }
#pragma unroll
    for (int kk = 0; kk < 16; kk++) {
        float a[8], b[8];
        *(float4*)&a[0] = *(const float4*)&As[st][kk][ty * 8];
        *(float4*)&a[4] = *(const float4*)&As[st][kk][ty * 8 + 4];
        *(float4*)&b[0] = *(const float4*)&Bs[st][kk][tx * 8];
        *(float4*)&b[4] = *(const float4*)&Bs[st][kk][tx * 8 + 4];
#pragma unroll
        for (int i = 0; i < 8; i++)
#pragma unroll
            for (int j = 0; j < 8; j++) acc[i][j] += a[i] * b[j];
    }

#pragma unroll
    for (int i = 0; i < 8; i++) {
        int m = m0 + ty * 8 + i;
        if (m >= M) continue;
#pragma unroll
        for (int jj = 0; jj < 2; jj++) {
            int n = n0 + tx * 8 + jj * 4;
            if (n >= N) continue;
            float4 v;
            v.x = acc[i][jj * 4 + 0]; v.y = acc[i][jj * 4 + 1];
            v.z = acc[i][jj * 4 + 2]; v.w = acc[i][jj * 4 + 3];
            float4 bb = *(const float4*)(bias + n);
            v.x += bb.x; v.y += bb.y; v.z += bb.z; v.w += bb.w;
            if (act) {
                v.x = gelu_f(v.x); v.y = gelu_f(v.y);
                v.z = gelu_f(v.z); v.w = gelu_f(v.w);
            }
            if (addsrc) {
                float4 r = *(const float4*)(addsrc + (long long)m * ldc + n);
                v.x += r.x; v.y += r.y; v.z += r.z; v.w += r.w;
            }
            *(float4*)(C + (long long)m * ldc + n) = v;
        }
    }
}

// ---------------- small batched GEMM (qer = scale * Q er^T) ----------
__global__ void __launch_bounds__(256) gemm_kernel(
    const float* __restrict__ A, const float* __restrict__ Bm,
    float* __restrict__ C,
    int M, int N, int K, int lda, int ldb, int ldc,
    long long sAo, long long sAi, long long sBo, long long sBi,
    long long sCo, long long sCi, int batchInner,
    int transB, float alpha)
{
    __shared__ float As[16][64];
    __shared__ float Bs[16][68];

    int zo = blockIdx.z / batchInner, zi = blockIdx.z % batchInner;
    A  += (long long)zo * sAo + (long long)zi * sAi;
    Bm += (long long)zo * sBo + (long long)zi * sBi;
    long long coff = (long long)zo * sCo + (long long)zi * sCi;

    int m0 = blockIdx.y * 64, n0 = blockIdx.x * 64;
    int tid = threadIdx.x;
    int tx = tid % 16, ty = tid / 16;

    float acc[4][4];
#pragma unroll
    for (int i = 0; i < 4; i++)
#pragma unroll
        for (int j = 0; j < 4; j++) acc[i][j] = 0.f;

    int am = tid / 4;
    int ak = (tid % 4) * 4;
    int bn_nt = tid % 64;
    int bk_nt = (tid / 64) * 4;
    int bk_t = tid % 16;
    int bn_t = (tid / 16) * 4;

    for (int k0 = 0; k0 < K; k0 += 16) {
#pragma unroll
        for (int r = 0; r < 4; r++) {
            int kk = k0 + ak + r;
            As[ak + r][am] = (m0 + am < M && kk < K) ? A[(long long)(m0 + am) * lda + kk] : 0.f;
        }
        if (!transB) {
#pragma unroll
            for (int r = 0; r < 4; r++) {
                int kk = k0 + bk_nt + r;
                Bs[bk_nt + r][bn_nt] = (kk < K && n0 + bn_nt < N)
                                           ? Bm[(long long)kk * ldb + n0 + bn_nt] : 0.f;
            }
        } else {
#pragma unroll
            for (int r = 0; r < 4; r++) {
                int n = n0 + bn_t + r;
                int kk = k0 + bk_t;
                Bs[bk_t][bn_t + r] = (kk < K && n < N) ? Bm[(long long)n * ldb + kk] : 0.f;
            }
        }
        __syncthreads();
#pragma unroll
        for (int kk = 0; kk < 16; kk++) {
            float4 a = *(const float4*)&As[kk][ty * 4];
            float4 b = *(const float4*)&Bs[kk][tx * 4];
            acc[0][0] += a.x * b.x; acc[0][1] += a.x * b.y; acc[0][2] += a.x * b.z; acc[0][3] += a.x * b.w;
            acc[1][0] += a.y * b.x; acc[1][1] += a.y * b.y; acc[1][2] += a.y * b.z; acc[1][3] += a.y * b.w;
            acc[2][0] += a.z * b.x; acc[2][1] += a.z * b.y; acc[2][2] += a.z * b.z; acc[2][3] += a.z * b.w;
            acc[3][0] += a.w * b.x; acc[3][1] += a.w * b.y; acc[3][2] += a.w * b.z; acc[3][3] += a.w * b.w;
        }
        __syncthreads();
    }

    float* Cp = C + coff;
#pragma unroll
    for (int i = 0; i < 4; i++) {
        int m = m0 + ty * 4 + i;
        if (m >= M) continue;
#pragma unroll
        for (int j = 0; j < 4; j++) {
            int n = n0 + tx * 4 + j;
            if (n >= N) continue;
            Cp[(long long)m * ldc + n] = acc[i][j] * alpha;
        }
    }
}

// ---------------- flash attention (fused QK^T + skew + softmax + PV) ------------
// Block: (qtile, h, b). 256 threads = 16(tx:k/d) x 16(ty:q). Q-tile 128, K-tile 64.
// S microtile 8x4/thread; O microtile 8x4/thread. Exact online softmax.
#define FA_QLD 132
#define FA_KLD 68
#define FA_PLD 68
#define FA_SMEM_FLOATS (64*FA_QLD + 64*FA_KLD + 64*FA_KLD + 128*FA_PLD)

extern __shared__ float fa_smem[];

__global__ void __launch_bounds__(256) flash_attn_kernel(
    const float* __restrict__ Q, const float* __restrict__ K,
    const float* __restrict__ V, const float* __restrict__ qer,
    float* __restrict__ O)
{
    float* Qs = fa_smem;               // [64 d][132] holds 128 q
    float* Ks = Qs + 64 * FA_QLD;      // [64 d][68] holds 64 k
    float* Vs = Ks + 64 * FA_KLD;      // [64 k][68] holds 64 d
    float* Ps = Vs + 64 * FA_KLD;      // [128 q][68] holds 64 k

    const float scale = 0.125f;
    int qt = blockIdx.x;
    int h = blockIdx.y, b = blockIdx.z;
    int q0 = qt * 128;
    const float* Qp = Q + (long long)b * 500 * 768 + h * 64;
    const float* Kp = K + (long long)b * 500 * 768 + h * 64;
    const float* Vp = V + (long long)b * 500 * 768 + h * 64;
    const float* qerp = qer + (long long)(b * 12 + h) * 250000;

    int tid = threadIdx.x;
    int tx = tid & 15, ty = tid >> 4;

    // load Q tile -> Qs[d][q]
#pragma unroll
    for (int i = 0; i < 8; i++) {
        int r = i * 16 + (tid >> 4);
        int d4 = (tid & 15) * 4;
        float4 v = make_float4(0.f, 0.f, 0.f, 0.f);
        if (q0 + r < 500) v = *(const float4*)(Qp + (long long)(q0 + r) * 768 + d4);
        Qs[(d4 + 0) * FA_QLD + r] = v.x;
        Qs[(d4 + 1) * FA_QLD + r] = v.y;
        Qs[(d4 + 2) * FA_QLD + r] = v.z;
        Qs[(d4 + 3) * FA_QLD + r] = v.w;
    }

    float m[8], l[8], o[8][4];
#pragma unroll
    for (int i = 0; i < 8; i++) {
        m[i] = -1e30f; l[i] = 0.f;
#pragma unroll
        for (int j = 0; j < 4; j++) o[i][j] = 0.f;
    }
    __syncthreads();

    for (int kt0 = 0; kt0 < 500; kt0 += 64) {
        // load K -> Ks[d][k], V -> Vs[k][d]
#pragma unroll
        for (int i = 0; i < 4; i++) {
            int r = i * 16 + (tid >> 4);
            int d4 = (tid & 15) * 4;
            float4 kv = make_float4(0.f, 0.f, 0.f, 0.f);
            float4 vv = make_float4(0.f, 0.f, 0.f, 0.f);
            if (kt0 + r < 500) {
                kv = *(const float4*)(Kp + (long long)(kt0 + r) * 768 + d4);
                vv = *(const float4*)(Vp + (long long)(kt0 + r) * 768 + d4);
            }
            Ks[(d4 + 0) * FA_KLD + r] = kv.x;
            Ks[(d4 + 1) * FA_KLD + r] = kv.y;
            Ks[(d4 + 2) * FA_KLD + r] = kv.z;
            Ks[(d4 + 3) * FA_KLD + r] = kv.w;
            *(float4*)(Vs + r * FA_KLD + d4) = vv;
        }
        __syncthreads();

        // S = Q K^T (8q x 4k per thread)
        float S[8][4];
#pragma unroll
        for (int i = 0; i < 8; i++)
#pragma unroll
            for (int j = 0; j < 4; j++) S[i][j] = 0.f;
#pragma unroll
        for (int d = 0; d < 64; d++) {
            float a[8];
            *(float4*)&a[0] = *(const float4*)(Qs + d * FA_QLD + ty * 8);
            *(float4*)&a[4] = *(const float4*)(Qs + d * FA_QLD + ty * 8 + 4);
            float4 bb = *(const float4*)(Ks + d * FA_KLD + tx * 4);
#pragma unroll
            for (int i = 0; i < 8; i++) {
                S[i][0] += a[i] * bb.x; S[i][1] += a[i] * bb.y;
                S[i][2] += a[i] * bb.z; S[i][3] += a[i] * bb.w;
            }
        }
        // scale + skew bias + mask
#pragma unroll
        for (int i = 0; i < 8; i++) {
            int q = q0 + ty * 8 + i;
#pragma unroll
            for (int j = 0; j < 4; j++) {
                int k = kt0 + tx * 4 + j;
                if (q < 500 && k < 500) {
                    float srel;
                    if (k <= q)          srel = qerp[(long long)q * 500 + 499 - q + k];
                    else if (k == q + 1) srel = 0.f;
                    else                 srel = qerp[(long long)(q + 1) * 500 + k - q - 2];
                    S[i][j] = S[i][j] * scale + srel;
                } else {
                    S[i][j] = -1e30f;
                }
            }
        }
        // online softmax (reduce over tx within 16-lane groups)
#pragma unroll
        for (int i = 0; i < 8; i++) {
            float rmax = fmaxf(fmaxf(S[i][0], S[i][1]), fmaxf(S[i][2], S[i][3]));
#pragma unroll
            for (int off = 1; off < 16; off <<= 1)
                rmax = fmaxf(rmax, __shfl_xor_sync(0xffffffffu, rmax, off, 32));
            float mnew = fmaxf(m[i], rmax);
            float corr = __expf(m[i] - mnew);
            float rsum = 0.f;
#pragma unroll
            for (int j = 0; j < 4; j++) {
                S[i][j] = __expf(S[i][j] - mnew);
                rsum += S[i][j];
            }
#pragma unroll
            for (int off = 1; off < 16; off <<= 1)
                rsum += __shfl_xor_sync(0xffffffffu, rsum, off, 32);
            l[i] = l[i] * corr + rsum;
            m[i] = mnew;
#pragma unroll
            for (int j = 0; j < 4; j++) o[i][j] *= corr;
            *(float4*)(Ps + (long long)(ty * 8 + i) * FA_PLD + tx * 4) =
                make_float4(S[i][0], S[i][1], S[i][2], S[i][3]);
        }
        __syncthreads();

        // O += P @ V  (8q x 4d per thread)
#pragma unroll
        for (int kk = 0; kk < 64; kk++) {
            float4 vr = *(const float4*)(Vs + kk * FA_KLD + tx * 4);
#pragma unroll
            for (int i = 0; i < 8; i++) {
                float p = Ps[(ty * 8 + i) * FA_PLD + kk];
                o[i][0] += p * vr.x; o[i][1] += p * vr.y;
                o[i][2] += p * vr.z; o[i][3] += p * vr.w;
            }
        }
        __syncthreads();
    }

    float* Op = O + (long long)b * 500 * 768 + h * 64;
#pragma unroll
    for (int i = 0; i < 8; i++) {
        int q = q0 + ty * 8 + i;
        if (q < 500) {
            float inv = 1.0f / l[i];
            float4 r = make_float4(o[i][0] * inv, o[i][1] * inv, o[i][2] * inv, o[i][3] * inv);
            *(float4*)(Op + (long long)q * 768 + tx * 4) = r;
        }
    }
}

// ---------------- layernorm (row = 768) ----------------
__global__ void __launch_bounds__(256) layernorm_kernel(
    const float* __restrict__ in, float* __restrict__ out,
    const float* __restrict__ g, const float* __restrict__ b)
{
    __shared__ float red[256];
    int row = blockIdx.x, tid = threadIdx.x;
    const float* xp = in + (long long)row * 768;
    float v0 = xp[tid], v1 = xp[tid + 256], v2 = xp[tid + 512];
    red[tid] = v0 + v1 + v2;
    __syncthreads();
    for (int o = 128; o > 0; o >>= 1) { if (tid < o) red[tid] += red[tid + o]; __syncthreads(); }
    float mean = red[0] * (1.0f / 768.0f);
    __syncthreads();
    float d0 = v0 - mean, d1 = v1 - mean, d2 = v2 - mean;
    red[tid] = d0 * d0 + d1 * d1 + d2 * d2;
    __syncthreads();
    for (int o = 128; o > 0; o >>= 1) { if (tid < o) red[tid] += red[tid + o]; __syncthreads(); }
    float rstd = rsqrtf(red[0] * (1.0f / 768.0f) + 1e-5f);
    float* op = out + (long long)row * 768;
    op[tid]       = d0 * rstd * g[tid]       + b[tid];
    op[tid + 256] = d1 * rstd * g[tid + 256] + b[tid + 256];
    op[tid + 512] = d2 * rstd * g[tid + 512] + b[tid + 512];
}

// ---------------- orchestration ----------------
static void gemm_attn(const float* A, const float* Bm, float* C,
                      int M, int N, int K, int lda, int ldb, int ldc,
                      long long sAo, long long sAi, long long sBo, long long sBi,
                      long long sCo, long long sCi, int binner, int batch,
                      int transB, float alpha)
{
    dim3 grid((N + 63) / 64, (M + 63) / 64, batch);
    gemm_kernel<<<grid, 256>>>(A, Bm, C, M, N, K, lda, ldb, ldc,
                               sAo, sAi, sBo, sBi, sCo, sCi, binner, transB, alpha);
}

static void gemm_big(const float* A, const float* Bm, const float* bias,
                     const float* add, float* C, int M, int N, int K,
                     int lda, int ldb, int ldc, int act)
{
    dim3 grid((N + 127) / 128, (M + 127) / 128);
    gemm128_kernel<<<grid, 256>>>(A, Bm, bias, add, C, M, N, K, lda, ldb, ldc, act);
}

extern "C" void kernel_launch(void* const* d_in, const int* in_sizes, int n_in,
                              void* d_out, int out_size)
{
    (void)in_sizes; (void)n_in; (void)out_size;
    const float* spec    = (const float*)d_in[0];
    const float* cw1     = (const float*)d_in[1];
    const float* cb1     = (const float*)d_in[2];
    const float* cw2     = (const float*)d_in[3];
    const float* cb2     = (const float*)d_in[4];
    const float* cw3     = (const float*)d_in[5];
    const float* cb3     = (const float*)d_in[6];
    const float* cw4     = (const float*)d_in[7];
    const float* cb4     = (const float*)d_in[8];
    const float* proj_w  = (const float*)d_in[9];
    const float* proj_b  = (const float*)d_in[10];
    const float* ln1_g   = (const float*)d_in[11];
    const float* ln1_b   = (const float*)d_in[12];
    const float* wq      = (const float*)d_in[13];
    const float* bq      = (const float*)d_in[14];
    const float* wk      = (const float*)d_in[15];
    const float* bk      = (const float*)d_in[16];
    const float* wv      = (const float*)d_in[17];
    const float* bv      = (const float*)d_in[18];
    const float* wo      = (const float*)d_in[19];
    const float* bo      = (const float*)d_in[20];
    const float* er      = (const float*)d_in[21];
    const float* ln2_g   = (const float*)d_in[22];
    const float* ln2_b   = (const float*)d_in[23];
    const float* w1      = (const float*)d_in[24];
    const float* b1      = (const float*)d_in[25];
    const float* w2      = (const float*)d_in[26];
    const float* b2      = (const float*)d_in[27];
    const float* deprj_w = (const float*)d_in[28];
    const float* deprj_b = (const float*)d_in[29];
    float* outp = (float*)d_out;

    float *bufA, *bufB, *qer, *x, *xn, *q, *k, *v, *o;
    cudaGetSymbolAddress((void**)&bufA, g_bufA);
    cudaGetSymbolAddress((void**)&bufB, g_bufB);
    cudaGetSymbolAddress((void**)&qer,  g_qer);
    cudaGetSymbolAddress((void**)&x,    g_x);
    cudaGetSymbolAddress((void**)&xn,   g_xn);
    cudaGetSymbolAddress((void**)&q,    g_q);
    cudaGetSymbolAddress((void**)&k,    g_k);
    cudaGetSymbolAddress((void**)&v,    g_v);
    cudaGetSymbolAddress((void**)&o,    g_o);
    float* hbuf = bufB;

    // opt-in smem for the flash kernel (idempotent; not a stream op)
    const int fa_smem_bytes = FA_SMEM_FLOATS * 4;
    cudaFuncSetAttribute(flash_attn_kernel,
                         cudaFuncAttributeMaxDynamicSharedMemorySize, fa_smem_bytes);

    dim3 cblk(32, 4);
    // --- CNN with fused GELU+maxpool ---
    conv5x5_gelu_pool<<<dim3(16, 12 * 8,  16), cblk>>>(spec, cw1, cb1, bufB, 1, 32, 192);
    conv5x5_gelu_pool<<<dim3(16, 6 * 16,  16), cblk>>>(bufB, cw2, cb2, bufA, 32, 64, 96);
    conv5x5_gelu_pool<<<dim3(16, 3 * 16,  16), cblk>>>(bufA, cw3, cb3, bufB, 64, 64, 48);
    conv5x5_gelu_pool<<<dim3(16, 2 * 16,  16), cblk>>>(bufB, cw4, cb4, bufA, 64, 64, 24);
    // bufA = [B,768,500]; transpose -> xn [B,500,768]
    transpose_kernel<<<dim3(24, 16, 16), dim3(32, 8)>>>(bufA, xn);
    // proj
    gemm_big(xn, proj_w, proj_b, 0, x, 8000, 768, 768, 768, 768, 768, 0);

    const float scale = 0.125f; // 1/sqrt(64)
    const long long sQ = (long long)T_ * D_;
    const long long sS = 12LL * T_ * T_;
    const long long sSi = (long long)T_ * T_;

    for (int i = 0; i < L_; i++) {
        layernorm_kernel<<<8000, 256>>>(x, xn, ln1_g + i * 768, ln1_b + i * 768);
        gemm_big(xn, wq + (long long)i * 768 * 768, bq + i * 768, 0, q, 8000, 768, 768, 768, 768, 768, 0);
        gemm_big(xn, wk + (long long)i * 768 * 768, bk + i * 768, 0, k, 8000, 768, 768, 768, 768, 768, 0);
        gemm_big(xn, wv + (long long)i * 768 * 768, bv + i * 768, 0, v, 8000, 768, 768, 768, 768, 768, 0);
        // qer = scale * Q er^T
        gemm_attn(q, er + (long long)i * 500 * 64, qer, 500, 500, 64, 768, 64, 500,
                  sQ, 64, 0, 0, sS, sSi, 12, 192, 1, scale);
        // fused attention: softmax(scale*QK^T + srel) @ V
        flash_attn_kernel<<<dim3(4, 12, 16), 256, fa_smem_bytes>>>(q, k, v, qer, o);
        // x = x + o @ wo + bo
        gemm_big(o, wo + (long long)i * 768 * 768, bo + i * 768, x, x, 8000, 768, 768, 768, 768, 768, 0);
        layernorm_kernel<<<8000, 256>>>(x, xn, ln2_g + i * 768, ln2_b + i * 768);
        // h = gelu(xn @ w1 + b1)
        gemm_big(xn, w1 + (long long)i * 768 * 3072, b1 + i * 3072, 0, hbuf, 8000, 3072, 768,
                 768, 3072, 3072, 1);
        // x = x + h @ w2 + b2
        gemm_big(hbuf, w2 + (long long)i * 3072 * 768, b2 + i * 768, x, x, 8000, 768, 3072,
                 3072, 768, 768, 0);
    }
    // final deproj
    gemm_big(x, deprj_w, deprj_b, 0, outp, 8000, 192, 768, 768, 192, 192, 0);
}

// round 6
// speedup vs baseline: 1.8409x; 1.5135x over previous
#include <cuda_runtime.h>
#include <math.h>
#include <stdint.h>

#define Bb_ 16
#define T_ 500
#define D_ 768
#define FFN_ 3072
#define NH_ 12
#define DH_ 64
#define L_ 3

// ---------------- scratch (device globals; no allocation) ----------------
__device__ float g_bufA[49152000];   // conv ping
__device__ float g_bufB[24576000];   // conv pong / FFN hidden
__device__ float g_qer[48000000];    // qer buffer
__device__ float g_x[6144000];
__device__ float g_xn[6144000];
__device__ float g_q[6144000];
__device__ float g_k[6144000];
__device__ float g_v[6144000];
__device__ float g_o[6144000];

__device__ __forceinline__ float gelu_f(float x) {
    return 0.5f * x * (1.0f + erff(x * 0.7071067811865475f));
}

__device__ __forceinline__ uint32_t tf32_rn(float x) {
    uint32_t r; asm("cvt.rna.tf32.f32 %0, %1;" : "=r"(r) : "f"(x));
    return r;
}

// ---------------- tensor-core dense GEMM via mma.sync (tf32) ----------------
// C = act(A @ B + bias) (+ addsrc). A: [M][K] row-major. B: [K][N] row-major.
// CTA tile 128(M) x 64(N), K-step 32. 8 warps: 4(m) x 2(n), warp tile 32x32.
// mma.sync.m16n8k8 tf32. Requires K%32==0, N%64==0.
#define ALD 136   // As row pad: bank = (8k + m) % 32 -> conflict-free frags
#define BLD 72    // Bs row pad: bank = (8k + n) % 32 -> conflict-free frags

__global__ void __launch_bounds__(256) mma_gemm_kernel(
    const float* __restrict__ A, const float* __restrict__ Bm,
    const float* __restrict__ bias, const float* __restrict__ addsrc,
    float* __restrict__ C, int M, int N, int K,
    int lda, int ldb, int ldc, int act)
{
    __shared__ float As[32 * ALD];   // [k][m] 32 x 128 (+pad)
    __shared__ float Bs[32 * BLD];   // [k][n] 32 x 64  (+pad)

    int tid = threadIdx.x;
    int wid = tid >> 5, lane = tid & 31;
    int grp = lane >> 2, tig = lane & 3;
    int wm = wid & 3, wn = wid >> 2;           // warp -> (m,n) tile
    int m0 = blockIdx.y * 128, n0 = blockIdx.x * 64;

    // A staging: thread -> row m=tid>>1 (0..127), k half (tid&1)*16
    int am = tid >> 1;
    int akh = (tid & 1) * 16;
    // B staging: thread -> k row tid>>3 (0..31), n chunk (tid&7)*8
    int bk = tid >> 3;
    int bn = (tid & 7) * 8;

    float acc[2][4][4];
#pragma unroll
    for (int i = 0; i < 2; i++)
#pragma unroll
        for (int j = 0; j < 4; j++)
#pragma unroll
            for (int r = 0; r < 4; r++) acc[i][j][r] = 0.f;

    float4 pa[4], pb[2];
    // prologue load k-tile 0
    {
        const float* Ap = (m0 + am < M) ? A + (long long)(m0 + am) * lda + akh : (const float*)0;
#pragma unroll
        for (int i = 0; i < 4; i++)
            pa[i] = Ap ? *(const float4*)(Ap + i * 4) : make_float4(0.f, 0.f, 0.f, 0.f);
        const float* Bp = Bm + (long long)bk * ldb + n0 + bn;
        pb[0] = *(const float4*)(Bp);
        pb[1] = *(const float4*)(Bp + 4);
    }

    for (int k0 = 0;; k0 += 32) {
        // store staged tile (tf32-rounded)
#pragma unroll
        for (int i = 0; i < 4; i++) {
            int kk = akh + i * 4;
            *(uint32_t*)&As[(kk + 0) * ALD + am] = tf32_rn(pa[i].x);
            *(uint32_t*)&As[(kk + 1) * ALD + am] = tf32_rn(pa[i].y);
            *(uint32_t*)&As[(kk + 2) * ALD + am] = tf32_rn(pa[i].z);
            *(uint32_t*)&As[(kk + 3) * ALD + am] = tf32_rn(pa[i].w);
        }
        {
            uint32_t* bsp = (uint32_t*)&Bs[bk * BLD + bn];
            bsp[0] = tf32_rn(pb[0].x); bsp[1] = tf32_rn(pb[0].y);
            bsp[2] = tf32_rn(pb[0].z); bsp[3] = tf32_rn(pb[0].w);
            bsp[4] = tf32_rn(pb[1].x); bsp[5] = tf32_rn(pb[1].y);
            bsp[6] = tf32_rn(pb[1].z); bsp[7] = tf32_rn(pb[1].w);
        }
        __syncthreads();

        bool last = (k0 + 32 >= K);
        if (!last) {
            int kn = k0 + 32;
            const float* Ap = (m0 + am < M) ? A + (long long)(m0 + am) * lda + kn + akh : (const float*)0;
#pragma unroll
            for (int i = 0; i < 4; i++)
                pa[i] = Ap ? *(const float4*)(Ap + i * 4) : make_float4(0.f, 0.f, 0.f, 0.f);
            const float* Bp = Bm + (long long)(kn + bk) * ldb + n0 + bn;
            pb[0] = *(const float4*)(Bp);
            pb[1] = *(const float4*)(Bp + 4);
        }

        // compute: 4 k8 sub-steps, 8 mma each warp
#pragma unroll
        for (int ks = 0; ks < 4; ks++) {
            int kb = ks * 8;
            uint32_t a[2][4], b[4][2];
            int mB = wm * 32;
#pragma unroll
            for (int mf = 0; mf < 2; mf++) {
                int mb = mB + mf * 16 + grp;
                a[mf][0] = *(const uint32_t*)&As[(kb + tig) * ALD + mb];
                a[mf][1] = *(const uint32_t*)&As[(kb + tig) * ALD + mb + 8];
                a[mf][2] = *(const uint32_t*)&As[(kb + tig + 4) * ALD + mb];
                a[mf][3] = *(const uint32_t*)&As[(kb + tig + 4) * ALD + mb + 8];
            }
            int nB = wn * 32;
#pragma unroll
            for (int nf = 0; nf < 4; nf++) {
                int nb = nB + nf * 8 + grp;
                b[nf][0] = *(const uint32_t*)&Bs[(kb + tig) * BLD + nb];
                b[nf][1] = *(const uint32_t*)&Bs[(kb + tig + 4) * BLD + nb];
            }
#pragma unroll
            for (int mf = 0; mf < 2; mf++)
#pragma unroll
                for (int nf = 0; nf < 4; nf++) {
                    asm volatile(
                        "mma.sync.aligned.m16n8k8.row.col.f32.tf32.tf32.f32 "
                        "{%0,%1,%2,%3}, {%4,%5,%6,%7}, {%8,%9}, {%0,%1,%2,%3};"
                        : "+f"(acc[mf][nf][0]), "+f"(acc[mf][nf][1]),
                          "+f"(acc[mf][nf][2]), "+f"(acc[mf][nf][3])
                        : "r"(a[mf][0]), "r"(a[mf][1]), "r"(a[mf][2]), "r"(a[mf][3]),
                          "r"(b[nf][0]), "r"(b[nf][1]));
                }
        }
        if (last) break;
        __syncthreads();
    }

    // epilogue: each thread owns rows (grp, grp+8) of 2 m16 frags, cols tig*2(+1) of 4 n8 frags
#pragma unroll
    for (int mf = 0; mf < 2; mf++) {
#pragma unroll
        for (int r = 0; r < 2; r++) {
            int m = m0 + wm * 32 + mf * 16 + grp + r * 8;
            if (m >= M) continue;
            float* Cp = C + (long long)m * ldc;
            const float* addp = addsrc ? addsrc + (long long)m * ldc : (const float*)0;
#pragma unroll
            for (int nf = 0; nf < 4; nf++) {
                int n = n0 + wn * 32 + nf * 8 + tig * 2;
                float v0 = acc[mf][nf][r * 2 + 0] + bias[n];
                float v1 = acc[mf][nf][r * 2 + 1] + bias[n + 1];
                if (act) { v0 = gelu_f(v0); v1 = gelu_f(v1); }
                if (addp) { v0 += addp[n]; v1 += addp[n + 1]; }
                Cp[n] = v0; Cp[n + 1] = v1;
            }
        }
    }
}

// ---------------- conv 5x5, pad 2, + GELU + freq-maxpool(2,1) fused ----------------
// block 32x4; tile 32(W) x 24(H in-rows) x 4 out-channels; 6 rows/thread.
__global__ void __launch_bounds__(128) conv5x5_gelu_pool(
    const float* __restrict__ in, const float* __restrict__ w,
    const float* __restrict__ bias, float* __restrict__ out,
    int Ci, int Co, int H)
{
    const int W = 500;
    __shared__ float tile[28][36];
    __shared__ float ws[6400];
    int tx = threadIdx.x, ty = threadIdx.y;
    int tid = ty * 32 + tx;
    int hBlocks = H / 24;
    int x0 = blockIdx.x * 32;
    int y0 = (blockIdx.y % hBlocks) * 24;
    int co0 = (blockIdx.y / hBlocks) * 4;
    int b = blockIdx.z;
    int HP = H >> 1;

    int wtot = 4 * Ci * 25;
    const float* wbase = w + (long long)co0 * Ci * 25;
    for (int s = tid; s < wtot; s += 128) ws[s] = wbase[s];

    float acc[4][6];
#pragma unroll
    for (int i = 0; i < 4; i++)
#pragma unroll
        for (int j = 0; j < 6; j++) acc[i][j] = 0.f;

    for (int ci = 0; ci < Ci; ci++) {
        const float* ip = in + ((long long)(b * Ci + ci)) * H * W;
        for (int idx = tid; idx < 1008; idx += 128) {
            int r = idx / 36, c = idx % 36;
            int gy = y0 + r - 2, gx = x0 + c - 2;
            tile[r][c] = (gy >= 0 && gy < H && gx >= 0 && gx < W) ? ip[gy * W + gx] : 0.f;
        }
        __syncthreads();
#pragma unroll
        for (int dx = 0; dx < 5; dx++) {
            float v[10];
#pragma unroll
            for (int rr = 0; rr < 10; rr++) v[rr] = tile[ty * 6 + rr][tx + dx];
#pragma unroll
            for (int c4 = 0; c4 < 4; c4++) {
                const float* wp = ws + (c4 * Ci + ci) * 25 + dx;
#pragma unroll
                for (int dy = 0; dy < 5; dy++) {
                    float wv = wp[dy * 5];
#pragma unroll
                    for (int ry = 0; ry < 6; ry++) acc[c4][ry] += v[ry + dy] * wv;
                }
            }
        }
        __syncthreads();
    }
    int x = x0 + tx;
    if (x < W) {
#pragma unroll
        for (int c4 = 0; c4 < 4; c4++) {
            float bv = bias[co0 + c4];
#pragma unroll
            for (int p = 0; p < 3; p++) {
                int y = y0 + ty * 6 + 2 * p;
                if (y + 1 < H) {
                    float g0 = gelu_f(acc[c4][2 * p] + bv);
                    float g1 = gelu_f(acc[c4][2 * p + 1] + bv);
                    out[(((long long)b * Co + co0 + c4) * HP + (y >> 1)) * W + x] = fmaxf(g0, g1);
                }
            }
        }
    }
}

// ---------------- transpose [B,768,500] -> [B,500,768] ----------------
__global__ void transpose_kernel(const float* __restrict__ in, float* __restrict__ out)
{
    __shared__ float t[32][33];
    int b = blockIdx.z;
    int k0 = blockIdx.x * 32;
    int t0 = blockIdx.y * 32;
    int tx = threadIdx.x, ty = threadIdx.y;
    const float* ip = in + (long long)b * 768 * 500;
    float* op = out + (long long)b * 500 * 768;
#pragma unroll
    for (int r = 0; r < 32; r += 8) {
        int kk = k0 + ty + r, tt = t0 + tx;
        t[ty + r][tx] = (tt < 500) ? ip[(long long)kk * 500 + tt] : 0.f;
    }
    __syncthreads();
#pragma unroll
    for (int r = 0; r < 32; r += 8) {
        int tt = t0 + ty + r, kk = k0 + tx;
        if (tt < 500) op[(long long)tt * 768 + kk] = t[tx][ty + r];
    }
}

// ---------------- small batched GEMM (qer = scale * Q er^T) ----------
__global__ void __launch_bounds__(256) gemm_kernel(
    const float* __restrict__ A, const float* __restrict__ Bm,
    float* __restrict__ C,
    int M, int N, int K, int lda, int ldb, int ldc,
    long long sAo, long long sAi, long long sBo, long long sBi,
    long long sCo, long long sCi, int batchInner,
    int transB, float alpha)
{
    __shared__ float As[16][64];
    __shared__ float Bs[16][68];

    int zo = blockIdx.z / batchInner, zi = blockIdx.z % batchInner;
    A  += (long long)zo * sAo + (long long)zi * sAi;
    Bm += (long long)zo * sBo + (long long)zi * sBi;
    long long coff = (long long)zo * sCo + (long long)zi * sCi;

    int m0 = blockIdx.y * 64, n0 = blockIdx.x * 64;
    int tid = threadIdx.x;
    int tx = tid % 16, ty = tid / 16;

    float acc[4][4];
#pragma unroll
    for (int i = 0; i < 4; i++)
#pragma unroll
        for (int j = 0; j < 4; j++) acc[i][j] = 0.f;

    int am = tid / 4;
    int ak = (tid % 4) * 4;
    int bn_nt = tid % 64;
    int bk_nt = (tid / 64) * 4;
    int bk_t = tid % 16;
    int bn_t = (tid / 16) * 4;

    for (int k0 = 0; k0 < K; k0 += 16) {
#pragma unroll
        for (int r = 0; r < 4; r++) {
            int kk = k0 + ak + r;
            As[ak + r][am] = (m0 + am < M && kk < K) ? A[(long long)(m0 + am) * lda + kk] : 0.f;
        }
        if (!transB) {
#pragma unroll
            for (int r = 0; r < 4; r++) {
                int kk = k0 + bk_nt + r;
                Bs[bk_nt + r][bn_nt] = (kk < K && n0 + bn_nt < N)
                                           ? Bm[(long long)kk * ldb + n0 + bn_nt] : 0.f;
            }
        } else {
#pragma unroll
            for (int r = 0; r < 4; r++) {
                int n = n0 + bn_t + r;
                int kk = k0 + bk_t;
                Bs[bk_t][bn_t + r] = (kk < K && n < N) ? Bm[(long long)n * ldb + kk] : 0.f;
            }
        }
        __syncthreads();
#pragma unroll
        for (int kk = 0; kk < 16; kk++) {
            float4 a = *(const float4*)&As[kk][ty * 4];
            float4 b = *(const float4*)&Bs[kk][tx * 4];
            acc[0][0] += a.x * b.x; acc[0][1] += a.x * b.y; acc[0][2] += a.x * b.z; acc[0][3] += a.x * b.w;
            acc[1][0] += a.y * b.x; acc[1][1] += a.y * b.y; acc[1][2] += a.y * b.z; acc[1][3] += a.y * b.w;
            acc[2][0] += a.z * b.x; acc[2][1] += a.z * b.y; acc[2][2] += a.z * b.z; acc[2][3] += a.z * b.w;
            acc[3][0] += a.w * b.x; acc[3][1] += a.w * b.y; acc[3][2] += a.w * b.z; acc[3][3] += a.w * b.w;
        }
        __syncthreads();
    }

    float* Cp = C + coff;
#pragma unroll
    for (int i = 0; i < 4; i++) {
        int m = m0 + ty * 4 + i;
        if (m >= M) continue;
#pragma unroll
        for (int j = 0; j < 4; j++) {
            int n = n0 + tx * 4 + j;
            if (n >= N) continue;
            Cp[(long long)m * ldc + n] = acc[i][j] * alpha;
        }
    }
}

// ---------------- flash attention (fused QK^T + skew + softmax + PV) ------------
#define FA_QLD 132
#define FA_KLD 68
#define FA_PLD 68
#define FA_SMEM_FLOATS (64*FA_QLD + 64*FA_KLD + 64*FA_KLD + 128*FA_PLD)

extern __shared__ float fa_smem[];

__global__ void __launch_bounds__(256) flash_attn_kernel(
    const float* __restrict__ Q, const float* __restrict__ K,
    const float* __restrict__ V, const float* __restrict__ qer,
    float* __restrict__ O)
{
    float* Qs = fa_smem;
    float* Ks = Qs + 64 * FA_QLD;
    float* Vs = Ks + 64 * FA_KLD;
    float* Ps = Vs + 64 * FA_KLD;

    const float scale = 0.125f;
    int qt = blockIdx.x;
    int h = blockIdx.y, b = blockIdx.z;
    int q0 = qt * 128;
    const float* Qp = Q + (long long)b * 500 * 768 + h * 64;
    const float* Kp = K + (long long)b * 500 * 768 + h * 64;
    const float* Vp = V + (long long)b * 500 * 768 + h * 64;
    const float* qerp = qer + (long long)(b * 12 + h) * 250000;

    int tid = threadIdx.x;
    int tx = tid & 15, ty = tid >> 4;

#pragma unroll
    for (int i = 0; i < 8; i++) {
        int r = i * 16 + (tid >> 4);
        int d4 = (tid & 15) * 4;
        float4 v = make_float4(0.f, 0.f, 0.f, 0.f);
        if (q0 + r < 500) v = *(const float4*)(Qp + (long long)(q0 + r) * 768 + d4);
        Qs[(d4 + 0) * FA_QLD + r] = v.x;
        Qs[(d4 + 1) * FA_QLD + r] = v.y;
        Qs[(d4 + 2) * FA_QLD + r] = v.z;
        Qs[(d4 + 3) * FA_QLD + r] = v.w;
    }

    float m[8], l[8], o[8][4];
#pragma unroll
    for (int i = 0; i < 8; i++) {
        m[i] = -1e30f; l[i] = 0.f;
#pragma unroll
        for (int j = 0; j < 4; j++) o[i][j] = 0.f;
    }
    __syncthreads();

    for (int kt0 = 0; kt0 < 500; kt0 += 64) {
#pragma unroll
        for (int i = 0; i < 4; i++) {
            int r = i * 16 + (tid >> 4);
            int d4 = (tid & 15) * 4;
            float4 kv = make_float4(0.f, 0.f, 0.f, 0.f);
            float4 vv = make_float4(0.f, 0.f, 0.f, 0.f);
            if (kt0 + r < 500) {
                kv = *(const float4*)(Kp + (long long)(kt0 + r) * 768 + d4);
                vv = *(const float4*)(Vp + (long long)(kt0 + r) * 768 + d4);
            }
            Ks[(d4 + 0) * FA_KLD + r] = kv.x;
            Ks[(d4 + 1) * FA_KLD + r] = kv.y;
            Ks[(d4 + 2) * FA_KLD + r] = kv.z;
            Ks[(d4 + 3) * FA_KLD + r] = kv.w;
            *(float4*)(Vs + r * FA_KLD + d4) = vv;
        }
        __syncthreads();

        float S[8][4];
#pragma unroll
        for (int i = 0; i < 8; i++)
#pragma unroll
            for (int j = 0; j < 4; j++) S[i][j] = 0.f;
#pragma unroll
        for (int d = 0; d < 64; d++) {
            float a[8];
            *(float4*)&a[0] = *(const float4*)(Qs + d * FA_QLD + ty * 8);
            *(float4*)&a[4] = *(const float4*)(Qs + d * FA_QLD + ty * 8 + 4);
            float4 bb = *(const float4*)(Ks + d * FA_KLD + tx * 4);
#pragma unroll
            for (int i = 0; i < 8; i++) {
                S[i][0] += a[i] * bb.x; S[i][1] += a[i] * bb.y;
                S[i][2] += a[i] * bb.z; S[i][3] += a[i] * bb.w;
            }
        }
#pragma unroll
        for (int i = 0; i < 8; i++) {
            int q = q0 + ty * 8 + i;
#pragma unroll
            for (int j = 0; j < 4; j++) {
                int k = kt0 + tx * 4 + j;
                if (q < 500 && k < 500) {
                    float srel;
                    if (k <= q)          srel = qerp[(long long)q * 500 + 499 - q + k];
                    else if (k == q + 1) srel = 0.f;
                    else                 srel = qerp[(long long)(q + 1) * 500 + k - q - 2];
                    S[i][j] = S[i][j] * scale + srel;
                } else {
                    S[i][j] = -1e30f;
                }
            }
        }
#pragma unroll
        for (int i = 0; i < 8; i++) {
            float rmax = fmaxf(fmaxf(S[i][0], S[i][1]), fmaxf(S[i][2], S[i][3]));
#pragma unroll
            for (int off = 1; off < 16; off <<= 1)
                rmax = fmaxf(rmax, __shfl_xor_sync(0xffffffffu, rmax, off, 32));
            float mnew = fmaxf(m[i], rmax);
            float corr = __expf(m[i] - mnew);
            float rsum = 0.f;
#pragma unroll
            for (int j = 0; j < 4; j++) {
                S[i][j] = __expf(S[i][j] - mnew);
                rsum += S[i][j];
            }
#pragma unroll
            for (int off = 1; off < 16; off <<= 1)
                rsum += __shfl_xor_sync(0xffffffffu, rsum, off, 32);
            l[i] = l[i] * corr + rsum;
            m[i] = mnew;
#pragma unroll
            for (int j = 0; j < 4; j++) o[i][j] *= corr;
            *(float4*)(Ps + (long long)(ty * 8 + i) * FA_PLD + tx * 4) =
                make_float4(S[i][0], S[i][1], S[i][2], S[i][3]);
        }
        __syncthreads();

#pragma unroll
        for (int kk = 0; kk < 64; kk++) {
            float4 vr = *(const float4*)(Vs + kk * FA_KLD + tx * 4);
#pragma unroll
            for (int i = 0; i < 8; i++) {
                float p = Ps[(ty * 8 + i) * FA_PLD + kk];
                o[i][0] += p * vr.x; o[i][1] += p * vr.y;
                o[i][2] += p * vr.z; o[i][3] += p * vr.w;
            }
        }
        __syncthreads();
    }

    float* Op = O + (long long)b * 500 * 768 + h * 64;
#pragma unroll
    for (int i = 0; i < 8; i++) {
        int q = q0 + ty * 8 + i;
        if (q < 500) {
            float inv = 1.0f / l[i];
            *(float4*)(Op + (long long)q * 768 + tx * 4) =
                make_float4(o[i][0] * inv, o[i][1] * inv, o[i][2] * inv, o[i][3] * inv);
        }
    }
}

// ---------------- layernorm (row = 768) ----------------
__global__ void __launch_bounds__(256) layernorm_kernel(
    const float* __restrict__ in, float* __restrict__ out,
    const float* __restrict__ g, const float* __restrict__ b)
{
    __shared__ float red[256];
    int row = blockIdx.x, tid = threadIdx.x;
    const float* xp = in + (long long)row * 768;
    float v0 = xp[tid], v1 = xp[tid + 256], v2 = xp[tid + 512];
    red[tid] = v0 + v1 + v2;
    __syncthreads();
    for (int o = 128; o > 0; o >>= 1) { if (tid < o) red[tid] += red[tid + o]; __syncthreads(); }
    float mean = red[0] * (1.0f / 768.0f);
    __syncthreads();
    float d0 = v0 - mean, d1 = v1 - mean, d2 = v2 - mean;
    red[tid] = d0 * d0 + d1 * d1 + d2 * d2;
    __syncthreads();
    for (int o = 128; o > 0; o >>= 1) { if (tid < o) red[tid] += red[tid + o]; __syncthreads(); }
    float rstd = rsqrtf(red[0] * (1.0f / 768.0f) + 1e-5f);
    float* op = out + (long long)row * 768;
    op[tid]       = d0 * rstd * g[tid]       + b[tid];
    op[tid + 256] = d1 * rstd * g[tid + 256] + b[tid + 256];
    op[tid + 512] = d2 * rstd * g[tid + 512] + b[tid + 512];
}

// ---------------- orchestration ----------------
static void gemm_attn(const float* A, const float* Bm, float* C,
                      int M, int N, int K, int lda, int ldb, int ldc,
                      long long sAo, long long sAi, long long sBo, long long sBi,
                      long long sCo, long long sCi, int binner, int batch,
                      int transB, float alpha)
{
    dim3 grid((N + 63) / 64, (M + 63) / 64, batch);
    gemm_kernel<<<grid, 256>>>(A, Bm, C, M, N, K, lda, ldb, ldc,
                               sAo, sAi, sBo, sBi, sCo, sCi, binner, transB, alpha);
}

static void tc(const float* A, const float* B, const float* bias, const float* add,
               float* C, int M, int N, int K, int lda, int ldb, int ldc, int act)
{
    dim3 grid(N / 64, (M + 127) / 128);
    mma_gemm_kernel<<<grid, 256>>>(A, B, bias, add, C, M, N, K, lda, ldb, ldc, act);
}

extern "C" void kernel_launch(void* const* d_in, const int* in_sizes, int n_in,
                              void* d_out, int out_size)
{
    (void)in_sizes; (void)n_in; (void)out_size;
    const float* spec    = (const float*)d_in[0];
    const float* cw1     = (const float*)d_in[1];
    const float* cb1     = (const float*)d_in[2];
    const float* cw2     = (const float*)d_in[3];
    const float* cb2     = (const float*)d_in[4];
    const float* cw3     = (const float*)d_in[5];
    const float* cb3     = (const float*)d_in[6];
    const float* cw4     = (const float*)d_in[7];
    const float* cb4     = (const float*)d_in[8];
    const float* proj_w  = (const float*)d_in[9];
    const float* proj_b  = (const float*)d_in[10];
    const float* ln1_g   = (const float*)d_in[11];
    const float* ln1_b   = (const float*)d_in[12];
    const float* wq      = (const float*)d_in[13];
    const float* bq      = (const float*)d_in[14];
    const float* wk      = (const float*)d_in[15];
    const float* bk      = (const float*)d_in[16];
    const float* wv      = (const float*)d_in[17];
    const float* bv      = (const float*)d_in[18];
    const float* wo      = (const float*)d_in[19];
    const float* bo      = (const float*)d_in[20];
    const float* er      = (const float*)d_in[21];
    const float* ln2_g   = (const float*)d_in[22];
    const float* ln2_b   = (const float*)d_in[23];
    const float* w1      = (const float*)d_in[24];
    const float* b1      = (const float*)d_in[25];
    const float* w2      = (const float*)d_in[26];
    const float* b2      = (const float*)d_in[27];
    const float* deprj_w = (const float*)d_in[28];
    const float* deprj_b = (const float*)d_in[29];
    float* outp = (float*)d_out;

    float *bufA, *bufB, *qer, *x, *xn, *q, *k, *v, *o;
    cudaGetSymbolAddress((void**)&bufA, g_bufA);
    cudaGetSymbolAddress((void**)&bufB, g_bufB);
    cudaGetSymbolAddress((void**)&qer,  g_qer);
    cudaGetSymbolAddress((void**)&x,    g_x);
    cudaGetSymbolAddress((void**)&xn,   g_xn);
    cudaGetSymbolAddress((void**)&q,    g_q);
    cudaGetSymbolAddress((void**)&k,    g_k);
    cudaGetSymbolAddress((void**)&v,    g_v);
    cudaGetSymbolAddress((void**)&o,    g_o);
    float* hbuf = bufB;

    const int fa_smem_bytes = FA_SMEM_FLOATS * 4;
    cudaFuncSetAttribute(flash_attn_kernel,
                         cudaFuncAttributeMaxDynamicSharedMemorySize, fa_smem_bytes);

    dim3 cblk(32, 4);
    // --- CNN with fused GELU+maxpool (H-tile 24) ---
    conv5x5_gelu_pool<<<dim3(16, 8 * 8, 16), cblk>>>(spec, cw1, cb1, bufB, 1, 32, 192);
    conv5x5_gelu_pool<<<dim3(16, 4 * 16, 16), cblk>>>(bufB, cw2, cb2, bufA, 32, 64, 96);
    conv5x5_gelu_pool<<<dim3(16, 2 * 16, 16), cblk>>>(bufA, cw3, cb3, bufB, 64, 64, 48);
    conv5x5_gelu_pool<<<dim3(16, 1 * 16, 16), cblk>>>(bufB, cw4, cb4, bufA, 64, 64, 24);
    transpose_kernel<<<dim3(24, 16, 16), dim3(32, 8)>>>(bufA, xn);

    // proj
    tc(xn, proj_w, proj_b, 0, x, 8000, 768, 768, 768, 768, 768, 0);

    const float scale = 0.125f;
    const long long sQ = (long long)T_ * D_;
    const long long sS = 12LL * T_ * T_;
    const long long sSi = (long long)T_ * T_;

    for (int i = 0; i < L_; i++) {
        layernorm_kernel<<<8000, 256>>>(x, xn, ln1_g + i * 768, ln1_b + i * 768);
        tc(xn, wq + (long long)i * 768 * 768, bq + i * 768, 0, q, 8000, 768, 768, 768, 768, 768, 0);
        tc(xn, wk + (long long)i * 768 * 768, bk + i * 768, 0, k, 8000, 768, 768, 768, 768, 768, 0);
        tc(xn, wv + (long long)i * 768 * 768, bv + i * 768, 0, v, 8000, 768, 768, 768, 768, 768, 0);
        // qer = scale * Q er^T
        gemm_attn(q, er + (long long)i * 500 * 64, qer, 500, 500, 64, 768, 64, 500,
                  sQ, 64, 0, 0, sS, sSi, 12, 192, 1, scale);
        flash_attn_kernel<<<dim3(4, 12, 16), 256, fa_smem_bytes>>>(q, k, v, qer, o);
        // x = x + o @ wo + bo
        tc(o, wo + (long long)i * 768 * 768, bo + i * 768, x, x, 8000, 768, 768, 768, 768, 768, 0);
        layernorm_kernel<<<8000, 256>>>(x, xn, ln2_g + i * 768, ln2_b + i * 768);
        // h = gelu(xn @ w1 + b1)
        tc(xn, w1 + (long long)i * 768 * 3072, b1 + i * 3072, 0, hbuf, 8000, 3072, 768,
           768, 3072, 3072, 1);
        // x = x + h @ w2 + b2
        tc(hbuf, w2 + (long long)i * 3072 * 768, b2 + i * 768, x, x, 8000, 768, 3072,
           3072, 768, 768, 0);
    }
    // final deproj
    tc(x, deprj_w, deprj_b, 0, outp, 8000, 192, 768, 768, 192, 192, 0);
}

// round 7
// speedup vs baseline: 2.1609x; 1.1739x over previous
#include <cuda_runtime.h>
#include <math.h>
#include <stdint.h>

#define Bb_ 16
#define T_ 500
#define D_ 768
#define FFN_ 3072
#define NH_ 12
#define DH_ 64
#define L_ 3

// ---------------- scratch (device globals; no allocation) ----------------
__device__ float g_bufA[49152000];   // conv ping
__device__ float g_bufB[24576000];   // conv pong / FFN hidden
__device__ float g_qer[48000000];    // qer buffer
__device__ float g_x[6144000];
__device__ float g_xn[6144000];
__device__ float g_q[6144000];
__device__ float g_k[6144000];
__device__ float g_v[6144000];
__device__ float g_o[6144000];

__device__ __forceinline__ float gelu_f(float x) {
    return 0.5f * x * (1.0f + erff(x * 0.7071067811865475f));
}

__device__ __forceinline__ uint32_t tf32_rn(float x) {
    uint32_t r; asm("cvt.rna.tf32.f32 %0, %1;" : "=r"(r) : "f"(x));
    return r;
}

// ---- packed f32x2 helpers (Blackwell FFMA2; PTX requires sm_100+) ----
__device__ __forceinline__ unsigned long long pack_f32x2(float lo, float hi) {
    unsigned long long d;
    asm("mov.b64 %0, {%1, %2};" : "=l"(d) : "r"(__float_as_uint(lo)), "r"(__float_as_uint(hi)));
    return d;
}
__device__ __forceinline__ void unpack_f32x2(float& lo, float& hi, unsigned long long v) {
    uint32_t a, b;
    asm("mov.b64 {%0, %1}, %2;" : "=r"(a), "=r"(b) : "l"(v));
    lo = __uint_as_float(a); hi = __uint_as_float(b);
}
__device__ __forceinline__ void fma2(unsigned long long& d, unsigned long long a,
                                     unsigned long long b) {
    asm("fma.rn.f32x2 %0, %1, %2, %0;" : "+l"(d) : "l"(a), "l"(b));
}

// ---------------- tensor-core dense GEMM via mma.sync (tf32) ----------------
// C = act(A @ B + bias) (+ addsrc). A: [M][K] row-major. B: [K][N] row-major.
// CTA tile 128(M) x 128(N), K-step 32. 8 warps: 4(m) x 2(n), warp tile 32x64.
// mma.sync.m16n8k8 tf32. Requires K%32==0, N%8==0.
#define ALD 136   // pad so fragment bank = (8*tig + grp) % 32 -> conflict-free

__global__ void __launch_bounds__(256) mma_gemm_kernel(
    const float* __restrict__ A, const float* __restrict__ Bm,
    const float* __restrict__ bias, const float* __restrict__ addsrc,
    float* __restrict__ C, int M, int N, int K,
    int lda, int ldb, int ldc, int act)
{
    __shared__ float As[32 * ALD];   // [k][m] 32 x 128 (+pad)
    __shared__ float Bs[32 * ALD];   // [k][n] 32 x 128 (+pad)

    int tid = threadIdx.x;
    int wid = tid >> 5, lane = tid & 31;
    int grp = lane >> 2, tig = lane & 3;
    int wm = wid & 3, wn = wid >> 2;           // warp -> (m,n) tile: 4 x 2
    int m0 = blockIdx.y * 128, n0 = blockIdx.x * 128;

    // A staging: thread -> row m=tid>>1 (0..127), k half (tid&1)*16
    int am = tid >> 1;
    int akh = (tid & 1) * 16;
    // B staging: thread -> k rows {tid>>4, tid>>4+16}, n chunk (tid&15)*8
    int bkr = tid >> 4;
    int bn = (tid & 15) * 8;

    float acc[2][8][4];
#pragma unroll
    for (int i = 0; i < 2; i++)
#pragma unroll
        for (int j = 0; j < 8; j++)
#pragma unroll
            for (int r = 0; r < 4; r++) acc[i][j][r] = 0.f;

    float4 pa[4], pb[2][2];
    // prologue load k-tile 0
    {
        const float* Ap = (m0 + am < M) ? A + (long long)am * lda + (long long)m0 * lda + akh : (const float*)0;
#pragma unroll
        for (int i = 0; i < 4; i++)
            pa[i] = Ap ? *(const float4*)(Ap + i * 4) : make_float4(0.f, 0.f, 0.f, 0.f);
#pragma unroll
        for (int p = 0; p < 2; p++) {
            const float* Bp = Bm + (long long)(bkr + p * 16) * ldb + n0 + bn;
            bool okn = (n0 + bn < N);
            pb[p][0] = okn ? *(const float4*)(Bp)     : make_float4(0.f, 0.f, 0.f, 0.f);
            pb[p][1] = okn ? *(const float4*)(Bp + 4) : make_float4(0.f, 0.f, 0.f, 0.f);
        }
    }

    for (int k0 = 0;; k0 += 32) {
        // store staged tile (tf32-rounded)
#pragma unroll
        for (int i = 0; i < 4; i++) {
            int kk = akh + i * 4;
            *(uint32_t*)&As[(kk + 0) * ALD + am] = tf32_rn(pa[i].x);
            *(uint32_t*)&As[(kk + 1) * ALD + am] = tf32_rn(pa[i].y);
            *(uint32_t*)&As[(kk + 2) * ALD + am] = tf32_rn(pa[i].z);
            *(uint32_t*)&As[(kk + 3) * ALD + am] = tf32_rn(pa[i].w);
        }
#pragma unroll
        for (int p = 0; p < 2; p++) {
            uint32_t* bsp = (uint32_t*)&Bs[(bkr + p * 16) * ALD + bn];
            bsp[0] = tf32_rn(pb[p][0].x); bsp[1] = tf32_rn(pb[p][0].y);
            bsp[2] = tf32_rn(pb[p][0].z); bsp[3] = tf32_rn(pb[p][0].w);
            bsp[4] = tf32_rn(pb[p][1].x); bsp[5] = tf32_rn(pb[p][1].y);
            bsp[6] = tf32_rn(pb[p][1].z); bsp[7] = tf32_rn(pb[p][1].w);
        }
        __syncthreads();

        bool last = (k0 + 32 >= K);
        if (!last) {
            int kn = k0 + 32;
            const float* Ap = (m0 + am < M) ? A + (long long)(m0 + am) * lda + kn + akh : (const float*)0;
#pragma unroll
            for (int i = 0; i < 4; i++)
                pa[i] = Ap ? *(const float4*)(Ap + i * 4) : make_float4(0.f, 0.f, 0.f, 0.f);
#pragma unroll
            for (int p = 0; p < 2; p++) {
                const float* Bp = Bm + (long long)(kn + bkr + p * 16) * ldb + n0 + bn;
                bool okn = (n0 + bn < N);
                pb[p][0] = okn ? *(const float4*)(Bp)     : make_float4(0.f, 0.f, 0.f, 0.f);
                pb[p][1] = okn ? *(const float4*)(Bp + 4) : make_float4(0.f, 0.f, 0.f, 0.f);
            }
        }

        // compute: 4 k8 sub-steps, 16 mma each warp
#pragma unroll
        for (int ks = 0; ks < 4; ks++) {
            int kb = ks * 8;
            uint32_t a[2][4], b[8][2];
            int mB = wm * 32;
#pragma unroll
            for (int mf = 0; mf < 2; mf++) {
                int mb = mB + mf * 16 + grp;
                a[mf][0] = *(const uint32_t*)&As[(kb + tig) * ALD + mb];
                a[mf][1] = *(const uint32_t*)&As[(kb + tig) * ALD + mb + 8];
                a[mf][2] = *(const uint32_t*)&As[(kb + tig + 4) * ALD + mb];
                a[mf][3] = *(const uint32_t*)&As[(kb + tig + 4) * ALD + mb + 8];
            }
            int nB = wn * 64;
#pragma unroll
            for (int nf = 0; nf < 8; nf++) {
                int nb = nB + nf * 8 + grp;
                b[nf][0] = *(const uint32_t*)&Bs[(kb + tig) * ALD + nb];
                b[nf][1] = *(const uint32_t*)&Bs[(kb + tig + 4) * ALD + nb];
            }
#pragma unroll
            for (int mf = 0; mf < 2; mf++)
#pragma unroll
                for (int nf = 0; nf < 8; nf++) {
                    asm volatile(
                        "mma.sync.aligned.m16n8k8.row.col.f32.tf32.tf32.f32 "
                        "{%0,%1,%2,%3}, {%4,%5,%6,%7}, {%8,%9}, {%0,%1,%2,%3};"
                        : "+f"(acc[mf][nf][0]), "+f"(acc[mf][nf][1]),
                          "+f"(acc[mf][nf][2]), "+f"(acc[mf][nf][3])
                        : "r"(a[mf][0]), "r"(a[mf][1]), "r"(a[mf][2]), "r"(a[mf][3]),
                          "r"(b[nf][0]), "r"(b[nf][1]));
                }
        }
        if (last) break;
        __syncthreads();
    }

    // epilogue
#pragma unroll
    for (int mf = 0; mf < 2; mf++) {
#pragma unroll
        for (int r = 0; r < 2; r++) {
            int m = m0 + wm * 32 + mf * 16 + grp + r * 8;
            if (m >= M) continue;
            float* Cp = C + (long long)m * ldc;
            const float* addp = addsrc ? addsrc + (long long)m * ldc : (const float*)0;
#pragma unroll
            for (int nf = 0; nf < 8; nf++) {
                int n = n0 + wn * 64 + nf * 8 + tig * 2;
                if (n >= N) continue;
                float v0 = acc[mf][nf][r * 2 + 0] + bias[n];
                float v1 = acc[mf][nf][r * 2 + 1] + bias[n + 1];
                if (act) { v0 = gelu_f(v0); v1 = gelu_f(v1); }
                if (addp) { v0 += addp[n]; v1 += addp[n + 1]; }
                Cp[n] = v0; Cp[n + 1] = v1;
            }
        }
    }
}

// ---------------- conv 5x5, pad 2, + GELU + freq-maxpool(2,1), f32x2 packed ------
// block 32x4; tile 64(W, x-pairs per thread) x 24(H in-rows) x 4 out-channels.
__global__ void __launch_bounds__(128) conv5x5_gelu_pool(
    const float* __restrict__ in, const float* __restrict__ w,
    const float* __restrict__ bias, float* __restrict__ out,
    int Ci, int Co, int H)
{
    const int W = 500;
    __shared__ float tile[28][72];   // 24 rows + 4 halo, 64 cols + 4 halo (pad to 72)
    __shared__ float ws[6400];
    int tx = threadIdx.x, ty = threadIdx.y;
    int tid = ty * 32 + tx;
    int hBlocks = H / 24;
    int x0 = blockIdx.x * 64;
    int y0 = (blockIdx.y % hBlocks) * 24;
    int co0 = (blockIdx.y / hBlocks) * 4;
    int b = blockIdx.z;
    int HP = H >> 1;

    int wtot = 4 * Ci * 25;
    const float* wbase = w + (long long)co0 * Ci * 25;
    for (int s = tid; s < wtot; s += 128) ws[s] = wbase[s];

    unsigned long long acc2[4][6];
#pragma unroll
    for (int i = 0; i < 4; i++)
#pragma unroll
        for (int j = 0; j < 6; j++) acc2[i][j] = 0ull;

    for (int ci = 0; ci < Ci; ci++) {
        const float* ip = in + ((long long)(b * Ci + ci)) * H * W;
        for (int idx = tid; idx < 28 * 68; idx += 128) {
            int r = idx / 68, c = idx % 68;
            int gy = y0 + r - 2, gx = x0 + c - 2;
            tile[r][c] = (gy >= 0 && gy < H && gx >= 0 && gx < W) ? ip[gy * W + gx] : 0.f;
        }
        __syncthreads();
#pragma unroll
        for (int dx = 0; dx < 5; dx++) {
            unsigned long long v2[10];
#pragma unroll
            for (int rr = 0; rr < 10; rr++)
                v2[rr] = pack_f32x2(tile[ty * 6 + rr][2 * tx + dx],
                                    tile[ty * 6 + rr][2 * tx + dx + 1]);
#pragma unroll
            for (int c4 = 0; c4 < 4; c4++) {
                const float* wp = ws + (c4 * Ci + ci) * 25 + dx;
#pragma unroll
                for (int dy = 0; dy < 5; dy++) {
                    float wv = wp[dy * 5];
                    unsigned long long w2 = pack_f32x2(wv, wv);
#pragma unroll
                    for (int ry = 0; ry < 6; ry++) fma2(acc2[c4][ry], v2[ry + dy], w2);
                }
            }
        }
        __syncthreads();
    }
    int xe = x0 + 2 * tx;       // even x of the pair
#pragma unroll
    for (int c4 = 0; c4 < 4; c4++) {
        float bv = bias[co0 + c4];
#pragma unroll
        for (int p = 0; p < 3; p++) {
            int y = y0 + ty * 6 + 2 * p;
            float a0, a1, b0, b1;
            unpack_f32x2(a0, a1, acc2[c4][2 * p]);
            unpack_f32x2(b0, b1, acc2[c4][2 * p + 1]);
            float r0 = fmaxf(gelu_f(a0 + bv), gelu_f(b0 + bv));
            float r1 = fmaxf(gelu_f(a1 + bv), gelu_f(b1 + bv));
            long long base = (((long long)b * Co + co0 + c4) * HP + (y >> 1)) * W;
            if (xe < W)     out[base + xe]     = r0;
            if (xe + 1 < W) out[base + xe + 1] = r1;
        }
    }
}

// ---------------- transpose [B,768,500] -> [B,500,768] ----------------
__global__ void transpose_kernel(const float* __restrict__ in, float* __restrict__ out)
{
    __shared__ float t[32][33];
    int b = blockIdx.z;
    int k0 = blockIdx.x * 32;
    int t0 = blockIdx.y * 32;
    int tx = threadIdx.x, ty = threadIdx.y;
    const float* ip = in + (long long)b * 768 * 500;
    float* op = out + (long long)b * 500 * 768;
#pragma unroll
    for (int r = 0; r < 32; r += 8) {
        int kk = k0 + ty + r, tt = t0 + tx;
        t[ty + r][tx] = (tt < 500) ? ip[(long long)kk * 500 + tt] : 0.f;
    }
    __syncthreads();
#pragma unroll
    for (int r = 0; r < 32; r += 8) {
        int tt = t0 + ty + r, kk = k0 + tx;
        if (tt < 500) op[(long long)tt * 768 + kk] = t[tx][ty + r];
    }
}

// ---------------- small batched GEMM (qer = scale * Q er^T) ----------
__global__ void __launch_bounds__(256) gemm_kernel(
    const float* __restrict__ A, const float* __restrict__ Bm,
    float* __restrict__ C,
    int M, int N, int K, int lda, int ldb, int ldc,
    long long sAo, long long sAi, long long sBo, long long sBi,
    long long sCo, long long sCi, int batchInner,
    int transB, float alpha)
{
    __shared__ float As[16][64];
    __shared__ float Bs[16][68];

    int zo = blockIdx.z / batchInner, zi = blockIdx.z % batchInner;
    A  += (long long)zo * sAo + (long long)zi * sAi;
    Bm += (long long)zo * sBo + (long long)zi * sBi;
    long long coff = (long long)zo * sCo + (long long)zi * sCi;

    int m0 = blockIdx.y * 64, n0 = blockIdx.x * 64;
    int tid = threadIdx.x;
    int tx = tid % 16, ty = tid / 16;

    float acc[4][4];
#pragma unroll
    for (int i = 0; i < 4; i++)
#pragma unroll
        for (int j = 0; j < 4; j++) acc[i][j] = 0.f;

    int am = tid / 4;
    int ak = (tid % 4) * 4;
    int bn_nt = tid % 64;
    int bk_nt = (tid / 64) * 4;
    int bk_t = tid % 16;
    int bn_t = (tid / 16) * 4;

    for (int k0 = 0; k0 < K; k0 += 16) {
#pragma unroll
        for (int r = 0; r < 4; r++) {
            int kk = k0 + ak + r;
            As[ak + r][am] = (m0 + am < M && kk < K) ? A[(long long)(m0 + am) * lda + kk] : 0.f;
        }
        if (!transB) {
#pragma unroll
            for (int r = 0; r < 4; r++) {
                int kk = k0 + bk_nt + r;
                Bs[bk_nt + r][bn_nt] = (kk < K && n0 + bn_nt < N)
                                           ? Bm[(long long)kk * ldb + n0 + bn_nt] : 0.f;
            }
        } else {
#pragma unroll
            for (int r = 0; r < 4; r++) {
                int n = n0 + bn_t + r;
                int kk = k0 + bk_t;
                Bs[bk_t][bn_t + r] = (kk < K && n < N) ? Bm[(long long)n * ldb + kk] : 0.f;
            }
        }
        __syncthreads();
#pragma unroll
        for (int kk = 0; kk < 16; kk++) {
            float4 a = *(const float4*)&As[kk][ty * 4];
            float4 b = *(const float4*)&Bs[kk][tx * 4];
            acc[0][0] += a.x * b.x; acc[0][1] += a.x * b.y; acc[0][2] += a.x * b.z; acc[0][3] += a.x * b.w;
            acc[1][0] += a.y * b.x; acc[1][1] += a.y * b.y; acc[1][2] += a.y * b.z; acc[1][3] += a.y * b.w;
            acc[2][0] += a.z * b.x; acc[2][1] += a.z * b.y; acc[2][2] += a.z * b.z; acc[2][3] += a.z * b.w;
            acc[3][0] += a.w * b.x; acc[3][1] += a.w * b.y; acc[3][2] += a.w * b.z; acc[3][3] += a.w * b.w;
        }
        __syncthreads();
    }

    float* Cp = C + coff;
#pragma unroll
    for (int i = 0; i < 4; i++) {
        int m = m0 + ty * 4 + i;
        if (m >= M) continue;
#pragma unroll
        for (int j = 0; j < 4; j++) {
            int n = n0 + tx * 4 + j;
            if (n >= N) continue;
            Cp[(long long)m * ldc + n] = acc[i][j] * alpha;
        }
    }
}

// ---------------- flash attention (fused QK^T + skew + softmax + PV) ------------
#define FA_QLD 132
#define FA_KLD 68
#define FA_PLD 68
#define FA_SMEM_FLOATS (64*FA_QLD + 64*FA_KLD + 64*FA_KLD + 128*FA_PLD)

extern __shared__ float fa_smem[];

__global__ void __launch_bounds__(256) flash_attn_kernel(
    const float* __restrict__ Q, const float* __restrict__ K,
    const float* __restrict__ V, const float* __restrict__ qer,
    float* __restrict__ O)
{
    float* Qs = fa_smem;
    float* Ks = Qs + 64 * FA_QLD;
    float* Vs = Ks + 64 * FA_KLD;
    float* Ps = Vs + 64 * FA_KLD;

    const float scale = 0.125f;
    int qt = blockIdx.x;
    int h = blockIdx.y, b = blockIdx.z;
    int q0 = qt * 128;
    const float* Qp = Q + (long long)b * 500 * 768 + h * 64;
    const float* Kp = K + (long long)b * 500 * 768 + h * 64;
    const float* Vp = V + (long long)b * 500 * 768 + h * 64;
    const float* qerp = qer + (long long)(b * 12 + h) * 250000;

    int tid = threadIdx.x;
    int tx = tid & 15, ty = tid >> 4;

#pragma unroll
    for (int i = 0; i < 8; i++) {
        int r = i * 16 + (tid >> 4);
        int d4 = (tid & 15) * 4;
        float4 v = make_float4(0.f, 0.f, 0.f, 0.f);
        if (q0 + r < 500) v = *(const float4*)(Qp + (long long)(q0 + r) * 768 + d4);
        Qs[(d4 + 0) * FA_QLD + r] = v.x;
        Qs[(d4 + 1) * FA_QLD + r] = v.y;
        Qs[(d4 + 2) * FA_QLD + r] = v.z;
        Qs[(d4 + 3) * FA_QLD + r] = v.w;
    }

    float m[8], l[8], o[8][4];
#pragma unroll
    for (int i = 0; i < 8; i++) {
        m[i] = -1e30f; l[i] = 0.f;
#pragma unroll
        for (int j = 0; j < 4; j++) o[i][j] = 0.f;
    }
    __syncthreads();

    for (int kt0 = 0; kt0 < 500; kt0 += 64) {
#pragma unroll
        for (int i = 0; i < 4; i++) {
            int r = i * 16 + (tid >> 4);
            int d4 = (tid & 15) * 4;
            float4 kv = make_float4(0.f, 0.f, 0.f, 0.f);
            float4 vv = make_float4(0.f, 0.f, 0.f, 0.f);
            if (kt0 + r < 500) {
                kv = *(const float4*)(Kp + (long long)(kt0 + r) * 768 + d4);
                vv = *(const float4*)(Vp + (long long)(kt0 + r) * 768 + d4);
            }
            Ks[(d4 + 0) * FA_KLD + r] = kv.x;
            Ks[(d4 + 1) * FA_KLD + r] = kv.y;
            Ks[(d4 + 2) * FA_KLD + r] = kv.z;
            Ks[(d4 + 3) * FA_KLD + r] = kv.w;
            *(float4*)(Vs + r * FA_KLD + d4) = vv;
        }
        __syncthreads();

        float S[8][4];
#pragma unroll
        for (int i = 0; i < 8; i++)
#pragma unroll
            for (int j = 0; j < 4; j++) S[i][j] = 0.f;
#pragma unroll
        for (int d = 0; d < 64; d++) {
            float a[8];
            *(float4*)&a[0] = *(const float4*)(Qs + d * FA_QLD + ty * 8);
            *(float4*)&a[4] = *(const float4*)(Qs + d * FA_QLD + ty * 8 + 4);
            float4 bb = *(const float4*)(Ks + d * FA_KLD + tx * 4);
#pragma unroll
            for (int i = 0; i < 8; i++) {
                S[i][0] += a[i] * bb.x; S[i][1] += a[i] * bb.y;
                S[i][2] += a[i] * bb.z; S[i][3] += a[i] * bb.w;
            }
        }
#pragma unroll
        for (int i = 0; i < 8; i++) {
            int q = q0 + ty * 8 + i;
#pragma unroll
            for (int j = 0; j < 4; j++) {
                int k = kt0 + tx * 4 + j;
                if (q < 500 && k < 500) {
                    float srel;
                    if (k <= q)          srel = qerp[(long long)q * 500 + 499 - q + k];
                    else if (k == q + 1) srel = 0.f;
                    else                 srel = qerp[(long long)(q + 1) * 500 + k - q - 2];
                    S[i][j] = S[i][j] * scale + srel;
                } else {
                    S[i][j] = -1e30f;
                }
            }
        }
#pragma unroll
        for (int i = 0; i < 8; i++) {
            float rmax = fmaxf(fmaxf(S[i][0], S[i][1]), fmaxf(S[i][2], S[i][3]));
#pragma unroll
            for (int off = 1; off < 16; off <<= 1)
                rmax = fmaxf(rmax, __shfl_xor_sync(0xffffffffu, rmax, off, 32));
            float mnew = fmaxf(m[i], rmax);
            float corr = __expf(m[i] - mnew);
            float rsum = 0.f;
#pragma unroll
            for (int j = 0; j < 4; j++) {
                S[i][j] = __expf(S[i][j] - mnew);
                rsum += S[i][j];
            }
#pragma unroll
            for (int off = 1; off < 16; off <<= 1)
                rsum += __shfl_xor_sync(0xffffffffu, rsum, off, 32);
            l[i] = l[i] * corr + rsum;
            m[i] = mnew;
#pragma unroll
            for (int j = 0; j < 4; j++) o[i][j] *= corr;
            *(float4*)(Ps + (long long)(ty * 8 + i) * FA_PLD + tx * 4) =
                make_float4(S[i][0], S[i][1], S[i][2], S[i][3]);
        }
        __syncthreads();

#pragma unroll
        for (int kk = 0; kk < 64; kk++) {
            float4 vr = *(const float4*)(Vs + kk * FA_KLD + tx * 4);
#pragma unroll
            for (int i = 0; i < 8; i++) {
                float p = Ps[(ty * 8 + i) * FA_PLD + kk];
                o[i][0] += p * vr.x; o[i][1] += p * vr.y;
                o[i][2] += p * vr.z; o[i][3] += p * vr.w;
            }
        }
        __syncthreads();
    }

    float* Op = O + (long long)b * 500 * 768 + h * 64;
#pragma unroll
    for (int i = 0; i < 8; i++) {
        int q = q0 + ty * 8 + i;
        if (q < 500) {
            float inv = 1.0f / l[i];
            *(float4*)(Op + (long long)q * 768 + tx * 4) =
                make_float4(o[i][0] * inv, o[i][1] * inv, o[i][2] * inv, o[i][3] * inv);
        }
    }
}

// ---------------- layernorm (row = 768) ----------------
__global__ void __launch_bounds__(256) layernorm_kernel(
    const float* __restrict__ in, float* __restrict__ out,
    const float* __restrict__ g, const float* __restrict__ b)
{
    __shared__ float red[256];
    int row = blockIdx.x, tid = threadIdx.x;
    const float* xp = in + (long long)row * 768;
    float v0 = xp[tid], v1 = xp[tid + 256], v2 = xp[tid + 512];
    red[tid] = v0 + v1 + v2;
    __syncthreads();
    for (int o = 128; o > 0; o >>= 1) { if (tid < o) red[tid] += red[tid + o]; __syncthreads(); }
    float mean = red[0] * (1.0f / 768.0f);
    __syncthreads();
    float d0 = v0 - mean, d1 = v1 - mean, d2 = v2 - mean;
    red[tid] = d0 * d0 + d1 * d1 + d2 * d2;
    __syncthreads();
    for (int o = 128; o > 0; o >>= 1) { if (tid < o) red[tid] += red[tid + o]; __syncthreads(); }
    float rstd = rsqrtf(red[0] * (1.0f / 768.0f) + 1e-5f);
    float* op = out + (long long)row * 768;
    op[tid]       = d0 * rstd * g[tid]       + b[tid];
    op[tid + 256] = d1 * rstd * g[tid + 256] + b[tid + 256];
    op[tid + 512] = d2 * rstd * g[tid + 512] + b[tid + 512];
}

// ---------------- orchestration ----------------
static void gemm_attn(const float* A, const float* Bm, float* C,
                      int M, int N, int K, int lda, int ldb, int ldc,
                      long long sAo, long long sAi, long long sBo, long long sBi,
                      long long sCo, long long sCi, int binner, int batch,
                      int transB, float alpha)
{
    dim3 grid((N + 63) / 64, (M + 63) / 64, batch);
    gemm_kernel<<<grid, 256>>>(A, Bm, C, M, N, K, lda, ldb, ldc,
                               sAo, sAi, sBo, sBi, sCo, sCi, binner, transB, alpha);
}

static void tc(const float* A, const float* B, const float* bias, const float* add,
               float* C, int M, int N, int K, int lda, int ldb, int ldc, int act)
{
    dim3 grid((N + 127) / 128, (M + 127) / 128);
    mma_gemm_kernel<<<grid, 256>>>(A, B, bias, add, C, M, N, K, lda, ldb, ldc, act);
}

extern "C" void kernel_launch(void* const* d_in, const int* in_sizes, int n_in,
                              void* d_out, int out_size)
{
    (void)in_sizes; (void)n_in; (void)out_size;
    const float* spec    = (const float*)d_in[0];
    const float* cw1     = (const float*)d_in[1];
    const float* cb1     = (const float*)d_in[2];
    const float* cw2     = (const float*)d_in[3];
    const float* cb2     = (const float*)d_in[4];
    const float* cw3     = (const float*)d_in[5];
    const float* cb3     = (const float*)d_in[6];
    const float* cw4     = (const float*)d_in[7];
    const float* cb4     = (const float*)d_in[8];
    const float* proj_w  = (const float*)d_in[9];
    const float* proj_b  = (const float*)d_in[10];
    const float* ln1_g   = (const float*)d_in[11];
    const float* ln1_b   = (const float*)d_in[12];
    const float* wq      = (const float*)d_in[13];
    const float* bq      = (const float*)d_in[14];
    const float* wk      = (const float*)d_in[15];
    const float* bk      = (const float*)d_in[16];
    const float* wv      = (const float*)d_in[17];
    const float* bv      = (const float*)d_in[18];
    const float* wo      = (const float*)d_in[19];
    const float* bo      = (const float*)d_in[20];
    const float* er      = (const float*)d_in[21];
    const float* ln2_g   = (const float*)d_in[22];
    const float* ln2_b   = (const float*)d_in[23];
    const float* w1      = (const float*)d_in[24];
    const float* b1      = (const float*)d_in[25];
    const float* w2      = (const float*)d_in[26];
    const float* b2      = (const float*)d_in[27];
    const float* deprj_w = (const float*)d_in[28];
    const float* deprj_b = (const float*)d_in[29];
    float* outp = (float*)d_out;

    float *bufA, *bufB, *qer, *x, *xn, *q, *k, *v, *o;
    cudaGetSymbolAddress((void**)&bufA, g_bufA);
    cudaGetSymbolAddress((void**)&bufB, g_bufB);
    cudaGetSymbolAddress((void**)&qer,  g_qer);
    cudaGetSymbolAddress((void**)&x,    g_x);
    cudaGetSymbolAddress((void**)&xn,   g_xn);
    cudaGetSymbolAddress((void**)&q,    g_q);
    cudaGetSymbolAddress((void**)&k,    g_k);
    cudaGetSymbolAddress((void**)&v,    g_v);
    cudaGetSymbolAddress((void**)&o,    g_o);
    float* hbuf = bufB;

    const int fa_smem_bytes = FA_SMEM_FLOATS * 4;
    cudaFuncSetAttribute(flash_attn_kernel,
                         cudaFuncAttributeMaxDynamicSharedMemorySize, fa_smem_bytes);

    dim3 cblk(32, 4);
    // --- CNN with fused GELU+maxpool (x-tile 64, H-tile 24) ---
    conv5x5_gelu_pool<<<dim3(8, 8 * 8, 16), cblk>>>(spec, cw1, cb1, bufB, 1, 32, 192);
    conv5x5_gelu_pool<<<dim3(8, 4 * 16, 16), cblk>>>(bufB, cw2, cb2, bufA, 32, 64, 96);
    conv5x5_gelu_pool<<<dim3(8, 2 * 16, 16), cblk>>>(bufA, cw3, cb3, bufB, 64, 64, 48);
    conv5x5_gelu_pool<<<dim3(8, 1 * 16, 16), cblk>>>(bufB, cw4, cb4, bufA, 64, 64, 24);
    transpose_kernel<<<dim3(24, 16, 16), dim3(32, 8)>>>(bufA, xn);

    // proj
    tc(xn, proj_w, proj_b, 0, x, 8000, 768, 768, 768, 768, 768, 0);

    const float scale = 0.125f;
    const long long sQ = (long long)T_ * D_;
    const long long sS = 12LL * T_ * T_;
    const long long sSi = (long long)T_ * T_;

    for (int i = 0; i < L_; i++) {
        layernorm_kernel<<<8000, 256>>>(x, xn, ln1_g + i * 768, ln1_b + i * 768);
        tc(xn, wq + (long long)i * 768 * 768, bq + i * 768, 0, q, 8000, 768, 768, 768, 768, 768, 0);
        tc(xn, wk + (long long)i * 768 * 768, bk + i * 768, 0, k, 8000, 768, 768, 768, 768, 768, 0);
        tc(xn, wv + (long long)i * 768 * 768, bv + i * 768, 0, v, 8000, 768, 768, 768, 768, 768, 0);
        // qer = scale * Q er^T
        gemm_attn(q, er + (long long)i * 500 * 64, qer, 500, 500, 64, 768, 64, 500,
                  sQ, 64, 0, 0, sS, sSi, 12, 192, 1, scale);
        flash_attn_kernel<<<dim3(4, 12, 16), 256, fa_smem_bytes>>>(q, k, v, qer, o);
        // x = x + o @ wo + bo
        tc(o, wo + (long long)i * 768 * 768, bo + i * 768, x, x, 8000, 768, 768, 768, 768, 768, 0);
        layernorm_kernel<<<8000, 256>>>(x, xn, ln2_g + i * 768, ln2_b + i * 768);
        // h = gelu(xn @ w1 + b1)
        tc(xn, w1 + (long long)i * 768 * 3072, b1 + i * 3072, 0, hbuf, 8000, 3072, 768,
           768, 3072, 3072, 1);
        // x = x + h @ w2 + b2
        tc(hbuf, w2 + (long long)i * 3072 * 768, b2 + i * 768, x, x, 8000, 768, 3072,
           3072, 768, 768, 0);
    }
    // final deproj
    tc(x, deprj_w, deprj_b, 0, outp, 8000, 192, 768, 768, 192, 192, 0);
}

// round 8
// speedup vs baseline: 2.2413x; 1.0372x over previous
#include <cuda_runtime.h>
#include <math.h>
#include <stdint.h>

#define Bb_ 16
#define T_ 500
#define D_ 768
#define FFN_ 3072
#define NH_ 12
#define DH_ 64
#define L_ 3

// ---------------- scratch (device globals; no allocation) ----------------
__device__ float g_bufA[49152000];   // conv ping
__device__ float g_bufB[24576000];   // conv pong / FFN hidden
__device__ float g_qer[48000000];    // qer buffer, head-major [h][b][q][r]
__device__ float g_qkv[18432000];    // fused QKV [8000][2304]
__device__ float g_wqkv[5308416];    // fused QKV weights [3][768][2304]
__device__ float g_bqkv[6912];       // fused QKV bias [3][2304]
__device__ float g_ert[32768];       // er transposed+scaled [64][512]
__device__ float g_zero[512];        // zero bias (device globals are zero-init)
__device__ float g_x[6144000];
__device__ float g_xn[6144000];
__device__ float g_o[6144000];

__device__ __forceinline__ float gelu_f(float x) {
    return 0.5f * x * (1.0f + erff(x * 0.7071067811865475f));
}

__device__ __forceinline__ uint32_t tf32_rn(float x) {
    uint32_t r; asm("cvt.rna.tf32.f32 %0, %1;" : "=r"(r) : "f"(x));
    return r;
}

// ---- packed f32x2 helpers (Blackwell FFMA2) ----
__device__ __forceinline__ unsigned long long pack_f32x2(float lo, float hi) {
    unsigned long long d;
    asm("mov.b64 %0, {%1, %2};" : "=l"(d) : "r"(__float_as_uint(lo)), "r"(__float_as_uint(hi)));
    return d;
}
__device__ __forceinline__ void unpack_f32x2(float& lo, float& hi, unsigned long long v) {
    uint32_t a, b;
    asm("mov.b64 {%0, %1}, %2;" : "=r"(a), "=r"(b) : "l"(v));
    lo = __uint_as_float(a); hi = __uint_as_float(b);
}
__device__ __forceinline__ void fma2(unsigned long long& d, unsigned long long a,
                                     unsigned long long b) {
    asm("fma.rn.f32x2 %0, %1, %2, %0;" : "+l"(d) : "l"(a), "l"(b));
}

// ---------------- tensor-core dense GEMM via mma.sync (tf32) ----------------
// C = act(A @ B + bias) (+ addsrc). A: [M][K] row-major. B: [K][N] row-major.
// CTA tile 128x128, K-step 32. 8 warps 4(m)x2(n), warp tile 32x64.
// Batched over blockIdx.z with strides bAo (A) and bCo (C).
#define ALD 136   // pad -> conflict-free fragment LDS

__global__ void __launch_bounds__(256) mma_gemm_kernel(
    const float* __restrict__ A, const float* __restrict__ Bm,
    const float* __restrict__ bias, const float* __restrict__ addsrc,
    float* __restrict__ C, int M, int N, int K,
    int lda, int ldb, int ldc, int act, long long bAo, long long bCo)
{
    __shared__ float As[32 * ALD];   // [k][m] 32 x 128 (+pad)
    __shared__ float Bs[32 * ALD];   // [k][n] 32 x 128 (+pad)

    A += (long long)blockIdx.z * bAo;
    C += (long long)blockIdx.z * bCo;

    int tid = threadIdx.x;
    int wid = tid >> 5, lane = tid & 31;
    int grp = lane >> 2, tig = lane & 3;
    int wm = wid & 3, wn = wid >> 2;
    int m0 = blockIdx.y * 128, n0 = blockIdx.x * 128;

    int am = tid >> 1;
    int akh = (tid & 1) * 16;
    int bkr = tid >> 4;
    int bn = (tid & 15) * 8;

    float acc[2][8][4];
#pragma unroll
    for (int i = 0; i < 2; i++)
#pragma unroll
        for (int j = 0; j < 8; j++)
#pragma unroll
            for (int r = 0; r < 4; r++) acc[i][j][r] = 0.f;

    float4 pa[4], pb[2][2];
    {
        const float* Ap = (m0 + am < M) ? A + (long long)(m0 + am) * lda + akh : (const float*)0;
#pragma unroll
        for (int i = 0; i < 4; i++)
            pa[i] = Ap ? *(const float4*)(Ap + i * 4) : make_float4(0.f, 0.f, 0.f, 0.f);
#pragma unroll
        for (int p = 0; p < 2; p++) {
            const float* Bp = Bm + (long long)(bkr + p * 16) * ldb + n0 + bn;
            bool okn = (n0 + bn < N);
            pb[p][0] = okn ? *(const float4*)(Bp)     : make_float4(0.f, 0.f, 0.f, 0.f);
            pb[p][1] = okn ? *(const float4*)(Bp + 4) : make_float4(0.f, 0.f, 0.f, 0.f);
        }
    }

    for (int k0 = 0;; k0 += 32) {
#pragma unroll
        for (int i = 0; i < 4; i++) {
            int kk = akh + i * 4;
            *(uint32_t*)&As[(kk + 0) * ALD + am] = tf32_rn(pa[i].x);
            *(uint32_t*)&As[(kk + 1) * ALD + am] = tf32_rn(pa[i].y);
            *(uint32_t*)&As[(kk + 2) * ALD + am] = tf32_rn(pa[i].z);
            *(uint32_t*)&As[(kk + 3) * ALD + am] = tf32_rn(pa[i].w);
        }
#pragma unroll
        for (int p = 0; p < 2; p++) {
            uint32_t* bsp = (uint32_t*)&Bs[(bkr + p * 16) * ALD + bn];
            bsp[0] = tf32_rn(pb[p][0].x); bsp[1] = tf32_rn(pb[p][0].y);
            bsp[2] = tf32_rn(pb[p][0].z); bsp[3] = tf32_rn(pb[p][0].w);
            bsp[4] = tf32_rn(pb[p][1].x); bsp[5] = tf32_rn(pb[p][1].y);
            bsp[6] = tf32_rn(pb[p][1].z); bsp[7] = tf32_rn(pb[p][1].w);
        }
        __syncthreads();

        bool last = (k0 + 32 >= K);
        if (!last) {
            int kn = k0 + 32;
            const float* Ap = (m0 + am < M) ? A + (long long)(m0 + am) * lda + kn + akh : (const float*)0;
#pragma unroll
            for (int i = 0; i < 4; i++)
                pa[i] = Ap ? *(const float4*)(Ap + i * 4) : make_float4(0.f, 0.f, 0.f, 0.f);
#pragma unroll
            for (int p = 0; p < 2; p++) {
                const float* Bp = Bm + (long long)(kn + bkr + p * 16) * ldb + n0 + bn;
                bool okn = (n0 + bn < N);
                pb[p][0] = okn ? *(const float4*)(Bp)     : make_float4(0.f, 0.f, 0.f, 0.f);
                pb[p][1] = okn ? *(const float4*)(Bp + 4) : make_float4(0.f, 0.f, 0.f, 0.f);
            }
        }

#pragma unroll
        for (int ks = 0; ks < 4; ks++) {
            int kb = ks * 8;
            uint32_t a[2][4], b[8][2];
            int mB = wm * 32;
#pragma unroll
            for (int mf = 0; mf < 2; mf++) {
                int mb = mB + mf * 16 + grp;
                a[mf][0] = *(const uint32_t*)&As[(kb + tig) * ALD + mb];
                a[mf][1] = *(const uint32_t*)&As[(kb + tig) * ALD + mb + 8];
                a[mf][2] = *(const uint32_t*)&As[(kb + tig + 4) * ALD + mb];
                a[mf][3] = *(const uint32_t*)&As[(kb + tig + 4) * ALD + mb + 8];
            }
            int nB = wn * 64;
#pragma unroll
            for (int nf = 0; nf < 8; nf++) {
                int nb = nB + nf * 8 + grp;
                b[nf][0] = *(const uint32_t*)&Bs[(kb + tig) * ALD + nb];
                b[nf][1] = *(const uint32_t*)&Bs[(kb + tig + 4) * ALD + nb];
            }
#pragma unroll
            for (int mf = 0; mf < 2; mf++)
#pragma unroll
                for (int nf = 0; nf < 8; nf++) {
                    asm volatile(
                        "mma.sync.aligned.m16n8k8.row.col.f32.tf32.tf32.f32 "
                        "{%0,%1,%2,%3}, {%4,%5,%6,%7}, {%8,%9}, {%0,%1,%2,%3};"
                        : "+f"(acc[mf][nf][0]), "+f"(acc[mf][nf][1]),
                          "+f"(acc[mf][nf][2]), "+f"(acc[mf][nf][3])
                        : "r"(a[mf][0]), "r"(a[mf][1]), "r"(a[mf][2]), "r"(a[mf][3]),
                          "r"(b[nf][0]), "r"(b[nf][1]));
                }
        }
        if (last) break;
        __syncthreads();
    }

#pragma unroll
    for (int mf = 0; mf < 2; mf++) {
#pragma unroll
        for (int r = 0; r < 2; r++) {
            int m = m0 + wm * 32 + mf * 16 + grp + r * 8;
            if (m >= M) continue;
            float* Cp = C + (long long)m * ldc;
            const float* addp = addsrc ? addsrc + (long long)m * ldc : (const float*)0;
#pragma unroll
            for (int nf = 0; nf < 8; nf++) {
                int n = n0 + wn * 64 + nf * 8 + tig * 2;
                if (n >= N) continue;
                float v0 = acc[mf][nf][r * 2 + 0] + bias[n];
                float v1 = acc[mf][nf][r * 2 + 1] + bias[n + 1];
                if (act) { v0 = gelu_f(v0); v1 = gelu_f(v1); }
                if (addp) { v0 += addp[n]; v1 += addp[n + 1]; }
                Cp[n] = v0; Cp[n + 1] = v1;
            }
        }
    }
}

// ---------------- one-time weight prep kernels ----------------
// Concat wq/wk/wv -> [3][768][2304] and biases -> [3][2304]
__global__ void concat_qkv(const float* __restrict__ wq, const float* __restrict__ wk,
                           const float* __restrict__ wv, const float* __restrict__ bq,
                           const float* __restrict__ bk, const float* __restrict__ bv,
                           float* __restrict__ wqkv, float* __restrict__ bqkv)
{
    long long idx = (long long)blockIdx.x * blockDim.x + threadIdx.x;
    const long long TOT = 3LL * 768 * 2304;
    if (idx < TOT) {
        int i = (int)(idx / (768 * 2304));
        int rem = (int)(idx % (768 * 2304));
        int k = rem / 2304, n = rem % 2304;
        int sel = n / 768, nn = n % 768;
        const float* src = sel == 0 ? wq : sel == 1 ? wk : wv;
        wqkv[idx] = src[(long long)i * 589824 + k * 768 + nn];
    }
    if (idx < 3 * 2304) {
        int i = (int)(idx / 2304);
        int n = (int)(idx % 2304);
        int sel = n / 768, nn = n % 768;
        const float* src = sel == 0 ? bq : sel == 1 ? bk : bv;
        bqkv[idx] = src[i * 768 + nn];
    }
}

// er [500][64] -> out [64][512]: out[d][r] = 0.125*er[r][d], zero-padded
__global__ void er_transpose(const float* __restrict__ er, float* __restrict__ out)
{
    int d = blockIdx.x;
    int r = threadIdx.x;
    out[d * 512 + r] = (r < 500) ? 0.125f * er[r * 64 + d] : 0.f;
}

// ---------------- conv 5x5, pad 2, + GELU + freq-maxpool(2,1), f32x2 packed ------
__global__ void __launch_bounds__(128) conv5x5_gelu_pool(
    const float* __restrict__ in, const float* __restrict__ w,
    const float* __restrict__ bias, float* __restrict__ out,
    int Ci, int Co, int H)
{
    const int W = 500;
    __shared__ float tile[28][72];
    __shared__ float ws[6400];
    int tx = threadIdx.x, ty = threadIdx.y;
    int tid = ty * 32 + tx;
    int hBlocks = H / 24;
    int x0 = blockIdx.x * 64;
    int y0 = (blockIdx.y % hBlocks) * 24;
    int co0 = (blockIdx.y / hBlocks) * 4;
    int b = blockIdx.z;
    int HP = H >> 1;

    int wtot = 4 * Ci * 25;
    const float* wbase = w + (long long)co0 * Ci * 25;
    for (int s = tid; s < wtot; s += 128) ws[s] = wbase[s];

    unsigned long long acc2[4][6];
#pragma unroll
    for (int i = 0; i < 4; i++)
#pragma unroll
        for (int j = 0; j < 6; j++) acc2[i][j] = 0ull;

    for (int ci = 0; ci < Ci; ci++) {
        const float* ip = in + ((long long)(b * Ci + ci)) * H * W;
        for (int idx = tid; idx < 28 * 68; idx += 128) {
            int r = idx / 68, c = idx % 68;
            int gy = y0 + r - 2, gx = x0 + c - 2;
            tile[r][c] = (gy >= 0 && gy < H && gx >= 0 && gx < W) ? ip[gy * W + gx] : 0.f;
        }
        __syncthreads();
#pragma unroll
        for (int dx = 0; dx < 5; dx++) {
            unsigned long long v2[10];
#pragma unroll
            for (int rr = 0; rr < 10; rr++)
                v2[rr] = pack_f32x2(tile[ty * 6 + rr][2 * tx + dx],
                                    tile[ty * 6 + rr][2 * tx + dx + 1]);
#pragma unroll
            for (int c4 = 0; c4 < 4; c4++) {
                const float* wp = ws + (c4 * Ci + ci) * 25 + dx;
#pragma unroll
                for (int dy = 0; dy < 5; dy++) {
                    float wv = wp[dy * 5];
                    unsigned long long w2 = pack_f32x2(wv, wv);
#pragma unroll
                    for (int ry = 0; ry < 6; ry++) fma2(acc2[c4][ry], v2[ry + dy], w2);
                }
            }
        }
        __syncthreads();
    }
    int xe = x0 + 2 * tx;
#pragma unroll
    for (int c4 = 0; c4 < 4; c4++) {
        float bv = bias[co0 + c4];
#pragma unroll
        for (int p = 0; p < 3; p++) {
            int y = y0 + ty * 6 + 2 * p;
            float a0, a1, b0, b1;
            unpack_f32x2(a0, a1, acc2[c4][2 * p]);
            unpack_f32x2(b0, b1, acc2[c4][2 * p + 1]);
            float r0 = fmaxf(gelu_f(a0 + bv), gelu_f(b0 + bv));
            float r1 = fmaxf(gelu_f(a1 + bv), gelu_f(b1 + bv));
            long long base = (((long long)b * Co + co0 + c4) * HP + (y >> 1)) * W;
            if (xe < W)     out[base + xe]     = r0;
            if (xe + 1 < W) out[base + xe + 1] = r1;
        }
    }
}

// ---------------- transpose [B,768,500] -> [B,500,768] ----------------
__global__ void transpose_kernel(const float* __restrict__ in, float* __restrict__ out)
{
    __shared__ float t[32][33];
    int b = blockIdx.z;
    int k0 = blockIdx.x * 32;
    int t0 = blockIdx.y * 32;
    int tx = threadIdx.x, ty = threadIdx.y;
    const float* ip = in + (long long)b * 768 * 500;
    float* op = out + (long long)b * 500 * 768;
#pragma unroll
    for (int r = 0; r < 32; r += 8) {
        int kk = k0 + ty + r, tt = t0 + tx;
        t[ty + r][tx] = (tt < 500) ? ip[(long long)kk * 500 + tt] : 0.f;
    }
    __syncthreads();
#pragma unroll
    for (int r = 0; r < 32; r += 8) {
        int tt = t0 + ty + r, kk = k0 + tx;
        if (tt < 500) op[(long long)tt * 768 + kk] = t[tx][ty + r];
    }
}

// ---------------- flash attention (fused QK^T + skew + softmax + PV) ------------
// Q/K/V read from fused qkv buffer with row stride ldin; qer is head-major.
#define FA_QLD 132
#define FA_KLD 68
#define FA_PLD 68
#define FA_SMEM_FLOATS (64*FA_QLD + 64*FA_KLD + 64*FA_KLD + 128*FA_PLD)

extern __shared__ float fa_smem[];

__global__ void __launch_bounds__(256) flash_attn_kernel(
    const float* __restrict__ Q, const float* __restrict__ K,
    const float* __restrict__ V, const float* __restrict__ qer,
    float* __restrict__ O, int ldin)
{
    float* Qs = fa_smem;
    float* Ks = Qs + 64 * FA_QLD;
    float* Vs = Ks + 64 * FA_KLD;
    float* Ps = Vs + 64 * FA_KLD;

    const float scale = 0.125f;
    int qt = blockIdx.x;
    int h = blockIdx.y, b = blockIdx.z;
    int q0 = qt * 128;
    const float* Qp = Q + (long long)b * 500 * ldin + h * 64;
    const float* Kp = K + (long long)b * 500 * ldin + h * 64;
    const float* Vp = V + (long long)b * 500 * ldin + h * 64;
    const float* qerp = qer + (long long)(h * 16 + b) * 250000;   // head-major

    int tid = threadIdx.x;
    int tx = tid & 15, ty = tid >> 4;

#pragma unroll
    for (int i = 0; i < 8; i++) {
        int r = i * 16 + (tid >> 4);
        int d4 = (tid & 15) * 4;
        float4 v = make_float4(0.f, 0.f, 0.f, 0.f);
        if (q0 + r < 500) v = *(const float4*)(Qp + (long long)(q0 + r) * ldin + d4);
        Qs[(d4 + 0) * FA_QLD + r] = v.x;
        Qs[(d4 + 1) * FA_QLD + r] = v.y;
        Qs[(d4 + 2) * FA_QLD + r] = v.z;
        Qs[(d4 + 3) * FA_QLD + r] = v.w;
    }

    float m[8], l[8], o[8][4];
#pragma unroll
    for (int i = 0; i < 8; i++) {
        m[i] = -1e30f; l[i] = 0.f;
#pragma unroll
        for (int j = 0; j < 4; j++) o[i][j] = 0.f;
    }
    __syncthreads();

    for (int kt0 = 0; kt0 < 500; kt0 += 64) {
#pragma unroll
        for (int i = 0; i < 4; i++) {
            int r = i * 16 + (tid >> 4);
            int d4 = (tid & 15) * 4;
            float4 kv = make_float4(0.f, 0.f, 0.f, 0.f);
            float4 vv = make_float4(0.f, 0.f, 0.f, 0.f);
            if (kt0 + r < 500) {
                kv = *(const float4*)(Kp + (long long)(kt0 + r) * ldin + d4);
                vv = *(const float4*)(Vp + (long long)(kt0 + r) * ldin + d4);
            }
            Ks[(d4 + 0) * FA_KLD + r] = kv.x;
            Ks[(d4 + 1) * FA_KLD + r] = kv.y;
            Ks[(d4 + 2) * FA_KLD + r] = kv.z;
            Ks[(d4 + 3) * FA_KLD + r] = kv.w;
            *(float4*)(Vs + r * FA_KLD + d4) = vv;
        }
        __syncthreads();

        float S[8][4];
#pragma unroll
        for (int i = 0; i < 8; i++)
#pragma unroll
            for (int j = 0; j < 4; j++) S[i][j] = 0.f;
#pragma unroll
        for (int d = 0; d < 64; d++) {
            float a[8];
            *(float4*)&a[0] = *(const float4*)(Qs + d * FA_QLD + ty * 8);
            *(float4*)&a[4] = *(const float4*)(Qs + d * FA_QLD + ty * 8 + 4);
            float4 bb = *(const float4*)(Ks + d * FA_KLD + tx * 4);
#pragma unroll
            for (int i = 0; i < 8; i++) {
                S[i][0] += a[i] * bb.x; S[i][1] += a[i] * bb.y;
                S[i][2] += a[i] * bb.z; S[i][3] += a[i] * bb.w;
            }
        }
#pragma unroll
        for (int i = 0; i < 8; i++) {
            int q = q0 + ty * 8 + i;
#pragma unroll
            for (int j = 0; j < 4; j++) {
                int k = kt0 + tx * 4 + j;
                if (q < 500 && k < 500) {
                    float srel;
                    if (k <= q)          srel = qerp[(long long)q * 500 + 499 - q + k];
                    else if (k == q + 1) srel = 0.f;
                    else                 srel = qerp[(long long)(q + 1) * 500 + k - q - 2];
                    S[i][j] = S[i][j] * scale + srel;
                } else {
                    S[i][j] = -1e30f;
                }
            }
        }
#pragma unroll
        for (int i = 0; i < 8; i++) {
            float rmax = fmaxf(fmaxf(S[i][0], S[i][1]), fmaxf(S[i][2], S[i][3]));
#pragma unroll
            for (int off = 1; off < 16; off <<= 1)
                rmax = fmaxf(rmax, __shfl_xor_sync(0xffffffffu, rmax, off, 32));
            float mnew = fmaxf(m[i], rmax);
            float corr = __expf(m[i] - mnew);
            float rsum = 0.f;
#pragma unroll
            for (int j = 0; j < 4; j++) {
                S[i][j] = __expf(S[i][j] - mnew);
                rsum += S[i][j];
            }
#pragma unroll
            for (int off = 1; off < 16; off <<= 1)
                rsum += __shfl_xor_sync(0xffffffffu, rsum, off, 32);
            l[i] = l[i] * corr + rsum;
            m[i] = mnew;
#pragma unroll
            for (int j = 0; j < 4; j++) o[i][j] *= corr;
            *(float4*)(Ps + (long long)(ty * 8 + i) * FA_PLD + tx * 4) =
                make_float4(S[i][0], S[i][1], S[i][2], S[i][3]);
        }
        __syncthreads();

#pragma unroll
        for (int kk = 0; kk < 64; kk++) {
            float4 vr = *(const float4*)(Vs + kk * FA_KLD + tx * 4);
#pragma unroll
            for (int i = 0; i < 8; i++) {
                float p = Ps[(ty * 8 + i) * FA_PLD + kk];
                o[i][0] += p * vr.x; o[i][1] += p * vr.y;
                o[i][2] += p * vr.z; o[i][3] += p * vr.w;
            }
        }
        __syncthreads();
    }

    float* Op = O + (long long)b * 500 * 768 + h * 64;
#pragma unroll
    for (int i = 0; i < 8; i++) {
        int q = q0 + ty * 8 + i;
        if (q < 500) {
            float inv = 1.0f / l[i];
            *(float4*)(Op + (long long)q * 768 + tx * 4) =
                make_float4(o[i][0] * inv, o[i][1] * inv, o[i][2] * inv, o[i][3] * inv);
        }
    }
}

// ---------------- layernorm (row = 768) ----------------
__global__ void __launch_bounds__(256) layernorm_kernel(
    const float* __restrict__ in, float* __restrict__ out,
    const float* __restrict__ g, const float* __restrict__ b)
{
    __shared__ float red[256];
    int row = blockIdx.x, tid = threadIdx.x;
    const float* xp = in + (long long)row * 768;
    float v0 = xp[tid], v1 = xp[tid + 256], v2 = xp[tid + 512];
    red[tid] = v0 + v1 + v2;
    __syncthreads();
    for (int o = 128; o > 0; o >>= 1) { if (tid < o) red[tid] += red[tid + o]; __syncthreads(); }
    float mean = red[0] * (1.0f / 768.0f);
    __syncthreads();
    float d0 = v0 - mean, d1 = v1 - mean, d2 = v2 - mean;
    red[tid] = d0 * d0 + d1 * d1 + d2 * d2;
    __syncthreads();
    for (int o = 128; o > 0; o >>= 1) { if (tid < o) red[tid] += red[tid + o]; __syncthreads(); }
    float rstd = rsqrtf(red[0] * (1.0f / 768.0f) + 1e-5f);
    float* op = out + (long long)row * 768;
    op[tid]       = d0 * rstd * g[tid]       + b[tid];
    op[tid + 256] = d1 * rstd * g[tid + 256] + b[tid + 256];
    op[tid + 512] = d2 * rstd * g[tid + 512] + b[tid + 512];
}

// ---------------- orchestration ----------------
static void tc(const float* A, const float* B, const float* bias, const float* add,
               float* C, int M, int N, int K, int lda, int ldb, int ldc, int act,
               int batch = 1, long long bAo = 0, long long bCo = 0)
{
    dim3 grid((N + 127) / 128, (M + 127) / 128, batch);
    mma_gemm_kernel<<<grid, 256>>>(A, B, bias, add, C, M, N, K, lda, ldb, ldc, act, bAo, bCo);
}

extern "C" void kernel_launch(void* const* d_in, const int* in_sizes, int n_in,
                              void* d_out, int out_size)
{
    (void)in_sizes; (void)n_in; (void)out_size;
    const float* spec    = (const float*)d_in[0];
    const float* cw1     = (const float*)d_in[1];
    const float* cb1     = (const float*)d_in[2];
    const float* cw2     = (const float*)d_in[3];
    const float* cb2     = (const float*)d_in[4];
    const float* cw3     = (const float*)d_in[5];
    const float* cb3     = (const float*)d_in[6];
    const float* cw4     = (const float*)d_in[7];
    const float* cb4     = (const float*)d_in[8];
    const float* proj_w  = (const float*)d_in[9];
    const float* proj_b  = (const float*)d_in[10];
    const float* ln1_g   = (const float*)d_in[11];
    const float* ln1_b   = (const float*)d_in[12];
    const float* wq      = (const float*)d_in[13];
    const float* bq      = (const float*)d_in[14];
    const float* wk      = (const float*)d_in[15];
    const float* bk      = (const float*)d_in[16];
    const float* wv      = (const float*)d_in[17];
    const float* bv      = (const float*)d_in[18];
    const float* wo      = (const float*)d_in[19];
    const float* bo      = (const float*)d_in[20];
    const float* er      = (const float*)d_in[21];
    const float* ln2_g   = (const float*)d_in[22];
    const float* ln2_b   = (const float*)d_in[23];
    const float* w1      = (const float*)d_in[24];
    const float* b1      = (const float*)d_in[25];
    const float* w2      = (const float*)d_in[26];
    const float* b2      = (const float*)d_in[27];
    const float* deprj_w = (const float*)d_in[28];
    const float* deprj_b = (const float*)d_in[29];
    float* outp = (float*)d_out;

    float *bufA, *bufB, *qer, *qkv, *wqkv, *bqkv, *ert, *zerob, *x, *xn, *o;
    cudaGetSymbolAddress((void**)&bufA,  g_bufA);
    cudaGetSymbolAddress((void**)&bufB,  g_bufB);
    cudaGetSymbolAddress((void**)&qer,   g_qer);
    cudaGetSymbolAddress((void**)&qkv,   g_qkv);
    cudaGetSymbolAddress((void**)&wqkv,  g_wqkv);
    cudaGetSymbolAddress((void**)&bqkv,  g_bqkv);
    cudaGetSymbolAddress((void**)&ert,   g_ert);
    cudaGetSymbolAddress((void**)&zerob, g_zero);
    cudaGetSymbolAddress((void**)&x,     g_x);
    cudaGetSymbolAddress((void**)&xn,    g_xn);
    cudaGetSymbolAddress((void**)&o,     g_o);
    float* hbuf = bufB;

    const int fa_smem_bytes = FA_SMEM_FLOATS * 4;
    cudaFuncSetAttribute(flash_attn_kernel,
                         cudaFuncAttributeMaxDynamicSharedMemorySize, fa_smem_bytes);

    // --- one-time QKV weight/bias concat ---
    concat_qkv<<<(3 * 768 * 2304 + 255) / 256, 256>>>(wq, wk, wv, bq, bk, bv, wqkv, bqkv);

    dim3 cblk(32, 4);
    // --- CNN with fused GELU+maxpool ---
    conv5x5_gelu_pool<<<dim3(8, 8 * 8, 16), cblk>>>(spec, cw1, cb1, bufB, 1, 32, 192);
    conv5x5_gelu_pool<<<dim3(8, 4 * 16, 16), cblk>>>(bufB, cw2, cb2, bufA, 32, 64, 96);
    conv5x5_gelu_pool<<<dim3(8, 2 * 16, 16), cblk>>>(bufA, cw3, cb3, bufB, 64, 64, 48);
    conv5x5_gelu_pool<<<dim3(8, 1 * 16, 16), cblk>>>(bufB, cw4, cb4, bufA, 64, 64, 24);
    transpose_kernel<<<dim3(24, 16, 16), dim3(32, 8)>>>(bufA, xn);

    // proj
    tc(xn, proj_w, proj_b, 0, x, 8000, 768, 768, 768, 768, 768, 0);

    for (int i = 0; i < L_; i++) {
        layernorm_kernel<<<8000, 256>>>(x, xn, ln1_g + i * 768, ln1_b + i * 768);
        // fused QKV: [8000][2304]
        tc(xn, wqkv + (long long)i * 768 * 2304, bqkv + i * 2304, 0, qkv,
           8000, 2304, 768, 768, 2304, 2304, 0);
        // er transposed+scaled -> [64][512]
        er_transpose<<<64, 512>>>(er + (long long)i * 500 * 64, ert);
        // qer (head-major) = Q_h @ er^T, batched over 12 heads on tensor cores
        tc(qkv, ert, zerob, 0, qer, 8000, 500, 64, 2304, 512, 500, 0,
           12, 64LL, 4000000LL);
        // fused attention
        flash_attn_kernel<<<dim3(4, 12, 16), 256, fa_smem_bytes>>>(
            qkv, qkv + 768, qkv + 1536, qer, o, 2304);
        // x = x + o @ wo + bo
        tc(o, wo + (long long)i * 768 * 768, bo + i * 768, x, x, 8000, 768, 768, 768, 768, 768, 0);
        layernorm_kernel<<<8000, 256>>>(x, xn, ln2_g + i * 768, ln2_b + i * 768);
        // h = gelu(xn @ w1 + b1)
        tc(xn, w1 + (long long)i * 768 * 3072, b1 + i * 3072, 0, hbuf, 8000, 3072, 768,
           768, 3072, 3072, 1);
        // x = x + h @ w2 + b2
        tc(hbuf, w2 + (long long)i * 3072 * 768, b2 + i * 768, x, x, 8000, 768, 3072,
           3072, 768, 768, 0);
    }
    // final deproj
    tc(x, deprj_w, deprj_b, 0, outp, 8000, 192, 768, 768, 192, 192, 0);
}

// round 9
// speedup vs baseline: 2.2489x; 1.0034x over previous
#include <cuda_runtime.h>
#include <math.h>
#include <stdint.h>

#define Bb_ 16
#define T_ 500
#define D_ 768
#define FFN_ 3072
#define NH_ 12
#define DH_ 64
#define L_ 3

// ---------------- scratch (device globals; no allocation) ----------------
__device__ float g_bufA[49152000];   // conv ping
__device__ float g_bufB[24576000];   // conv pong / FFN hidden
__device__ float g_qer[48000000];    // qer buffer, head-major [h][b][q][r]
__device__ float g_qkv[18432000];    // fused QKV [8000][2304]
__device__ float g_wqkv[5308416];    // fused QKV weights [3][768][2304]
__device__ float g_bqkv[6912];       // fused QKV bias [3][2304]
__device__ float g_ert[32768];       // er transposed+scaled [64][512]
__device__ float g_zero[512];        // zero bias (device globals are zero-init)
__device__ float g_x[6144000];
__device__ float g_xn[6144000];
__device__ float g_o[6144000];

__device__ __forceinline__ float gelu_f(float x) {
    return 0.5f * x * (1.0f + erff(x * 0.7071067811865475f));
}

__device__ __forceinline__ uint32_t tf32_rn(float x) {
    uint32_t r; asm("cvt.rna.tf32.f32 %0, %1;" : "=r"(r) : "f"(x));
    return r;
}

// ---- packed f32x2 helpers (Blackwell FFMA2) ----
__device__ __forceinline__ unsigned long long pack_f32x2(float lo, float hi) {
    unsigned long long d;
    asm("mov.b64 %0, {%1, %2};" : "=l"(d) : "r"(__float_as_uint(lo)), "r"(__float_as_uint(hi)));
    return d;
}
__device__ __forceinline__ void unpack_f32x2(float& lo, float& hi, unsigned long long v) {
    uint32_t a, b;
    asm("mov.b64 {%0, %1}, %2;" : "=r"(a), "=r"(b) : "l"(v));
    lo = __uint_as_float(a); hi = __uint_as_float(b);
}
__device__ __forceinline__ void fma2(unsigned long long& d, unsigned long long a,
                                     unsigned long long b) {
    asm("fma.rn.f32x2 %0, %1, %2, %0;" : "+l"(d) : "l"(a), "l"(b));
}

// ---------------- tensor-core dense GEMM via mma.sync (tf32) ----------------
// C = act(A @ B + bias) (+ addsrc). A: [M][K] row-major. B: [K][N] row-major.
// CTA tile 128x128, K-step 32, DOUBLE-BUFFERED smem (one sync per k-tile).
// 8 warps 4(m)x2(n), warp tile 32x64. Batched over blockIdx.z.
#define ALD 136                  // pad -> conflict-free fragment LDS
#define STAGE_FLOATS (2 * 32 * ALD)   // As + Bs per stage = 8704 floats
#define MM_SMEM_BYTES (2 * STAGE_FLOATS * 4)

extern __shared__ float mm_smem[];

__global__ void __launch_bounds__(256) mma_gemm_kernel(
    const float* __restrict__ A, const float* __restrict__ Bm,
    const float* __restrict__ bias, const float* __restrict__ addsrc,
    float* __restrict__ C, int M, int N, int K,
    int lda, int ldb, int ldc, int act, long long bAo, long long bCo)
{
    A += (long long)blockIdx.z * bAo;
    C += (long long)blockIdx.z * bCo;

    int tid = threadIdx.x;
    int wid = tid >> 5, lane = tid & 31;
    int grp = lane >> 2, tig = lane & 3;
    int wm = wid & 3, wn = wid >> 2;
    int m0 = blockIdx.y * 128, n0 = blockIdx.x * 128;

    int am = tid >> 1;
    int akh = (tid & 1) * 16;
    int bkr = tid >> 4;
    int bn = (tid & 15) * 8;

    float acc[2][8][4];
#pragma unroll
    for (int i = 0; i < 2; i++)
#pragma unroll
        for (int j = 0; j < 8; j++)
#pragma unroll
            for (int r = 0; r < 4; r++) acc[i][j][r] = 0.f;

    float4 pa[4], pb[2][2];
    bool okn = (n0 + bn < N);

    // prologue: load k-tile 0 into regs, store to stage 0
    {
        const float* Ap = (m0 + am < M) ? A + (long long)(m0 + am) * lda + akh : (const float*)0;
#pragma unroll
        for (int i = 0; i < 4; i++)
            pa[i] = Ap ? *(const float4*)(Ap + i * 4) : make_float4(0.f, 0.f, 0.f, 0.f);
#pragma unroll
        for (int p = 0; p < 2; p++) {
            const float* Bp = Bm + (long long)(bkr + p * 16) * ldb + n0 + bn;
            pb[p][0] = okn ? *(const float4*)(Bp)     : make_float4(0.f, 0.f, 0.f, 0.f);
            pb[p][1] = okn ? *(const float4*)(Bp + 4) : make_float4(0.f, 0.f, 0.f, 0.f);
        }
    }
    {
        float* Asb = mm_smem;
        float* Bsb = mm_smem + 32 * ALD;
#pragma unroll
        for (int i = 0; i < 4; i++) {
            int kk = akh + i * 4;
            *(uint32_t*)&Asb[(kk + 0) * ALD + am] = tf32_rn(pa[i].x);
            *(uint32_t*)&Asb[(kk + 1) * ALD + am] = tf32_rn(pa[i].y);
            *(uint32_t*)&Asb[(kk + 2) * ALD + am] = tf32_rn(pa[i].z);
            *(uint32_t*)&Asb[(kk + 3) * ALD + am] = tf32_rn(pa[i].w);
        }
#pragma unroll
        for (int p = 0; p < 2; p++) {
            uint32_t* bsp = (uint32_t*)&Bsb[(bkr + p * 16) * ALD + bn];
            bsp[0] = tf32_rn(pb[p][0].x); bsp[1] = tf32_rn(pb[p][0].y);
            bsp[2] = tf32_rn(pb[p][0].z); bsp[3] = tf32_rn(pb[p][0].w);
            bsp[4] = tf32_rn(pb[p][1].x); bsp[5] = tf32_rn(pb[p][1].y);
            bsp[6] = tf32_rn(pb[p][1].z); bsp[7] = tf32_rn(pb[p][1].w);
        }
    }
    __syncthreads();

    int st = 0;
    for (int k0 = 0;; k0 += 32) {
        bool last = (k0 + 32 >= K);
        if (!last) {
            int kn = k0 + 32;
            const float* Ap = (m0 + am < M) ? A + (long long)(m0 + am) * lda + kn + akh : (const float*)0;
#pragma unroll
            for (int i = 0; i < 4; i++)
                pa[i] = Ap ? *(const float4*)(Ap + i * 4) : make_float4(0.f, 0.f, 0.f, 0.f);
#pragma unroll
            for (int p = 0; p < 2; p++) {
                const float* Bp = Bm + (long long)(kn + bkr + p * 16) * ldb + n0 + bn;
                pb[p][0] = okn ? *(const float4*)(Bp)     : make_float4(0.f, 0.f, 0.f, 0.f);
                pb[p][1] = okn ? *(const float4*)(Bp + 4) : make_float4(0.f, 0.f, 0.f, 0.f);
            }
        }

        // compute from stage st
        {
            const float* Asb = mm_smem + st * STAGE_FLOATS;
            const float* Bsb = Asb + 32 * ALD;
#pragma unroll
            for (int ks = 0; ks < 4; ks++) {
                int kb = ks * 8;
                uint32_t a[2][4], b[8][2];
                int mB = wm * 32;
#pragma unroll
                for (int mf = 0; mf < 2; mf++) {
                    int mb = mB + mf * 16 + grp;
                    a[mf][0] = *(const uint32_t*)&Asb[(kb + tig) * ALD + mb];
                    a[mf][1] = *(const uint32_t*)&Asb[(kb + tig) * ALD + mb + 8];
                    a[mf][2] = *(const uint32_t*)&Asb[(kb + tig + 4) * ALD + mb];
                    a[mf][3] = *(const uint32_t*)&Asb[(kb + tig + 4) * ALD + mb + 8];
                }
                int nB = wn * 64;
#pragma unroll
                for (int nf = 0; nf < 8; nf++) {
                    int nb = nB + nf * 8 + grp;
                    b[nf][0] = *(const uint32_t*)&Bsb[(kb + tig) * ALD + nb];
                    b[nf][1] = *(const uint32_t*)&Bsb[(kb + tig + 4) * ALD + nb];
                }
#pragma unroll
                for (int mf = 0; mf < 2; mf++)
#pragma unroll
                    for (int nf = 0; nf < 8; nf++) {
                        asm volatile(
                            "mma.sync.aligned.m16n8k8.row.col.f32.tf32.tf32.f32 "
                            "{%0,%1,%2,%3}, {%4,%5,%6,%7}, {%8,%9}, {%0,%1,%2,%3};"
                            : "+f"(acc[mf][nf][0]), "+f"(acc[mf][nf][1]),
                              "+f"(acc[mf][nf][2]), "+f"(acc[mf][nf][3])
                            : "r"(a[mf][0]), "r"(a[mf][1]), "r"(a[mf][2]), "r"(a[mf][3]),
                              "r"(b[nf][0]), "r"(b[nf][1]));
                    }
            }
        }
        if (last) break;

        // store prefetched tile into other stage, single sync
        {
            float* Asb = mm_smem + (st ^ 1) * STAGE_FLOATS;
            float* Bsb = Asb + 32 * ALD;
#pragma unroll
            for (int i = 0; i < 4; i++) {
                int kk = akh + i * 4;
                *(uint32_t*)&Asb[(kk + 0) * ALD + am] = tf32_rn(pa[i].x);
                *(uint32_t*)&Asb[(kk + 1) * ALD + am] = tf32_rn(pa[i].y);
                *(uint32_t*)&Asb[(kk + 2) * ALD + am] = tf32_rn(pa[i].z);
                *(uint32_t*)&Asb[(kk + 3) * ALD + am] = tf32_rn(pa[i].w);
            }
#pragma unroll
            for (int p = 0; p < 2; p++) {
                uint32_t* bsp = (uint32_t*)&Bsb[(bkr + p * 16) * ALD + bn];
                bsp[0] = tf32_rn(pb[p][0].x); bsp[1] = tf32_rn(pb[p][0].y);
                bsp[2] = tf32_rn(pb[p][0].z); bsp[3] = tf32_rn(pb[p][0].w);
                bsp[4] = tf32_rn(pb[p][1].x); bsp[5] = tf32_rn(pb[p][1].y);
                bsp[6] = tf32_rn(pb[p][1].z); bsp[7] = tf32_rn(pb[p][1].w);
            }
        }
        __syncthreads();
        st ^= 1;
    }

    // epilogue
#pragma unroll
    for (int mf = 0; mf < 2; mf++) {
#pragma unroll
        for (int r = 0; r < 2; r++) {
            int m = m0 + wm * 32 + mf * 16 + grp + r * 8;
            if (m >= M) continue;
            float* Cp = C + (long long)m * ldc;
            const float* addp = addsrc ? addsrc + (long long)m * ldc : (const float*)0;
#pragma unroll
            for (int nf = 0; nf < 8; nf++) {
                int n = n0 + wn * 64 + nf * 8 + tig * 2;
                if (n >= N) continue;
                float v0 = acc[mf][nf][r * 2 + 0] + bias[n];
                float v1 = acc[mf][nf][r * 2 + 1] + bias[n + 1];
                if (act) { v0 = gelu_f(v0); v1 = gelu_f(v1); }
                if (addp) { v0 += addp[n]; v1 += addp[n + 1]; }
                Cp[n] = v0; Cp[n + 1] = v1;
            }
        }
    }
}

// ---------------- one-time weight prep kernels ----------------
__global__ void concat_qkv(const float* __restrict__ wq, const float* __restrict__ wk,
                           const float* __restrict__ wv, const float* __restrict__ bq,
                           const float* __restrict__ bk, const float* __restrict__ bv,
                           float* __restrict__ wqkv, float* __restrict__ bqkv)
{
    long long idx = (long long)blockIdx.x * blockDim.x + threadIdx.x;
    const long long TOT = 3LL * 768 * 2304;
    if (idx < TOT) {
        int i = (int)(idx / (768 * 2304));
        int rem = (int)(idx % (768 * 2304));
        int k = rem / 2304, n = rem % 2304;
        int sel = n / 768, nn = n % 768;
        const float* src = sel == 0 ? wq : sel == 1 ? wk : wv;
        wqkv[idx] = src[(long long)i * 589824 + k * 768 + nn];
    }
    if (idx < 3 * 2304) {
        int i = (int)(idx / 2304);
        int n = (int)(idx % 2304);
        int sel = n / 768, nn = n % 768;
        const float* src = sel == 0 ? bq : sel == 1 ? bk : bv;
        bqkv[idx] = src[i * 768 + nn];
    }
}

__global__ void er_transpose(const float* __restrict__ er, float* __restrict__ out)
{
    int d = blockIdx.x;
    int r = threadIdx.x;
    out[d * 512 + r] = (r < 500) ? 0.125f * er[r * 64 + d] : 0.f;
}

// ---------------- conv 5x5, pad 2, + GELU + freq-maxpool(2,1), f32x2 packed ------
__global__ void __launch_bounds__(128) conv5x5_gelu_pool(
    const float* __restrict__ in, const float* __restrict__ w,
    const float* __restrict__ bias, float* __restrict__ out,
    int Ci, int Co, int H)
{
    const int W = 500;
    __shared__ float tile[28][72];
    __shared__ float ws[6400];
    int tx = threadIdx.x, ty = threadIdx.y;
    int tid = ty * 32 + tx;
    int hBlocks = H / 24;
    int x0 = blockIdx.x * 64;
    int y0 = (blockIdx.y % hBlocks) * 24;
    int co0 = (blockIdx.y / hBlocks) * 4;
    int b = blockIdx.z;
    int HP = H >> 1;

    int wtot = 4 * Ci * 25;
    const float* wbase = w + (long long)co0 * Ci * 25;
    for (int s = tid; s < wtot; s += 128) ws[s] = wbase[s];

    unsigned long long acc2[4][6];
#pragma unroll
    for (int i = 0; i < 4; i++)
#pragma unroll
        for (int j = 0; j < 6; j++) acc2[i][j] = 0ull;

    for (int ci = 0; ci < Ci; ci++) {
        const float* ip = in + ((long long)(b * Ci + ci)) * H * W;
        for (int idx = tid; idx < 28 * 68; idx += 128) {
            int r = idx / 68, c = idx % 68;
            int gy = y0 + r - 2, gx = x0 + c - 2;
            tile[r][c] = (gy >= 0 && gy < H && gx >= 0 && gx < W) ? ip[gy * W + gx] : 0.f;
        }
        __syncthreads();
#pragma unroll
        for (int dx = 0; dx < 5; dx++) {
            unsigned long long v2[10];
#pragma unroll
            for (int rr = 0; rr < 10; rr++)
                v2[rr] = pack_f32x2(tile[ty * 6 + rr][2 * tx + dx],
                                    tile[ty * 6 + rr][2 * tx + dx + 1]);
#pragma unroll
            for (int c4 = 0; c4 < 4; c4++) {
                const float* wp = ws + (c4 * Ci + ci) * 25 + dx;
#pragma unroll
                for (int dy = 0; dy < 5; dy++) {
                    float wv = wp[dy * 5];
                    unsigned long long w2 = pack_f32x2(wv, wv);
#pragma unroll
                    for (int ry = 0; ry < 6; ry++) fma2(acc2[c4][ry], v2[ry + dy], w2);
                }
            }
        }
        __syncthreads();
    }
    int xe = x0 + 2 * tx;
#pragma unroll
    for (int c4 = 0; c4 < 4; c4++) {
        float bv = bias[co0 + c4];
#pragma unroll
        for (int p = 0; p < 3; p++) {
            int y = y0 + ty * 6 + 2 * p;
            float a0, a1, b0, b1;
            unpack_f32x2(a0, a1, acc2[c4][2 * p]);
            unpack_f32x2(b0, b1, acc2[c4][2 * p + 1]);
            float r0 = fmaxf(gelu_f(a0 + bv), gelu_f(b0 + bv));
            float r1 = fmaxf(gelu_f(a1 + bv), gelu_f(b1 + bv));
            long long base = (((long long)b * Co + co0 + c4) * HP + (y >> 1)) * W;
            if (xe < W)     out[base + xe]     = r0;
            if (xe + 1 < W) out[base + xe + 1] = r1;
        }
    }
}

// ---------------- transpose [B,768,500] -> [B,500,768] ----------------
__global__ void transpose_kernel(const float* __restrict__ in, float* __restrict__ out)
{
    __shared__ float t[32][33];
    int b = blockIdx.z;
    int k0 = blockIdx.x * 32;
    int t0 = blockIdx.y * 32;
    int tx = threadIdx.x, ty = threadIdx.y;
    const float* ip = in + (long long)b * 768 * 500;
    float* op = out + (long long)b * 500 * 768;
#pragma unroll
    for (int r = 0; r < 32; r += 8) {
        int kk = k0 + ty + r, tt = t0 + tx;
        t[ty + r][tx] = (tt < 500) ? ip[(long long)kk * 500 + tt] : 0.f;
    }
    __syncthreads();
#pragma unroll
    for (int r = 0; r < 32; r += 8) {
        int tt = t0 + ty + r, kk = k0 + tx;
        if (tt < 500) op[(long long)tt * 768 + kk] = t[tx][ty + r];
    }
}

// ---------------- flash attention (fused QK^T + skew + softmax + PV) ------------
#define FA_QLD 132
#define FA_KLD 68
#define FA_PLD 68
#define FA_SMEM_FLOATS (64*FA_QLD + 64*FA_KLD + 64*FA_KLD + 128*FA_PLD)

extern __shared__ float fa_smem[];

__global__ void __launch_bounds__(256) flash_attn_kernel(
    const float* __restrict__ Q, const float* __restrict__ K,
    const float* __restrict__ V, const float* __restrict__ qer,
    float* __restrict__ O, int ldin)
{
    float* Qs = fa_smem;
    float* Ks = Qs + 64 * FA_QLD;
    float* Vs = Ks + 64 * FA_KLD;
    float* Ps = Vs + 64 * FA_KLD;

    const float scale = 0.125f;
    int qt = blockIdx.x;
    int h = blockIdx.y, b = blockIdx.z;
    int q0 = qt * 128;
    const float* Qp = Q + (long long)b * 500 * ldin + h * 64;
    const float* Kp = K + (long long)b * 500 * ldin + h * 64;
    const float* Vp = V + (long long)b * 500 * ldin + h * 64;
    const float* qerp = qer + (long long)(h * 16 + b) * 250000;   // head-major

    int tid = threadIdx.x;
    int tx = tid & 15, ty = tid >> 4;

#pragma unroll
    for (int i = 0; i < 8; i++) {
        int r = i * 16 + (tid >> 4);
        int d4 = (tid & 15) * 4;
        float4 v = make_float4(0.f, 0.f, 0.f, 0.f);
        if (q0 + r < 500) v = *(const float4*)(Qp + (long long)(q0 + r) * ldin + d4);
        Qs[(d4 + 0) * FA_QLD + r] = v.x;
        Qs[(d4 + 1) * FA_QLD + r] = v.y;
        Qs[(d4 + 2) * FA_QLD + r] = v.z;
        Qs[(d4 + 3) * FA_QLD + r] = v.w;
    }

    float m[8], l[8], o[8][4];
#pragma unroll
    for (int i = 0; i < 8; i++) {
        m[i] = -1e30f; l[i] = 0.f;
#pragma unroll
        for (int j = 0; j < 4; j++) o[i][j] = 0.f;
    }
    __syncthreads();

    for (int kt0 = 0; kt0 < 500; kt0 += 64) {
#pragma unroll
        for (int i = 0; i < 4; i++) {
            int r = i * 16 + (tid >> 4);
            int d4 = (tid & 15) * 4;
            float4 kv = make_float4(0.f, 0.f, 0.f, 0.f);
            float4 vv = make_float4(0.f, 0.f, 0.f, 0.f);
            if (kt0 + r < 500) {
                kv = *(const float4*)(Kp + (long long)(kt0 + r) * ldin + d4);
                vv = *(const float4*)(Vp + (long long)(kt0 + r) * ldin + d4);
            }
            Ks[(d4 + 0) * FA_KLD + r] = kv.x;
            Ks[(d4 + 1) * FA_KLD + r] = kv.y;
            Ks[(d4 + 2) * FA_KLD + r] = kv.z;
            Ks[(d4 + 3) * FA_KLD + r] = kv.w;
            *(float4*)(Vs + r * FA_KLD + d4) = vv;
        }
        __syncthreads();

        float S[8][4];
#pragma unroll
        for (int i = 0; i < 8; i++)
#pragma unroll
            for (int j = 0; j < 4; j++) S[i][j] = 0.f;
#pragma unroll
        for (int d = 0; d < 64; d++) {
            float a[8];
            *(float4*)&a[0] = *(const float4*)(Qs + d * FA_QLD + ty * 8);
            *(float4*)&a[4] = *(const float4*)(Qs + d * FA_QLD + ty * 8 + 4);
            float4 bb = *(const float4*)(Ks + d * FA_KLD + tx * 4);
#pragma unroll
            for (int i = 0; i < 8; i++) {
                S[i][0] += a[i] * bb.x; S[i][1] += a[i] * bb.y;
                S[i][2] += a[i] * bb.z; S[i][3] += a[i] * bb.w;
            }
        }
#pragma unroll
        for (int i = 0; i < 8; i++) {
            int q = q0 + ty * 8 + i;
#pragma unroll
            for (int j = 0; j < 4; j++) {
                int k = kt0 + tx * 4 + j;
                if (q < 500 && k < 500) {
                    float srel;
                    if (k <= q)          srel = qerp[(long long)q * 500 + 499 - q + k];
                    else if (k == q + 1) srel = 0.f;
                    else                 srel = qerp[(long long)(q + 1) * 500 + k - q - 2];
                    S[i][j] = S[i][j] * scale + srel;
                } else {
                    S[i][j] = -1e30f;
                }
            }
        }
#pragma unroll
        for (int i = 0; i < 8; i++) {
            float rmax = fmaxf(fmaxf(S[i][0], S[i][1]), fmaxf(S[i][2], S[i][3]));
#pragma unroll
            for (int off = 1; off < 16; off <<= 1)
                rmax = fmaxf(rmax, __shfl_xor_sync(0xffffffffu, rmax, off, 32));
            float mnew = fmaxf(m[i], rmax);
            float corr = __expf(m[i] - mnew);
            float rsum = 0.f;
#pragma unroll
            for (int j = 0; j < 4; j++) {
                S[i][j] = __expf(S[i][j] - mnew);
                rsum += S[i][j];
            }
#pragma unroll
            for (int off = 1; off < 16; off <<= 1)
                rsum += __shfl_xor_sync(0xffffffffu, rsum, off, 32);
            l[i] = l[i] * corr + rsum;
            m[i] = mnew;
#pragma unroll
            for (int j = 0; j < 4; j++) o[i][j] *= corr;
            *(float4*)(Ps + (long long)(ty * 8 + i) * FA_PLD + tx * 4) =
                make_float4(S[i][0], S[i][1], S[i][2], S[i][3]);
        }
        __syncthreads();

        // O += P @ V, k blocked by 4 with vectorized P loads
#pragma unroll
        for (int kk4 = 0; kk4 < 64; kk4 += 4) {
            float4 vr0 = *(const float4*)(Vs + (kk4 + 0) * FA_KLD + tx * 4);
            float4 vr1 = *(const float4*)(Vs + (kk4 + 1) * FA_KLD + tx * 4);
            float4 vr2 = *(const float4*)(Vs + (kk4 + 2) * FA_KLD + tx * 4);
            float4 vr3 = *(const float4*)(Vs + (kk4 + 3) * FA_KLD + tx * 4);
#pragma unroll
            for (int i = 0; i < 8; i++) {
                float4 p4 = *(const float4*)(Ps + (long long)(ty * 8 + i) * FA_PLD + kk4);
                o[i][0] += p4.x * vr0.x + p4.y * vr1.x + p4.z * vr2.x + p4.w * vr3.x;
                o[i][1] += p4.x * vr0.y + p4.y * vr1.y + p4.z * vr2.y + p4.w * vr3.y;
                o[i][2] += p4.x * vr0.z + p4.y * vr1.z + p4.z * vr2.z + p4.w * vr3.z;
                o[i][3] += p4.x * vr0.w + p4.y * vr1.w + p4.z * vr2.w + p4.w * vr3.w;
            }
        }
        __syncthreads();
    }

    float* Op = O + (long long)b * 500 * 768 + h * 64;
#pragma unroll
    for (int i = 0; i < 8; i++) {
        int q = q0 + ty * 8 + i;
        if (q < 500) {
            float inv = 1.0f / l[i];
            *(float4*)(Op + (long long)q * 768 + tx * 4) =
                make_float4(o[i][0] * inv, o[i][1] * inv, o[i][2] * inv, o[i][3] * inv);
        }
    }
}

// ---------------- layernorm (row = 768) ----------------
__global__ void __launch_bounds__(256) layernorm_kernel(
    const float* __restrict__ in, float* __restrict__ out,
    const float* __restrict__ g, const float* __restrict__ b)
{
    __shared__ float red[256];
    int row = blockIdx.x, tid = threadIdx.x;
    const float* xp = in + (long long)row * 768;
    float v0 = xp[tid], v1 = xp[tid + 256], v2 = xp[tid + 512];
    red[tid] = v0 + v1 + v2;
    __syncthreads();
    for (int o = 128; o > 0; o >>= 1) { if (tid < o) red[tid] += red[tid + o]; __syncthreads(); }
    float mean = red[0] * (1.0f / 768.0f);
    __syncthreads();
    float d0 = v0 - mean, d1 = v1 - mean, d2 = v2 - mean;
    red[tid] = d0 * d0 + d1 * d1 + d2 * d2;
    __syncthreads();
    for (int o = 128; o > 0; o >>= 1) { if (tid < o) red[tid] += red[tid + o]; __syncthreads(); }
    float rstd = rsqrtf(red[0] * (1.0f / 768.0f) + 1e-5f);
    float* op = out + (long long)row * 768;
    op[tid]       = d0 * rstd * g[tid]       + b[tid];
    op[tid + 256] = d1 * rstd * g[tid + 256] + b[tid + 256];
    op[tid + 512] = d2 * rstd * g[tid + 512] + b[tid + 512];
}

// ---------------- orchestration ----------------
static void tc(const float* A, const float* B, const float* bias, const float* add,
               float* C, int M, int N, int K, int lda, int ldb, int ldc, int act,
               int batch = 1, long long bAo = 0, long long bCo = 0)
{
    dim3 grid((N + 127) / 128, (M + 127) / 128, batch);
    mma_gemm_kernel<<<grid, 256, MM_SMEM_BYTES>>>(A, B, bias, add, C, M, N, K,
                                                  lda, ldb, ldc, act, bAo, bCo);
}

extern "C" void kernel_launch(void* const* d_in, const int* in_sizes, int n_in,
                              void* d_out, int out_size)
{
    (void)in_sizes; (void)n_in; (void)out_size;
    const float* spec    = (const float*)d_in[0];
    const float* cw1     = (const float*)d_in[1];
    const float* cb1     = (const float*)d_in[2];
    const float* cw2     = (const float*)d_in[3];
    const float* cb2     = (const float*)d_in[4];
    const float* cw3     = (const float*)d_in[5];
    const float* cb3     = (const float*)d_in[6];
    const float* cw4     = (const float*)d_in[7];
    const float* cb4     = (const float*)d_in[8];
    const float* proj_w  = (const float*)d_in[9];
    const float* proj_b  = (const float*)d_in[10];
    const float* ln1_g   = (const float*)d_in[11];
    const float* ln1_b   = (const float*)d_in[12];
    const float* wq      = (const float*)d_in[13];
    const float* bq      = (const float*)d_in[14];
    const float* wk      = (const float*)d_in[15];
    const float* bk      = (const float*)d_in[16];
    const float* wv      = (const float*)d_in[17];
    const float* bv      = (const float*)d_in[18];
    const float* wo      = (const float*)d_in[19];
    const float* bo      = (const float*)d_in[20];
    const float* er      = (const float*)d_in[21];
    const float* ln2_g   = (const float*)d_in[22];
    const float* ln2_b   = (const float*)d_in[23];
    const float* w1      = (const float*)d_in[24];
    const float* b1      = (const float*)d_in[25];
    const float* w2      = (const float*)d_in[26];
    const float* b2      = (const float*)d_in[27];
    const float* deprj_w = (const float*)d_in[28];
    const float* deprj_b = (const float*)d_in[29];
    float* outp = (float*)d_out;

    float *bufA, *bufB, *qer, *qkv, *wqkv, *bqkv, *ert, *zerob, *x, *xn, *o;
    cudaGetSymbolAddress((void**)&bufA,  g_bufA);
    cudaGetSymbolAddress((void**)&bufB,  g_bufB);
    cudaGetSymbolAddress((void**)&qer,   g_qer);
    cudaGetSymbolAddress((void**)&qkv,   g_qkv);
    cudaGetSymbolAddress((void**)&wqkv,  g_wqkv);
    cudaGetSymbolAddress((void**)&bqkv,  g_bqkv);
    cudaGetSymbolAddress((void**)&ert,   g_ert);
    cudaGetSymbolAddress((void**)&zerob, g_zero);
    cudaGetSymbolAddress((void**)&x,     g_x);
    cudaGetSymbolAddress((void**)&xn,    g_xn);
    cudaGetSymbolAddress((void**)&o,     g_o);
    float* hbuf = bufB;

    const int fa_smem_bytes = FA_SMEM_FLOATS * 4;
    cudaFuncSetAttribute(flash_attn_kernel,
                         cudaFuncAttributeMaxDynamicSharedMemorySize, fa_smem_bytes);
    cudaFuncSetAttribute(mma_gemm_kernel,
                         cudaFuncAttributeMaxDynamicSharedMemorySize, MM_SMEM_BYTES);

    // --- one-time QKV weight/bias concat ---
    concat_qkv<<<(3 * 768 * 2304 + 255) / 256, 256>>>(wq, wk, wv, bq, bk, bv, wqkv, bqkv);

    dim3 cblk(32, 4);
    // --- CNN with fused GELU+maxpool ---
    conv5x5_gelu_pool<<<dim3(8, 8 * 8, 16), cblk>>>(spec, cw1, cb1, bufB, 1, 32, 192);
    conv5x5_gelu_pool<<<dim3(8, 4 * 16, 16), cblk>>>(bufB, cw2, cb2, bufA, 32, 64, 96);
    conv5x5_gelu_pool<<<dim3(8, 2 * 16, 16), cblk>>>(bufA, cw3, cb3, bufB, 64, 64, 48);
    conv5x5_gelu_pool<<<dim3(8, 1 * 16, 16), cblk>>>(bufB, cw4, cb4, bufA, 64, 64, 24);
    transpose_kernel<<<dim3(24, 16, 16), dim3(32, 8)>>>(bufA, xn);

    // proj
    tc(xn, proj_w, proj_b, 0, x, 8000, 768, 768, 768, 768, 768, 0);

    for (int i = 0; i < L_; i++) {
        layernorm_kernel<<<8000, 256>>>(x, xn, ln1_g + i * 768, ln1_b + i * 768);
        // fused QKV: [8000][2304]
        tc(xn, wqkv + (long long)i * 768 * 2304, bqkv + i * 2304, 0, qkv,
           8000, 2304, 768, 768, 2304, 2304, 0);
        // er transposed+scaled -> [64][512]
        er_transpose<<<64, 512>>>(er + (long long)i * 500 * 64, ert);
        // qer (head-major) = Q_h @ er^T, batched over 12 heads
        tc(qkv, ert, zerob, 0, qer, 8000, 500, 64, 2304, 512, 500, 0,
           12, 64LL, 4000000LL);
        // fused attention
        flash_attn_kernel<<<dim3(4, 12, 16), 256, fa_smem_bytes>>>(
            qkv, qkv + 768, qkv + 1536, qer, o, 2304);
        // x = x + o @ wo + bo
        tc(o, wo + (long long)i * 768 * 768, bo + i * 768, x, x, 8000, 768, 768, 768, 768, 768, 0);
        layernorm_kernel<<<8000, 256>>>(x, xn, ln2_g + i * 768, ln2_b + i * 768);
        // h = gelu(xn @ w1 + b1)
        tc(xn, w1 + (long long)i * 768 * 3072, b1 + i * 3072, 0, hbuf, 8000, 3072, 768,
           768, 3072, 3072, 1);
        // x = x + h @ w2 + b2
        tc(hbuf, w2 + (long long)i * 3072 * 768, b2 + i * 768, x, x, 8000, 768, 3072,
           3072, 768, 768, 0);
    }
    // final deproj
    tc(x, deprj_w, deprj_b, 0, outp, 8000, 192, 768, 768, 192, 192, 0);
}

// round 10
// speedup vs baseline: 2.4142x; 1.0735x over previous
#include <cuda_runtime.h>
#include <math.h>
#include <stdint.h>

#define Bb_ 16
#define T_ 500
#define D_ 768
#define FFN_ 3072
#define NH_ 12
#define DH_ 64
#define L_ 3

// ---------------- scratch (device globals; no allocation) ----------------
__device__ float g_bufA[49152000];   // conv ping
__device__ float g_bufB[24576000];   // conv pong / FFN hidden
__device__ float g_qer[48000000];    // qer buffer, head-major [h][b][q][r]
__device__ float g_qkv[18432000];    // fused QKV [8000][2304]
__device__ float g_wqkv[5308416];    // fused QKV weights [3][768][2304]
__device__ float g_bqkv[6912];       // fused QKV bias [3][2304]
__device__ float g_ert[32768];       // er transposed+scaled [64][512]
__device__ float g_zero[512];        // zero bias (device globals are zero-init)
__device__ float g_x[6144000];
__device__ float g_xn[6144000];
__device__ float g_o[6144000];

__device__ __forceinline__ float gelu_f(float x) {
    return 0.5f * x * (1.0f + erff(x * 0.7071067811865475f));
}

__device__ __forceinline__ uint32_t tf32_rn(float x) {
    uint32_t r; asm("cvt.rna.tf32.f32 %0, %1;" : "=r"(r) : "f"(x));
    return r;
}

__device__ __forceinline__ uint32_t smem_u32(const void* p) {
    uint32_t a;
    asm("{ .reg .u64 t; cvta.to.shared.u64 t, %1; cvt.u32.u64 %0, t; }" : "=r"(a) : "l"(p));
    return a;
}

// ---- packed f32x2 helpers (Blackwell FFMA2) ----
__device__ __forceinline__ unsigned long long pack_f32x2(float lo, float hi) {
    unsigned long long d;
    asm("mov.b64 %0, {%1, %2};" : "=l"(d) : "r"(__float_as_uint(lo)), "r"(__float_as_uint(hi)));
    return d;
}
__device__ __forceinline__ void unpack_f32x2(float& lo, float& hi, unsigned long long v) {
    uint32_t a, b;
    asm("mov.b64 {%0, %1}, %2;" : "=r"(a), "=r"(b) : "l"(v));
    lo = __uint_as_float(a); hi = __uint_as_float(b);
}
__device__ __forceinline__ void fma2(unsigned long long& d, unsigned long long a,
                                     unsigned long long b) {
    asm("fma.rn.f32x2 %0, %1, %2, %0;" : "+l"(d) : "l"(a), "l"(b));
}

// ---------------- tensor-core dense GEMM via mma.sync (tf32) ----------------
// CTA tile 128x128, K-step 32, double-buffered smem. 8 warps 4(m)x2(n).
#define ALD 136
#define STAGE_FLOATS (2 * 32 * ALD)
#define MM_SMEM_BYTES (2 * STAGE_FLOATS * 4)

extern __shared__ float mm_smem[];

__global__ void __launch_bounds__(256) mma_gemm_kernel(
    const float* __restrict__ A, const float* __restrict__ Bm,
    const float* __restrict__ bias, const float* __restrict__ addsrc,
    float* __restrict__ C, int M, int N, int K,
    int lda, int ldb, int ldc, int act, long long bAo, long long bCo)
{
    A += (long long)blockIdx.z * bAo;
    C += (long long)blockIdx.z * bCo;

    int tid = threadIdx.x;
    int wid = tid >> 5, lane = tid & 31;
    int grp = lane >> 2, tig = lane & 3;
    int wm = wid & 3, wn = wid >> 2;
    int m0 = blockIdx.y * 128, n0 = blockIdx.x * 128;

    int am = tid >> 1;
    int akh = (tid & 1) * 16;
    int bkr = tid >> 4;
    int bn = (tid & 15) * 8;

    float acc[2][8][4];
#pragma unroll
    for (int i = 0; i < 2; i++)
#pragma unroll
        for (int j = 0; j < 8; j++)
#pragma unroll
            for (int r = 0; r < 4; r++) acc[i][j][r] = 0.f;

    float4 pa[4], pb[2][2];
    bool okn = (n0 + bn < N);

    {
        const float* Ap = (m0 + am < M) ? A + (long long)(m0 + am) * lda + akh : (const float*)0;
#pragma unroll
        for (int i = 0; i < 4; i++)
            pa[i] = Ap ? *(const float4*)(Ap + i * 4) : make_float4(0.f, 0.f, 0.f, 0.f);
#pragma unroll
        for (int p = 0; p < 2; p++) {
            const float* Bp = Bm + (long long)(bkr + p * 16) * ldb + n0 + bn;
            pb[p][0] = okn ? *(const float4*)(Bp)     : make_float4(0.f, 0.f, 0.f, 0.f);
            pb[p][1] = okn ? *(const float4*)(Bp + 4) : make_float4(0.f, 0.f, 0.f, 0.f);
        }
    }
    {
        float* Asb = mm_smem;
        float* Bsb = mm_smem + 32 * ALD;
#pragma unroll
        for (int i = 0; i < 4; i++) {
            int kk = akh + i * 4;
            *(uint32_t*)&Asb[(kk + 0) * ALD + am] = tf32_rn(pa[i].x);
            *(uint32_t*)&Asb[(kk + 1) * ALD + am] = tf32_rn(pa[i].y);
            *(uint32_t*)&Asb[(kk + 2) * ALD + am] = tf32_rn(pa[i].z);
            *(uint32_t*)&Asb[(kk + 3) * ALD + am] = tf32_rn(pa[i].w);
        }
#pragma unroll
        for (int p = 0; p < 2; p++) {
            uint32_t* bsp = (uint32_t*)&Bsb[(bkr + p * 16) * ALD + bn];
            bsp[0] = tf32_rn(pb[p][0].x); bsp[1] = tf32_rn(pb[p][0].y);
            bsp[2] = tf32_rn(pb[p][0].z); bsp[3] = tf32_rn(pb[p][0].w);
            bsp[4] = tf32_rn(pb[p][1].x); bsp[5] = tf32_rn(pb[p][1].y);
            bsp[6] = tf32_rn(pb[p][1].z); bsp[7] = tf32_rn(pb[p][1].w);
        }
    }
    __syncthreads();

    int st = 0;
    for (int k0 = 0;; k0 += 32) {
        bool last = (k0 + 32 >= K);
        if (!last) {
            int kn = k0 + 32;
            const float* Ap = (m0 + am < M) ? A + (long long)(m0 + am) * lda + kn + akh : (const float*)0;
#pragma unroll
            for (int i = 0; i < 4; i++)
                pa[i] = Ap ? *(const float4*)(Ap + i * 4) : make_float4(0.f, 0.f, 0.f, 0.f);
#pragma unroll
            for (int p = 0; p < 2; p++) {
                const float* Bp = Bm + (long long)(kn + bkr + p * 16) * ldb + n0 + bn;
                pb[p][0] = okn ? *(const float4*)(Bp)     : make_float4(0.f, 0.f, 0.f, 0.f);
                pb[p][1] = okn ? *(const float4*)(Bp + 4) : make_float4(0.f, 0.f, 0.f, 0.f);
            }
        }

        {
            const float* Asb = mm_smem + st * STAGE_FLOATS;
            const float* Bsb = Asb + 32 * ALD;
#pragma unroll
            for (int ks = 0; ks < 4; ks++) {
                int kb = ks * 8;
                uint32_t a[2][4], b[8][2];
                int mB = wm * 32;
#pragma unroll
                for (int mf = 0; mf < 2; mf++) {
                    int mb = mB + mf * 16 + grp;
                    a[mf][0] = *(const uint32_t*)&Asb[(kb + tig) * ALD + mb];
                    a[mf][1] = *(const uint32_t*)&Asb[(kb + tig) * ALD + mb + 8];
                    a[mf][2] = *(const uint32_t*)&Asb[(kb + tig + 4) * ALD + mb];
                    a[mf][3] = *(const uint32_t*)&Asb[(kb + tig + 4) * ALD + mb + 8];
                }
                int nB = wn * 64;
#pragma unroll
                for (int nf = 0; nf < 8; nf++) {
                    int nb = nB + nf * 8 + grp;
                    b[nf][0] = *(const uint32_t*)&Bsb[(kb + tig) * ALD + nb];
                    b[nf][1] = *(const uint32_t*)&Bsb[(kb + tig + 4) * ALD + nb];
                }
#pragma unroll
                for (int mf = 0; mf < 2; mf++)
#pragma unroll
                    for (int nf = 0; nf < 8; nf++) {
                        asm volatile(
                            "mma.sync.aligned.m16n8k8.row.col.f32.tf32.tf32.f32 "
                            "{%0,%1,%2,%3}, {%4,%5,%6,%7}, {%8,%9}, {%0,%1,%2,%3};"
                            : "+f"(acc[mf][nf][0]), "+f"(acc[mf][nf][1]),
                              "+f"(acc[mf][nf][2]), "+f"(acc[mf][nf][3])
                            : "r"(a[mf][0]), "r"(a[mf][1]), "r"(a[mf][2]), "r"(a[mf][3]),
                              "r"(b[nf][0]), "r"(b[nf][1]));
                    }
            }
        }
        if (last) break;

        {
            float* Asb = mm_smem + (st ^ 1) * STAGE_FLOATS;
            float* Bsb = Asb + 32 * ALD;
#pragma unroll
            for (int i = 0; i < 4; i++) {
                int kk = akh + i * 4;
                *(uint32_t*)&Asb[(kk + 0) * ALD + am] = tf32_rn(pa[i].x);
                *(uint32_t*)&Asb[(kk + 1) * ALD + am] = tf32_rn(pa[i].y);
                *(uint32_t*)&Asb[(kk + 2) * ALD + am] = tf32_rn(pa[i].z);
                *(uint32_t*)&Asb[(kk + 3) * ALD + am] = tf32_rn(pa[i].w);
            }
#pragma unroll
            for (int p = 0; p < 2; p++) {
                uint32_t* bsp = (uint32_t*)&Bsb[(bkr + p * 16) * ALD + bn];
                bsp[0] = tf32_rn(pb[p][0].x); bsp[1] = tf32_rn(pb[p][0].y);
                bsp[2] = tf32_rn(pb[p][0].z); bsp[3] = tf32_rn(pb[p][0].w);
                bsp[4] = tf32_rn(pb[p][1].x); bsp[5] = tf32_rn(pb[p][1].y);
                bsp[6] = tf32_rn(pb[p][1].z); bsp[7] = tf32_rn(pb[p][1].w);
            }
        }
        __syncthreads();
        st ^= 1;
    }

#pragma unroll
    for (int mf = 0; mf < 2; mf++) {
#pragma unroll
        for (int r = 0; r < 2; r++) {
            int m = m0 + wm * 32 + mf * 16 + grp + r * 8;
            if (m >= M) continue;
            float* Cp = C + (long long)m * ldc;
            const float* addp = addsrc ? addsrc + (long long)m * ldc : (const float*)0;
#pragma unroll
            for (int nf = 0; nf < 8; nf++) {
                int n = n0 + wn * 64 + nf * 8 + tig * 2;
                if (n >= N) continue;
                float v0 = acc[mf][nf][r * 2 + 0] + bias[n];
                float v1 = acc[mf][nf][r * 2 + 1] + bias[n + 1];
                if (act) { v0 = gelu_f(v0); v1 = gelu_f(v1); }
                if (addp) { v0 += addp[n]; v1 += addp[n + 1]; }
                Cp[n] = v0; Cp[n + 1] = v1;
            }
        }
    }
}

// ---------------- one-time weight prep kernels ----------------
__global__ void concat_qkv(const float* __restrict__ wq, const float* __restrict__ wk,
                           const float* __restrict__ wv, const float* __restrict__ bq,
                           const float* __restrict__ bk, const float* __restrict__ bv,
                           float* __restrict__ wqkv, float* __restrict__ bqkv)
{
    long long idx = (long long)blockIdx.x * blockDim.x + threadIdx.x;
    const long long TOT = 3LL * 768 * 2304;
    if (idx < TOT) {
        int i = (int)(idx / (768 * 2304));
        int rem = (int)(idx % (768 * 2304));
        int k = rem / 2304, n = rem % 2304;
        int sel = n / 768, nn = n % 768;
        const float* src = sel == 0 ? wq : sel == 1 ? wk : wv;
        wqkv[idx] = src[(long long)i * 589824 + k * 768 + nn];
    }
    if (idx < 3 * 2304) {
        int i = (int)(idx / 2304);
        int n = (int)(idx % 2304);
        int sel = n / 768, nn = n % 768;
        const float* src = sel == 0 ? bq : sel == 1 ? bk : bv;
        bqkv[idx] = src[i * 768 + nn];
    }
}

__global__ void er_transpose(const float* __restrict__ er, float* __restrict__ out)
{
    int d = blockIdx.x;
    int r = threadIdx.x;
    out[d * 512 + r] = (r < 500) ? 0.125f * er[r * 64 + d] : 0.f;
}

// ---------------- conv 5x5 + GELU + freq-maxpool, f32x2, cp.async pipelined ------
// block 32x4; tile 64(W pairs) x 24(H in-rows) x 4 out-ch. Input tile double-buffered
// via cp.async: body as 16B vectors (cols 4..67), halo cols 2,3,68,69 as 4B.
#define CTLD 76   // tile row stride (floats): body 16B-aligned, 304B = 16*19

__global__ void __launch_bounds__(128) conv5x5_gelu_pool(
    const float* __restrict__ in, const float* __restrict__ w,
    const float* __restrict__ bias, float* __restrict__ out,
    int Ci, int Co, int H)
{
    const int W = 500;
    __shared__ float tile[2][28][CTLD];
    __shared__ float ws[6400];
    int tx = threadIdx.x, ty = threadIdx.y;
    int tid = ty * 32 + tx;
    int hBlocks = H / 24;
    int x0 = blockIdx.x * 64;
    int y0 = (blockIdx.y % hBlocks) * 24;
    int co0 = (blockIdx.y / hBlocks) * 4;
    int b = blockIdx.z;
    int HP = H >> 1;

    int wtot = 4 * Ci * 25;
    const float* wbase = w + (long long)co0 * Ci * 25;
    for (int s = tid; s < wtot; s += 128) ws[s] = wbase[s];

    uint32_t tb0 = smem_u32(&tile[0][0][0]);
    uint32_t tb1 = smem_u32(&tile[1][0][0]);

    // issue cp.async for channel ci into buffer buf
    auto issue = [&](int ci, int buf) {
        const float* ip = in + ((long long)(b * Ci + ci)) * H * W;
        uint32_t tb = buf ? tb1 : tb0;
        // body: 28 rows x 16 vec4 (cols 4..67 <-> gx x0..x0+63)
        for (int idx = tid; idx < 448; idx += 128) {
            int r = idx >> 4, cv = idx & 15;
            int gy = y0 + r - 2;
            int gx = x0 + cv * 4;
            int sb = 0;
            if (gy >= 0 && gy < H) {
                int rem = W - gx;
                sb = rem >= 4 ? 16 : (rem > 0 ? rem * 4 : 0);
            }
            const float* src = (sb > 0) ? ip + (long long)gy * W + gx : ip;
            uint32_t dst = tb + (uint32_t)(r * CTLD + 4 + cv * 4) * 4u;
            asm volatile("cp.async.ca.shared.global [%0], [%1], 16, %2;"
                         :: "r"(dst), "l"(src), "r"(sb));
        }
        // halo: cols 2,3 (gx x0-2,x0-1) and 68,69 (gx x0+64,x0+65); 4 x 28 = 112
        if (tid < 112) {
            int r = tid >> 2, hc = tid & 3;
            int col = (hc < 2) ? (2 + hc) : (66 + hc);        // 2,3,68,69
            int gx = (hc < 2) ? (x0 - 2 + hc) : (x0 + 62 + hc);
            int gy = y0 + r - 2;
            int sb = (gy >= 0 && gy < H && gx >= 0 && gx < W) ? 4 : 0;
            const float* src = sb ? ip + (long long)gy * W + gx : ip;
            uint32_t dst = tb + (uint32_t)(r * CTLD + col) * 4u;
            asm volatile("cp.async.ca.shared.global [%0], [%1], 4, %2;"
                         :: "r"(dst), "l"(src), "r"(sb));
        }
        asm volatile("cp.async.commit_group;" ::: "memory");
    };

    unsigned long long acc2[4][6];
#pragma unroll
    for (int i = 0; i < 4; i++)
#pragma unroll
        for (int j = 0; j < 6; j++) acc2[i][j] = 0ull;

    issue(0, 0);

    for (int ci = 0; ci < Ci; ci++) {
        if (ci + 1 < Ci) {
            issue(ci + 1, (ci + 1) & 1);
            asm volatile("cp.async.wait_group 1;" ::: "memory");
        } else {
            asm volatile("cp.async.wait_group 0;" ::: "memory");
        }
        __syncthreads();

        const float (*tl)[CTLD] = tile[ci & 1];
#pragma unroll
        for (int dx = 0; dx < 5; dx++) {
            unsigned long long v2[10];
#pragma unroll
            for (int rr = 0; rr < 10; rr++)
                v2[rr] = pack_f32x2(tl[ty * 6 + rr][2 * tx + dx + 2],
                                    tl[ty * 6 + rr][2 * tx + dx + 3]);
#pragma unroll
            for (int c4 = 0; c4 < 4; c4++) {
                const float* wp = ws + (c4 * Ci + ci) * 25 + dx;
#pragma unroll
                for (int dy = 0; dy < 5; dy++) {
                    float wv = wp[dy * 5];
                    unsigned long long w2 = pack_f32x2(wv, wv);
#pragma unroll
                    for (int ry = 0; ry < 6; ry++) fma2(acc2[c4][ry], v2[ry + dy], w2);
                }
            }
        }
        __syncthreads();   // done reading tile[ci&1] before it is refilled
    }

    int xe = x0 + 2 * tx;
#pragma unroll
    for (int c4 = 0; c4 < 4; c4++) {
        float bv = bias[co0 + c4];
#pragma unroll
        for (int p = 0; p < 3; p++) {
            int y = y0 + ty * 6 + 2 * p;
            float a0, a1, b0, b1;
            unpack_f32x2(a0, a1, acc2[c4][2 * p]);
            unpack_f32x2(b0, b1, acc2[c4][2 * p + 1]);
            float r0 = fmaxf(gelu_f(a0 + bv), gelu_f(b0 + bv));
            float r1 = fmaxf(gelu_f(a1 + bv), gelu_f(b1 + bv));
            long long base = (((long long)b * Co + co0 + c4) * HP + (y >> 1)) * W;
            if (xe < W)     out[base + xe]     = r0;
            if (xe + 1 < W) out[base + xe + 1] = r1;
        }
    }
}

// ---------------- transpose [B,768,500] -> [B,500,768] ----------------
__global__ void transpose_kernel(const float* __restrict__ in, float* __restrict__ out)
{
    __shared__ float t[32][33];
    int b = blockIdx.z;
    int k0 = blockIdx.x * 32;
    int t0 = blockIdx.y * 32;
    int tx = threadIdx.x, ty = threadIdx.y;
    const float* ip = in + (long long)b * 768 * 500;
    float* op = out + (long long)b * 500 * 768;
#pragma unroll
    for (int r = 0; r < 32; r += 8) {
        int kk = k0 + ty + r, tt = t0 + tx;
        t[ty + r][tx] = (tt < 500) ? ip[(long long)kk * 500 + tt] : 0.f;
    }
    __syncthreads();
#pragma unroll
    for (int r = 0; r < 32; r += 8) {
        int tt = t0 + ty + r, kk = k0 + tx;
        if (tt < 500) op[(long long)tt * 768 + kk] = t[tx][ty + r];
    }
}

// ---------------- flash attention (fused QK^T + skew + softmax + PV) ------------
#define FA_QLD 132
#define FA_KLD 68
#define FA_PLD 68
#define FA_SMEM_FLOATS (64*FA_QLD + 64*FA_KLD + 64*FA_KLD + 128*FA_PLD)

extern __shared__ float fa_smem[];

__global__ void __launch_bounds__(256) flash_attn_kernel(
    const float* __restrict__ Q, const float* __restrict__ K,
    const float* __restrict__ V, const float* __restrict__ qer,
    float* __restrict__ O, int ldin)
{
    float* Qs = fa_smem;
    float* Ks = Qs + 64 * FA_QLD;
    float* Vs = Ks + 64 * FA_KLD;
    float* Ps = Vs + 64 * FA_KLD;

    const float scale = 0.125f;
    int qt = blockIdx.x;
    int h = blockIdx.y, b = blockIdx.z;
    int q0 = qt * 128;
    const float* Qp = Q + (long long)b * 500 * ldin + h * 64;
    const float* Kp = K + (long long)b * 500 * ldin + h * 64;
    const float* Vp = V + (long long)b * 500 * ldin + h * 64;
    const float* qerp = qer + (long long)(h * 16 + b) * 250000;

    int tid = threadIdx.x;
    int tx = tid & 15, ty = tid >> 4;

#pragma unroll
    for (int i = 0; i < 8; i++) {
        int r = i * 16 + (tid >> 4);
        int d4 = (tid & 15) * 4;
        float4 v = make_float4(0.f, 0.f, 0.f, 0.f);
        if (q0 + r < 500) v = *(const float4*)(Qp + (long long)(q0 + r) * ldin + d4);
        Qs[(d4 + 0) * FA_QLD + r] = v.x;
        Qs[(d4 + 1) * FA_QLD + r] = v.y;
        Qs[(d4 + 2) * FA_QLD + r] = v.z;
        Qs[(d4 + 3) * FA_QLD + r] = v.w;
    }

    float m[8], l[8], o[8][4];
#pragma unroll
    for (int i = 0; i < 8; i++) {
        m[i] = -1e30f; l[i] = 0.f;
#pragma unroll
        for (int j = 0; j < 4; j++) o[i][j] = 0.f;
    }
    __syncthreads();

    for (int kt0 = 0; kt0 < 500; kt0 += 64) {
#pragma unroll
        for (int i = 0; i < 4; i++) {
            int r = i * 16 + (tid >> 4);
            int d4 = (tid & 15) * 4;
            float4 kv = make_float4(0.f, 0.f, 0.f, 0.f);
            float4 vv = make_float4(0.f, 0.f, 0.f, 0.f);
            if (kt0 + r < 500) {
                kv = *(const float4*)(Kp + (long long)(kt0 + r) * ldin + d4);
                vv = *(const float4*)(Vp + (long long)(kt0 + r) * ldin + d4);
            }
            Ks[(d4 + 0) * FA_KLD + r] = kv.x;
            Ks[(d4 + 1) * FA_KLD + r] = kv.y;
            Ks[(d4 + 2) * FA_KLD + r] = kv.z;
            Ks[(d4 + 3) * FA_KLD + r] = kv.w;
            *(float4*)(Vs + r * FA_KLD + d4) = vv;
        }
        __syncthreads();

        float S[8][4];
#pragma unroll
        for (int i = 0; i < 8; i++)
#pragma unroll
            for (int j = 0; j < 4; j++) S[i][j] = 0.f;
#pragma unroll
        for (int d = 0; d < 64; d++) {
            float a[8];
            *(float4*)&a[0] = *(const float4*)(Qs + d * FA_QLD + ty * 8);
            *(float4*)&a[4] = *(const float4*)(Qs + d * FA_QLD + ty * 8 + 4);
            float4 bb = *(const float4*)(Ks + d * FA_KLD + tx * 4);
#pragma unroll
            for (int i = 0; i < 8; i++) {
                S[i][0] += a[i] * bb.x; S[i][1] += a[i] * bb.y;
                S[i][2] += a[i] * bb.z; S[i][3] += a[i] * bb.w;
            }
        }
#pragma unroll
        for (int i = 0; i < 8; i++) {
            int q = q0 + ty * 8 + i;
#pragma unroll
            for (int j = 0; j < 4; j++) {
                int k = kt0 + tx * 4 + j;
                if (q < 500 && k < 500) {
                    float srel;
                    if (k <= q)          srel = qerp[(long long)q * 500 + 499 - q + k];
                    else if (k == q + 1) srel = 0.f;
                    else                 srel = qerp[(long long)(q + 1) * 500 + k - q - 2];
                    S[i][j] = S[i][j] * scale + srel;
                } else {
                    S[i][j] = -1e30f;
                }
            }
        }
#pragma unroll
        for (int i = 0; i < 8; i++) {
            float rmax = fmaxf(fmaxf(S[i][0], S[i][1]), fmaxf(S[i][2], S[i][3]));
#pragma unroll
            for (int off = 1; off < 16; off <<= 1)
                rmax = fmaxf(rmax, __shfl_xor_sync(0xffffffffu, rmax, off, 32));
            float mnew = fmaxf(m[i], rmax);
            float corr = __expf(m[i] - mnew);
            float rsum = 0.f;
#pragma unroll
            for (int j = 0; j < 4; j++) {
                S[i][j] = __expf(S[i][j] - mnew);
                rsum += S[i][j];
            }
#pragma unroll
            for (int off = 1; off < 16; off <<= 1)
                rsum += __shfl_xor_sync(0xffffffffu, rsum, off, 32);
            l[i] = l[i] * corr + rsum;
            m[i] = mnew;
#pragma unroll
            for (int j = 0; j < 4; j++) o[i][j] *= corr;
            *(float4*)(Ps + (long long)(ty * 8 + i) * FA_PLD + tx * 4) =
                make_float4(S[i][0], S[i][1], S[i][2], S[i][3]);
        }
        __syncthreads();

#pragma unroll
        for (int kk4 = 0; kk4 < 64; kk4 += 4) {
            float4 vr0 = *(const float4*)(Vs + (kk4 + 0) * FA_KLD + tx * 4);
            float4 vr1 = *(const float4*)(Vs + (kk4 + 1) * FA_KLD + tx * 4);
            float4 vr2 = *(const float4*)(Vs + (kk4 + 2) * FA_KLD + tx * 4);
            float4 vr3 = *(const float4*)(Vs + (kk4 + 3) * FA_KLD + tx * 4);
#pragma unroll
            for (int i = 0; i < 8; i++) {
                float4 p4 = *(const float4*)(Ps + (long long)(ty * 8 + i) * FA_PLD + kk4);
                o[i][0] += p4.x * vr0.x + p4.y * vr1.x + p4.z * vr2.x + p4.w * vr3.x;
                o[i][1] += p4.x * vr0.y + p4.y * vr1.y + p4.z * vr2.y + p4.w * vr3.y;
                o[i][2] += p4.x * vr0.z + p4.y * vr1.z + p4.z * vr2.z + p4.w * vr3.z;
                o[i][3] += p4.x * vr0.w + p4.y * vr1.w + p4.z * vr2.w + p4.w * vr3.w;
            }
        }
        __syncthreads();
    }

    float* Op = O + (long long)b * 500 * 768 + h * 64;
#pragma unroll
    for (int i = 0; i < 8; i++) {
        int q = q0 + ty * 8 + i;
        if (q < 500) {
            float inv = 1.0f / l[i];
            *(float4*)(Op + (long long)q * 768 + tx * 4) =
                make_float4(o[i][0] * inv, o[i][1] * inv, o[i][2] * inv, o[i][3] * inv);
        }
    }
}

// ---------------- layernorm (row = 768) ----------------
__global__ void __launch_bounds__(256) layernorm_kernel(
    const float* __restrict__ in, float* __restrict__ out,
    const float* __restrict__ g, const float* __restrict__ b)
{
    __shared__ float red[256];
    int row = blockIdx.x, tid = threadIdx.x;
    const float* xp = in + (long long)row * 768;
    float v0 = xp[tid], v1 = xp[tid + 256], v2 = xp[tid + 512];
    red[tid] = v0 + v1 + v2;
    __syncthreads();
    for (int o = 128; o > 0; o >>= 1) { if (tid < o) red[tid] += red[tid + o]; __syncthreads(); }
    float mean = red[0] * (1.0f / 768.0f);
    __syncthreads();
    float d0 = v0 - mean, d1 = v1 - mean, d2 = v2 - mean;
    red[tid] = d0 * d0 + d1 * d1 + d2 * d2;
    __syncthreads();
    for (int o = 128; o > 0; o >>= 1) { if (tid < o) red[tid] += red[tid + o]; __syncthreads(); }
    float rstd = rsqrtf(red[0] * (1.0f / 768.0f) + 1e-5f);
    float* op = out + (long long)row * 768;
    op[tid]       = d0 * rstd * g[tid]       + b[tid];
    op[tid + 256] = d1 * rstd * g[tid + 256] + b[tid + 256];
    op[tid + 512] = d2 * rstd * g[tid + 512] + b[tid + 512];
}

// ---------------- orchestration ----------------
static void tc(const float* A, const float* B, const float* bias, const float* add,
               float* C, int M, int N, int K, int lda, int ldb, int ldc, int act,
               int batch = 1, long long bAo = 0, long long bCo = 0)
{
    dim3 grid((N + 127) / 128, (M + 127) / 128, batch);
    mma_gemm_kernel<<<grid, 256, MM_SMEM_BYTES>>>(A, B, bias, add, C, M, N, K,
                                                  lda, ldb, ldc, act, bAo, bCo);
}

extern "C" void kernel_launch(void* const* d_in, const int* in_sizes, int n_in,
                              void* d_out, int out_size)
{
    (void)in_sizes; (void)n_in; (void)out_size;
    const float* spec    = (const float*)d_in[0];
    const float* cw1     = (const float*)d_in[1];
    const float* cb1     = (const float*)d_in[2];
    const float* cw2     = (const float*)d_in[3];
    const float* cb2     = (const float*)d_in[4];
    const float* cw3     = (const float*)d_in[5];
    const float* cb3     = (const float*)d_in[6];
    const float* cw4     = (const float*)d_in[7];
    const float* cb4     = (const float*)d_in[8];
    const float* proj_w  = (const float*)d_in[9];
    const float* proj_b  = (const float*)d_in[10];
    const float* ln1_g   = (const float*)d_in[11];
    const float* ln1_b   = (const float*)d_in[12];
    const float* wq      = (const float*)d_in[13];
    const float* bq      = (const float*)d_in[14];
    const float* wk      = (const float*)d_in[15];
    const float* bk      = (const float*)d_in[16];
    const float* wv      = (const float*)d_in[17];
    const float* bv      = (const float*)d_in[18];
    const float* wo      = (const float*)d_in[19];
    const float* bo      = (const float*)d_in[20];
    const float* er      = (const float*)d_in[21];
    const float* ln2_g   = (const float*)d_in[22];
    const float* ln2_b   = (const float*)d_in[23];
    const float* w1      = (const float*)d_in[24];
    const float* b1      = (const float*)d_in[25];
    const float* w2      = (const float*)d_in[26];
    const float* b2      = (const float*)d_in[27];
    const float* deprj_w = (const float*)d_in[28];
    const float* deprj_b = (const float*)d_in[29];
    float* outp = (float*)d_out;

    float *bufA, *bufB, *qer, *qkv, *wqkv, *bqkv, *ert, *zerob, *x, *xn, *o;
    cudaGetSymbolAddress((void**)&bufA,  g_bufA);
    cudaGetSymbolAddress((void**)&bufB,  g_bufB);
    cudaGetSymbolAddress((void**)&qer,   g_qer);
    cudaGetSymbolAddress((void**)&qkv,   g_qkv);
    cudaGetSymbolAddress((void**)&wqkv,  g_wqkv);
    cudaGetSymbolAddress((void**)&bqkv,  g_bqkv);
    cudaGetSymbolAddress((void**)&ert,   g_ert);
    cudaGetSymbolAddress((void**)&zerob, g_zero);
    cudaGetSymbolAddress((void**)&x,     g_x);
    cudaGetSymbolAddress((void**)&xn,    g_xn);
    cudaGetSymbolAddress((void**)&o,     g_o);
    float* hbuf = bufB;

    const int fa_smem_bytes = FA_SMEM_FLOATS * 4;
    cudaFuncSetAttribute(flash_attn_kernel,
                         cudaFuncAttributeMaxDynamicSharedMemorySize, fa_smem_bytes);
    cudaFuncSetAttribute(mma_gemm_kernel,
                         cudaFuncAttributeMaxDynamicSharedMemorySize, MM_SMEM_BYTES);

    // --- one-time QKV weight/bias concat ---
    concat_qkv<<<(3 * 768 * 2304 + 255) / 256, 256>>>(wq, wk, wv, bq, bk, bv, wqkv, bqkv);

    dim3 cblk(32, 4);
    // --- CNN with fused GELU+maxpool ---
    conv5x5_gelu_pool<<<dim3(8, 8 * 8, 16), cblk>>>(spec, cw1, cb1, bufB, 1, 32, 192);
    conv5x5_gelu_pool<<<dim3(8, 4 * 16, 16), cblk>>>(bufB, cw2, cb2, bufA, 32, 64, 96);
    conv5x5_gelu_pool<<<dim3(8, 2 * 16, 16), cblk>>>(bufA, cw3, cb3, bufB, 64, 64, 48);
    conv5x5_gelu_pool<<<dim3(8, 1 * 16, 16), cblk>>>(bufB, cw4, cb4, bufA, 64, 64, 24);
    transpose_kernel<<<dim3(24, 16, 16), dim3(32, 8)>>>(bufA, xn);

    // proj
    tc(xn, proj_w, proj_b, 0, x, 8000, 768, 768, 768, 768, 768, 0);

    for (int i = 0; i < L_; i++) {
        layernorm_kernel<<<8000, 256>>>(x, xn, ln1_g + i * 768, ln1_b + i * 768);
        // fused QKV: [8000][2304]
        tc(xn, wqkv + (long long)i * 768 * 2304, bqkv + i * 2304, 0, qkv,
           8000, 2304, 768, 768, 2304, 2304, 0);
        // er transposed+scaled -> [64][512]
        er_transpose<<<64, 512>>>(er + (long long)i * 500 * 64, ert);
        // qer (head-major) = Q_h @ er^T, batched over 12 heads
        tc(qkv, ert, zerob, 0, qer, 8000, 500, 64, 2304, 512, 500, 0,
           12, 64LL, 4000000LL);
        // fused attention
        flash_attn_kernel<<<dim3(4, 12, 16), 256, fa_smem_bytes>>>(
            qkv, qkv + 768, qkv + 1536, qer, o, 2304);
        // x = x + o @ wo + bo
        tc(o, wo + (long long)i * 768 * 768, bo + i * 768, x, x, 8000, 768, 768, 768, 768, 768, 0);
        layernorm_kernel<<<8000, 256>>>(x, xn, ln2_g + i * 768, ln2_b + i * 768);
        // h = gelu(xn @ w1 + b1)
        tc(xn, w1 + (long long)i * 768 * 3072, b1 + i * 3072, 0, hbuf, 8000, 3072, 768,
           768, 3072, 3072, 1);
        // x = x + h @ w2 + b2
        tc(hbuf, w2 + (long long)i * 3072 * 768, b2 + i * 768, x, x, 8000, 768, 3072,
           3072, 768, 768, 0);
    }
    // final deproj
    tc(x, deprj_w, deprj_b, 0, outp, 8000, 192, 768, 768, 192, 192, 0);
}